// round 2
// baseline (speedup 1.0000x reference)
#include <cuda_runtime.h>
#include <math.h>

#define SEQ 4096
#define DM 1024
#define NH 16
#define DK 64
#define BATCHN 2
#define MTOT (BATCHN*SEQ)
#define PADW 68

// Scratch (allocation-free): Q,K,V in [b,h,s,d], attention out in [b,s,dm]
__device__ float g_q[(size_t)MTOT * DM];
__device__ float g_k[(size_t)MTOT * DM];
__device__ float g_v[(size_t)MTOT * DM];
__device__ float g_o[(size_t)MTOT * DM];

__device__ __forceinline__ float getc(float4 v, int i) {
    return i == 0 ? v.x : (i == 1 ? v.y : (i == 2 ? v.z : v.w));
}

// RoPE rotation of one (even, odd) pair. d_e = even feature index within head (0..62).
// Angle reduced mod 2*pi via Cody-Waite so cosf/sinf stay accurate even under
// --use_fast_math (large-argument fast-path reduction is lossy).
__device__ __forceinline__ void rope_rot(float p, float d_e, float& e, float& o) {
    const float LOG2_THETA_DIV = 13.287712379549449f / 64.0f;  // log2(10000)/64
    float freq = exp2f(-d_e * LOG2_THETA_DIV);                 // 10000^(-d_e/64)
    float ang = p * freq;
    // reduce ang mod 2*pi (ang < 4096, so n < 652 exact in fp32)
    float n = rintf(ang * 0.15915494309189535f);
    float r = fmaf(-n, 6.28125f, ang);
    r = fmaf(-n, 1.9353071795864774e-3f, r);
    float s, c;
    sincosf(r, &s, &c);
    float ne = e * c - o * s;
    float no = e * s + o * c;
    e = ne;
    o = no;
}

// C[m,o] = sum_i X[m,i] * W[o,i]   (X: [MTOT, DM] row-major, W: [DM, DM] row-major)
// mode 0: plain store row-major [m][o]            (output projection -> d_out)
// mode 1: RoPE + reshape to [b,h,s,d]             (Q, K)
// mode 2: reshape to [b,h,s,d]                    (V)
__global__ __launch_bounds__(256) void proj_kernel(
    const float* __restrict__ X, const float* __restrict__ W,
    const int* __restrict__ pos, float* __restrict__ out, int mode)
{
    __shared__ float sX[16][PADW];
    __shared__ float sW[16][PADW];
    int tid = threadIdx.x;
    int m0 = blockIdx.y << 6, n0 = blockIdx.x << 6;
    int row = tid >> 2;             // 0..63
    int cg  = (tid & 3) << 2;       // 0,4,8,12
    int tx  = (tid & 15) << 2;      // col offset 0..60
    int ty  = (tid >> 4) << 2;      // row offset 0..60

    float acc[4][4] = {};

    const float* xg = X + (size_t)(m0 + row) * DM + cg;
    const float* wg = W + (size_t)(n0 + row) * DM + cg;

    for (int k0 = 0; k0 < DM; k0 += 16) {
        float4 xv = *(const float4*)(xg + k0);
        float4 wv = *(const float4*)(wg + k0);
        __syncthreads();
        sX[cg + 0][row] = xv.x; sX[cg + 1][row] = xv.y;
        sX[cg + 2][row] = xv.z; sX[cg + 3][row] = xv.w;
        sW[cg + 0][row] = wv.x; sW[cg + 1][row] = wv.y;
        sW[cg + 2][row] = wv.z; sW[cg + 3][row] = wv.w;
        __syncthreads();
        #pragma unroll
        for (int k = 0; k < 16; k++) {
            float4 a4 = *(const float4*)&sX[k][ty];
            float4 b4 = *(const float4*)&sW[k][tx];
            float av[4] = {a4.x, a4.y, a4.z, a4.w};
            float bv[4] = {b4.x, b4.y, b4.z, b4.w};
            #pragma unroll
            for (int i = 0; i < 4; i++)
                #pragma unroll
                for (int j = 0; j < 4; j++)
                    acc[i][j] = fmaf(av[i], bv[j], acc[i][j]);
        }
    }

    if (mode == 0) {
        #pragma unroll
        for (int i = 0; i < 4; i++) {
            int m = m0 + ty + i;
            float4 v = make_float4(acc[i][0], acc[i][1], acc[i][2], acc[i][3]);
            *(float4*)(out + (size_t)m * DM + n0 + tx) = v;
        }
    } else {
        int n = n0 + tx;
        int h = n >> 6, d = n & 63;   // all 4 cols in the same head (tx multiple of 4 < 64)
        #pragma unroll
        for (int i = 0; i < 4; i++) {
            int m = m0 + ty + i;
            int b = m >> 12, s = m & (SEQ - 1);
            float e0 = acc[i][0], o0 = acc[i][1];
            float e1 = acc[i][2], o1 = acc[i][3];
            if (mode == 1) {
                float p = (float)pos[m];
                rope_rot(p, (float)d,       e0, o0);
                rope_rot(p, (float)(d + 2), e1, o1);
            }
            float4 v = make_float4(e0, o0, e1, o1);
            *(float4*)(out + ((size_t)(b * NH + h) * SEQ + s) * DK + d) = v;
        }
    }
}

// Causal flash attention, fp32, BQ = BK = 64, online softmax.
// Q/K/V in [b,h,s,d]; O written in [b,s,h*d] = [b,s,1024].
__global__ __launch_bounds__(256) void attn_kernel(
    const float* __restrict__ Q, const float* __restrict__ K,
    const float* __restrict__ V, float* __restrict__ O)
{
    extern __shared__ float sm[];
    float* sQ  = sm;                 // [64][PADW] row-major (q-row, d)
    float* sKT = sm + 64 * PADW;     // [64][PADW] d-major   (d, k-col)
    float* sV  = sm + 2 * 64 * PADW; // [64][PADW] row-major (k, d)
    float* sP  = sm + 3 * 64 * PADW; // [64][PADW] row-major (q-row, k)

    int tid = threadIdx.x;
    int tx  = (tid & 15) << 2;
    int ty  = (tid >> 4) << 2;
    int row = tid >> 2;             // 0..63
    int cg  = (tid & 3) << 2;       // 0,4,8,12  (+16*u covers all 64 cols)

    int qt = blockIdx.x;
    int h  = blockIdx.y;
    int b  = blockIdx.z;
    size_t base = (size_t)(b * NH + h) * SEQ * DK;
    int q0 = qt << 6;

    // Load full Q tile (64x64): 4 float4 per thread
    #pragma unroll
    for (int u = 0; u < 4; u++) {
        int c = cg + 16 * u;
        float4 qv = *(const float4*)(Q + base + (size_t)(q0 + row) * DK + c);
        *(float4*)&sQ[row * PADW + c] = qv;
    }

    float m_i[4] = {-1e30f, -1e30f, -1e30f, -1e30f};
    float l_i[4] = {0.f, 0.f, 0.f, 0.f};
    float oa[4][4] = {};

    for (int kt = 0; kt <= qt; kt++) {
        int k0 = kt << 6;
        // Stage full K/V tiles (64x64) in registers, then store after barrier
        float4 kvv[4], vvv[4];
        #pragma unroll
        for (int u = 0; u < 4; u++) {
            int c = cg + 16 * u;
            kvv[u] = *(const float4*)(K + base + (size_t)(k0 + row) * DK + c);
            vvv[u] = *(const float4*)(V + base + (size_t)(k0 + row) * DK + c);
        }
        __syncthreads();  // previous iteration's PV GEMM done with sKT/sV
        #pragma unroll
        for (int u = 0; u < 4; u++) {
            int c = cg + 16 * u;
            sKT[(c + 0) * PADW + row] = kvv[u].x;
            sKT[(c + 1) * PADW + row] = kvv[u].y;
            sKT[(c + 2) * PADW + row] = kvv[u].z;
            sKT[(c + 3) * PADW + row] = kvv[u].w;
            *(float4*)&sV[row * PADW + c] = vvv[u];
        }
        __syncthreads();

        // S = Q * K^T
        float s_[4][4] = {};
        #pragma unroll 2
        for (int d = 0; d < DK; d += 4) {
            float4 aq[4];
            #pragma unroll
            for (int i = 0; i < 4; i++)
                aq[i] = *(const float4*)&sQ[(ty + i) * PADW + d];
            #pragma unroll
            for (int dd = 0; dd < 4; dd++) {
                float4 bq = *(const float4*)&sKT[(d + dd) * PADW + tx];
                float bv[4] = {bq.x, bq.y, bq.z, bq.w};
                float av[4] = {getc(aq[0], dd), getc(aq[1], dd),
                               getc(aq[2], dd), getc(aq[3], dd)};
                #pragma unroll
                for (int i = 0; i < 4; i++)
                    #pragma unroll
                    for (int j = 0; j < 4; j++)
                        s_[i][j] = fmaf(av[i], bv[j], s_[i][j]);
            }
        }

        // scale + causal mask
        const float sc = 0.125f;  // 1/sqrt(64)
        if (kt == qt) {
            #pragma unroll
            for (int i = 0; i < 4; i++)
                #pragma unroll
                for (int j = 0; j < 4; j++)
                    s_[i][j] = (tx + j > ty + i) ? -1e30f : s_[i][j] * sc;
        } else {
            #pragma unroll
            for (int i = 0; i < 4; i++)
                #pragma unroll
                for (int j = 0; j < 4; j++)
                    s_[i][j] *= sc;
        }

        // online softmax (row reductions across 16 lanes via xor-shuffle)
        float p_[4][4];
        #pragma unroll
        for (int i = 0; i < 4; i++) {
            float rm = fmaxf(fmaxf(s_[i][0], s_[i][1]), fmaxf(s_[i][2], s_[i][3]));
            rm = fmaxf(rm, __shfl_xor_sync(0xffffffffu, rm, 1));
            rm = fmaxf(rm, __shfl_xor_sync(0xffffffffu, rm, 2));
            rm = fmaxf(rm, __shfl_xor_sync(0xffffffffu, rm, 4));
            rm = fmaxf(rm, __shfl_xor_sync(0xffffffffu, rm, 8));
            float mn = fmaxf(m_i[i], rm);
            float corr = __expf(m_i[i] - mn);
            m_i[i] = mn;
            float rs = 0.f;
            #pragma unroll
            for (int j = 0; j < 4; j++) {
                p_[i][j] = __expf(s_[i][j] - mn);
                rs += p_[i][j];
            }
            rs += __shfl_xor_sync(0xffffffffu, rs, 1);
            rs += __shfl_xor_sync(0xffffffffu, rs, 2);
            rs += __shfl_xor_sync(0xffffffffu, rs, 4);
            rs += __shfl_xor_sync(0xffffffffu, rs, 8);
            l_i[i] = l_i[i] * corr + rs;
            #pragma unroll
            for (int j = 0; j < 4; j++) oa[i][j] *= corr;
        }

        // stash P (float4 rows, conflict-free)
        #pragma unroll
        for (int i = 0; i < 4; i++)
            *(float4*)&sP[(ty + i) * PADW + tx] =
                make_float4(p_[i][0], p_[i][1], p_[i][2], p_[i][3]);
        __syncthreads();

        // O += P * V
        #pragma unroll 2
        for (int k = 0; k < 64; k += 4) {
            float4 aq[4];
            #pragma unroll
            for (int i = 0; i < 4; i++)
                aq[i] = *(const float4*)&sP[(ty + i) * PADW + k];
            #pragma unroll
            for (int kk = 0; kk < 4; kk++) {
                float4 bq = *(const float4*)&sV[(k + kk) * PADW + tx];
                float bv[4] = {bq.x, bq.y, bq.z, bq.w};
                float av[4] = {getc(aq[0], kk), getc(aq[1], kk),
                               getc(aq[2], kk), getc(aq[3], kk)};
                #pragma unroll
                for (int i = 0; i < 4; i++)
                    #pragma unroll
                    for (int j = 0; j < 4; j++)
                        oa[i][j] = fmaf(av[i], bv[j], oa[i][j]);
            }
        }
    }

    // finalize: O /= l, write to [b, s, h*64 + d]
    #pragma unroll
    for (int i = 0; i < 4; i++) {
        float inv = 1.0f / l_i[i];
        int s = q0 + ty + i;
        float4 v = make_float4(oa[i][0] * inv, oa[i][1] * inv,
                               oa[i][2] * inv, oa[i][3] * inv);
        *(float4*)(O + (size_t)(b * SEQ + s) * DM + h * DK + tx) = v;
    }
}

extern "C" void kernel_launch(void* const* d_in, const int* in_sizes, int n_in,
                              void* d_out, int out_size) {
    (void)in_sizes; (void)n_in; (void)out_size;
    const float* x   = (const float*)d_in[0];
    const int*   pos = (const int*)d_in[1];
    const float* Wq  = (const float*)d_in[2];
    const float* Wk  = (const float*)d_in[3];
    const float* Wv  = (const float*)d_in[4];
    const float* Wo  = (const float*)d_in[5];
    float* out = (float*)d_out;

    float *q, *k, *v, *o;
    cudaGetSymbolAddress((void**)&q, g_q);
    cudaGetSymbolAddress((void**)&k, g_k);
    cudaGetSymbolAddress((void**)&v, g_v);
    cudaGetSymbolAddress((void**)&o, g_o);

    const size_t ATTN_SMEM = (size_t)4 * 64 * PADW * sizeof(float);  // 69632 B
    cudaFuncSetAttribute(attn_kernel, cudaFuncAttributeMaxDynamicSharedMemorySize,
                         (int)ATTN_SMEM);

    dim3 pgrid(DM / 64, MTOT / 64);
    proj_kernel<<<pgrid, 256>>>(x, Wq, pos, q, 1);
    proj_kernel<<<pgrid, 256>>>(x, Wk, pos, k, 1);
    proj_kernel<<<pgrid, 256>>>(x, Wv, pos, v, 2);

    dim3 agrid(SEQ / 64, NH, BATCHN);
    attn_kernel<<<agrid, 256, ATTN_SMEM>>>(q, k, v, o);

    proj_kernel<<<pgrid, 256>>>(o, Wo, pos, out, 0);
}

// round 5
// speedup vs baseline: 1.4019x; 1.4019x over previous
#include <cuda_runtime.h>
#include <cuda_bf16.h>
#include <math.h>
#include <stdint.h>

#define SEQ 4096
#define DM 1024
#define NH 16
#define DK 64
#define BATCHN 2
#define MTOT (BATCHN*SEQ)
#define PADW 68

// ---------------- scratch (allocation-free) ----------------
__device__ __nv_bfloat16 g_xh[(size_t)MTOT * DM];
__device__ __nv_bfloat16 g_xl[(size_t)MTOT * DM];
__device__ __nv_bfloat16 g_wh[(size_t)4 * DM * DM];
__device__ __nv_bfloat16 g_wl[(size_t)4 * DM * DM];
__device__ float g_q[(size_t)MTOT * DM];
__device__ float g_k[(size_t)MTOT * DM];
__device__ float g_v[(size_t)MTOT * DM];
__device__ float g_o[(size_t)MTOT * DM];

// ---------------- helpers ----------------
__device__ __forceinline__ uint32_t s2u(const void* p) {
    uint32_t a;
    asm("{ .reg .u64 t; cvta.to.shared.u64 t, %1; cvt.u32.u64 %0, t; }" : "=r"(a) : "l"(p));
    return a;
}

__device__ __forceinline__ float getc(float4 v, int i) {
    return i == 0 ? v.x : (i == 1 ? v.y : (i == 2 ? v.z : v.w));
}

// RoPE rotation; Cody-Waite 2*pi reduction (robust under fast-math).
__device__ __forceinline__ void rope_rot(float p, float d_e, float& e, float& o) {
    const float LOG2_THETA_DIV = 13.287712379549449f / 64.0f;
    float freq = exp2f(-d_e * LOG2_THETA_DIV);
    float ang = p * freq;
    float n = rintf(ang * 0.15915494309189535f);
    float r = fmaf(-n, 6.28125f, ang);
    r = fmaf(-n, 1.9353071795864774e-3f, r);
    float s, c;
    sincosf(r, &s, &c);
    float ne = e * c - o * s;
    float no = e * s + o * c;
    e = ne; o = no;
}

#define LDSM4(r0, r1, r2, r3, addr) \
    asm volatile("ldmatrix.sync.aligned.m8n8.x4.shared.b16 {%0,%1,%2,%3}, [%4];" \
        : "=r"(r0), "=r"(r1), "=r"(r2), "=r"(r3) : "r"(addr))

#define MMA16816(c, a, b) \
    asm volatile("mma.sync.aligned.m16n8k16.row.col.f32.bf16.bf16.f32 " \
        "{%0,%1,%2,%3}, {%4,%5,%6,%7}, {%8,%9}, {%0,%1,%2,%3};" \
        : "+f"((c)[0]), "+f"((c)[1]), "+f"((c)[2]), "+f"((c)[3]) \
        : "r"((a)[0]), "r"((a)[1]), "r"((a)[2]), "r"((a)[3]), "r"((b)[0]), "r"((b)[1]))

// ---------------- split kernel: fp32 x -> (bf16 hi, bf16 lo) ----------------
__global__ __launch_bounds__(256) void split_kernel(
    const float* __restrict__ in, __nv_bfloat16* __restrict__ hi,
    __nv_bfloat16* __restrict__ lo, int n4)
{
    int i = blockIdx.x * 256 + threadIdx.x;
    if (i >= n4) return;
    float4 x = ((const float4*)in)[i];
    float xs[4] = {x.x, x.y, x.z, x.w};
    __nv_bfloat16 h[4], l[4];
    #pragma unroll
    for (int j = 0; j < 4; j++) {
        h[j] = __float2bfloat16_rn(xs[j]);
        l[j] = __float2bfloat16_rn(xs[j] - __bfloat162float(h[j]));
    }
    __nv_bfloat162 h01, h23, l01, l23;
    h01.x = h[0]; h01.y = h[1]; h23.x = h[2]; h23.y = h[3];
    l01.x = l[0]; l01.y = l[1]; l23.x = l[2]; l23.y = l[3];
    uint2 uh = make_uint2(*(uint32_t*)&h01, *(uint32_t*)&h23);
    uint2 ul = make_uint2(*(uint32_t*)&l01, *(uint32_t*)&l23);
    ((uint2*)hi)[i] = uh;
    ((uint2*)lo)[i] = ul;
}

// ---------------- bf16 split-3 GEMM via mma.sync (HMMA) ----------------
// C[m,n] = sum_k A[m,k]*B[n,k]. A: [MTOT,DM] bf16 hi/lo, B: [DM,DM] bf16 hi/lo.
// mode 0: out[m][n]; mode 1: RoPE + [b,h,s,d]; mode 2: [b,h,s,d]
// CTA tile 128x128, BK=32, 8 warps (2m x 4n), warp tile 64x32.
// smem rows padded to 40 bf16 (80B) -> conflict-free ldmatrix.
#define SROWB 80
#define ARR_B (128 * SROWB)              // 10240 bytes per operand array
#define STAGE_B (4 * ARR_B)              // 40960 per stage
#define GSMEM (2 * STAGE_B)              // 81920 total

__global__ __launch_bounds__(256) void gemm_bf16(
    const __nv_bfloat16* __restrict__ Ah, const __nv_bfloat16* __restrict__ Al,
    const __nv_bfloat16* __restrict__ Bh, const __nv_bfloat16* __restrict__ Bl,
    const int* __restrict__ pos, float* __restrict__ out, int mode)
{
    extern __shared__ char smem[];
    const uint32_t sb32 = s2u(smem);
    int tid = threadIdx.x, lane = tid & 31, wid = tid >> 5;
    int m0 = blockIdx.y << 7, n0 = blockIdx.x << 7;
    int wm = (wid >> 2) << 6;   // 0 / 64
    int wn = (wid & 3) << 5;    // 0 / 32 / 64 / 96

    // fill mapping: row = tid>>1 (0..127), half = tid&1 covers 16 bf16 (32B)
    int frow = tid >> 1;
    int fh = tid & 1;
    const uint4* gAh = (const uint4*)(Ah + (size_t)(m0 + frow) * DM);
    const uint4* gAl = (const uint4*)(Al + (size_t)(m0 + frow) * DM);
    const uint4* gBh = (const uint4*)(Bh + (size_t)(n0 + frow) * DM);
    const uint4* gBl = (const uint4*)(Bl + (size_t)(n0 + frow) * DM);
    char* sfill = smem + frow * SROWB + fh * 32;

    float c[4][4][4] = {};
    uint4 st[8];

    #define LOADG(s) { \
        int bi = (s) * 4 + (fh << 1); \
        st[0] = gAh[bi]; st[1] = gAh[bi + 1]; \
        st[2] = gAl[bi]; st[3] = gAl[bi + 1]; \
        st[4] = gBh[bi]; st[5] = gBh[bi + 1]; \
        st[6] = gBl[bi]; st[7] = gBl[bi + 1]; }

    LOADG(0);

    for (int s = 0; s < 32; s++) {
        int buf = s & 1;
        __syncthreads();
        char* sp = sfill + buf * STAGE_B;
        *(uint4*)(sp + 0 * ARR_B)      = st[0];
        *(uint4*)(sp + 0 * ARR_B + 16) = st[1];
        *(uint4*)(sp + 1 * ARR_B)      = st[2];
        *(uint4*)(sp + 1 * ARR_B + 16) = st[3];
        *(uint4*)(sp + 2 * ARR_B)      = st[4];
        *(uint4*)(sp + 2 * ARR_B + 16) = st[5];
        *(uint4*)(sp + 3 * ARR_B)      = st[6];
        *(uint4*)(sp + 3 * ARR_B + 16) = st[7];
        __syncthreads();
        if (s < 31) LOADG(s + 1);

        uint32_t base = sb32 + buf * STAGE_B;
        uint32_t aRow = base + (uint32_t)(wm + (lane & 15)) * SROWB + ((lane >> 4) << 4);
        int q = lane >> 3;
        uint32_t bRow = base + 2 * ARR_B +
                        (uint32_t)(wn + ((q >> 1) << 3) + (lane & 7)) * SROWB +
                        ((q & 1) << 4);

        #pragma unroll
        for (int step = 0; step < 2; step++) {
            uint32_t ko = step * 32;
            uint32_t ah[4][4], al[4][4], bh[4][2], bl[4][2];
            #pragma unroll
            for (int mt = 0; mt < 4; mt++) {
                uint32_t aAddr = aRow + (uint32_t)(mt * 16) * SROWB + ko;
                LDSM4(ah[mt][0], ah[mt][1], ah[mt][2], ah[mt][3], aAddr);
                LDSM4(al[mt][0], al[mt][1], al[mt][2], al[mt][3], aAddr + ARR_B);
            }
            #pragma unroll
            for (int pn = 0; pn < 2; pn++) {
                uint32_t bAddr = bRow + (uint32_t)(pn * 16) * SROWB + ko;
                LDSM4(bh[2*pn][0], bh[2*pn][1], bh[2*pn+1][0], bh[2*pn+1][1], bAddr);
                LDSM4(bl[2*pn][0], bl[2*pn][1], bl[2*pn+1][0], bl[2*pn+1][1], bAddr + ARR_B);
            }
            #pragma unroll
            for (int mt = 0; mt < 4; mt++)
                #pragma unroll
                for (int nt = 0; nt < 4; nt++) {
                    MMA16816(c[mt][nt], ah[mt], bh[nt]);
                    MMA16816(c[mt][nt], ah[mt], bl[nt]);
                    MMA16816(c[mt][nt], al[mt], bh[nt]);
                }
        }
    }

    // ---------------- epilogue ----------------
    int gid = lane >> 2, tig = lane & 3;
    #pragma unroll
    for (int mt = 0; mt < 4; mt++) {
        int m_a = m0 + wm + mt * 16 + gid;
        int m_b = m_a + 8;
        float p_a = 0.f, p_b = 0.f;
        if (mode == 1) { p_a = (float)pos[m_a]; p_b = (float)pos[m_b]; }
        #pragma unroll
        for (int nt = 0; nt < 4; nt++) {
            int n = n0 + wn + nt * 8 + tig * 2;
            float v0 = c[mt][nt][0], v1 = c[mt][nt][1];
            float v2 = c[mt][nt][2], v3 = c[mt][nt][3];
            if (mode == 0) {
                *(float2*)(out + (size_t)m_a * DM + n) = make_float2(v0, v1);
                *(float2*)(out + (size_t)m_b * DM + n) = make_float2(v2, v3);
            } else {
                int h = n >> 6, d = n & 63;
                if (mode == 1) {
                    rope_rot(p_a, (float)d, v0, v1);
                    rope_rot(p_b, (float)d, v2, v3);
                }
                int ba = m_a >> 12, sa = m_a & (SEQ - 1);
                int bb = m_b >> 12, sbq = m_b & (SEQ - 1);
                *(float2*)(out + ((size_t)(ba * NH + h) * SEQ + sa) * DK + d) =
                    make_float2(v0, v1);
                *(float2*)(out + ((size_t)(bb * NH + h) * SEQ + sbq) * DK + d) =
                    make_float2(v2, v3);
            }
        }
    }
}

// ---------------- fp32 flash attention (unchanged, passing) ----------------
__global__ __launch_bounds__(256) void attn_kernel(
    const float* __restrict__ Q, const float* __restrict__ K,
    const float* __restrict__ V, float* __restrict__ O)
{
    extern __shared__ float sm[];
    float* sQ  = sm;
    float* sKT = sm + 64 * PADW;
    float* sV  = sm + 2 * 64 * PADW;
    float* sP  = sm + 3 * 64 * PADW;

    int tid = threadIdx.x;
    int tx  = (tid & 15) << 2;
    int ty  = (tid >> 4) << 2;
    int row = tid >> 2;
    int cg  = (tid & 3) << 2;

    int qt = blockIdx.x;
    int h  = blockIdx.y;
    int b  = blockIdx.z;
    size_t base = (size_t)(b * NH + h) * SEQ * DK;
    int q0 = qt << 6;

    #pragma unroll
    for (int u = 0; u < 4; u++) {
        int c = cg + 16 * u;
        float4 qv = *(const float4*)(Q + base + (size_t)(q0 + row) * DK + c);
        *(float4*)&sQ[row * PADW + c] = qv;
    }

    float m_i[4] = {-1e30f, -1e30f, -1e30f, -1e30f};
    float l_i[4] = {0.f, 0.f, 0.f, 0.f};
    float oa[4][4] = {};

    for (int kt = 0; kt <= qt; kt++) {
        int k0 = kt << 6;
        float4 kvv[4], vvv[4];
        #pragma unroll
        for (int u = 0; u < 4; u++) {
            int c = cg + 16 * u;
            kvv[u] = *(const float4*)(K + base + (size_t)(k0 + row) * DK + c);
            vvv[u] = *(const float4*)(V + base + (size_t)(k0 + row) * DK + c);
        }
        __syncthreads();
        #pragma unroll
        for (int u = 0; u < 4; u++) {
            int c = cg + 16 * u;
            sKT[(c + 0) * PADW + row] = kvv[u].x;
            sKT[(c + 1) * PADW + row] = kvv[u].y;
            sKT[(c + 2) * PADW + row] = kvv[u].z;
            sKT[(c + 3) * PADW + row] = kvv[u].w;
            *(float4*)&sV[row * PADW + c] = vvv[u];
        }
        __syncthreads();

        float s_[4][4] = {};
        #pragma unroll 2
        for (int d = 0; d < DK; d += 4) {
            float4 aq[4];
            #pragma unroll
            for (int i = 0; i < 4; i++)
                aq[i] = *(const float4*)&sQ[(ty + i) * PADW + d];
            #pragma unroll
            for (int dd = 0; dd < 4; dd++) {
                float4 bq = *(const float4*)&sKT[(d + dd) * PADW + tx];
                float bv[4] = {bq.x, bq.y, bq.z, bq.w};
                float av[4] = {getc(aq[0], dd), getc(aq[1], dd),
                               getc(aq[2], dd), getc(aq[3], dd)};
                #pragma unroll
                for (int i = 0; i < 4; i++)
                    #pragma unroll
                    for (int j = 0; j < 4; j++)
                        s_[i][j] = fmaf(av[i], bv[j], s_[i][j]);
            }
        }

        const float sc = 0.125f;
        if (kt == qt) {
            #pragma unroll
            for (int i = 0; i < 4; i++)
                #pragma unroll
                for (int j = 0; j < 4; j++)
                    s_[i][j] = (tx + j > ty + i) ? -1e30f : s_[i][j] * sc;
        } else {
            #pragma unroll
            for (int i = 0; i < 4; i++)
                #pragma unroll
                for (int j = 0; j < 4; j++)
                    s_[i][j] *= sc;
        }

        float p_[4][4];
        #pragma unroll
        for (int i = 0; i < 4; i++) {
            float rm = fmaxf(fmaxf(s_[i][0], s_[i][1]), fmaxf(s_[i][2], s_[i][3]));
            rm = fmaxf(rm, __shfl_xor_sync(0xffffffffu, rm, 1));
            rm = fmaxf(rm, __shfl_xor_sync(0xffffffffu, rm, 2));
            rm = fmaxf(rm, __shfl_xor_sync(0xffffffffu, rm, 4));
            rm = fmaxf(rm, __shfl_xor_sync(0xffffffffu, rm, 8));
            float mn = fmaxf(m_i[i], rm);
            float corr = __expf(m_i[i] - mn);
            m_i[i] = mn;
            float rs = 0.f;
            #pragma unroll
            for (int j = 0; j < 4; j++) {
                p_[i][j] = __expf(s_[i][j] - mn);
                rs += p_[i][j];
            }
            rs += __shfl_xor_sync(0xffffffffu, rs, 1);
            rs += __shfl_xor_sync(0xffffffffu, rs, 2);
            rs += __shfl_xor_sync(0xffffffffu, rs, 4);
            rs += __shfl_xor_sync(0xffffffffu, rs, 8);
            l_i[i] = l_i[i] * corr + rs;
            #pragma unroll
            for (int j = 0; j < 4; j++) oa[i][j] *= corr;
        }

        #pragma unroll
        for (int i = 0; i < 4; i++)
            *(float4*)&sP[(ty + i) * PADW + tx] =
                make_float4(p_[i][0], p_[i][1], p_[i][2], p_[i][3]);
        __syncthreads();

        #pragma unroll 2
        for (int k = 0; k < 64; k += 4) {
            float4 aq[4];
            #pragma unroll
            for (int i = 0; i < 4; i++)
                aq[i] = *(const float4*)&sP[(ty + i) * PADW + k];
            #pragma unroll
            for (int kk = 0; kk < 4; kk++) {
                float4 bq = *(const float4*)&sV[(k + kk) * PADW + tx];
                float bv[4] = {bq.x, bq.y, bq.z, bq.w};
                float av[4] = {getc(aq[0], kk), getc(aq[1], kk),
                               getc(aq[2], kk), getc(aq[3], kk)};
                #pragma unroll
                for (int i = 0; i < 4; i++)
                    #pragma unroll
                    for (int j = 0; j < 4; j++)
                        oa[i][j] = fmaf(av[i], bv[j], oa[i][j]);
            }
        }
    }

    #pragma unroll
    for (int i = 0; i < 4; i++) {
        float inv = 1.0f / l_i[i];
        int s = q0 + ty + i;
        float4 v = make_float4(oa[i][0] * inv, oa[i][1] * inv,
                               oa[i][2] * inv, oa[i][3] * inv);
        *(float4*)(O + (size_t)(b * SEQ + s) * DM + h * DK + tx) = v;
    }
}

// ---------------- launch ----------------
extern "C" void kernel_launch(void* const* d_in, const int* in_sizes, int n_in,
                              void* d_out, int out_size) {
    (void)in_sizes; (void)n_in; (void)out_size;
    const float* x   = (const float*)d_in[0];
    const int*   pos = (const int*)d_in[1];
    const float* Wq  = (const float*)d_in[2];
    const float* Wk  = (const float*)d_in[3];
    const float* Wv  = (const float*)d_in[4];
    const float* Wo  = (const float*)d_in[5];
    float* out = (float*)d_out;

    __nv_bfloat16 *xh, *xl, *wh, *wl;
    float *q, *k, *v, *o;
    cudaGetSymbolAddress((void**)&xh, g_xh);
    cudaGetSymbolAddress((void**)&xl, g_xl);
    cudaGetSymbolAddress((void**)&wh, g_wh);
    cudaGetSymbolAddress((void**)&wl, g_wl);
    cudaGetSymbolAddress((void**)&q, g_q);
    cudaGetSymbolAddress((void**)&k, g_k);
    cudaGetSymbolAddress((void**)&v, g_v);
    cudaGetSymbolAddress((void**)&o, g_o);

    cudaFuncSetAttribute(gemm_bf16, cudaFuncAttributeMaxDynamicSharedMemorySize, GSMEM);
    const size_t ATTN_SMEM = (size_t)4 * 64 * PADW * sizeof(float);
    cudaFuncSetAttribute(attn_kernel, cudaFuncAttributeMaxDynamicSharedMemorySize,
                         (int)ATTN_SMEM);

    const int n4x = MTOT * DM / 4;
    const int n4w = DM * DM / 4;
    const size_t WSTRIDE = (size_t)DM * DM;

    split_kernel<<<n4x / 256, 256>>>(x, xh, xl, n4x);
    split_kernel<<<n4w / 256, 256>>>(Wq, wh + 0 * WSTRIDE, wl + 0 * WSTRIDE, n4w);
    split_kernel<<<n4w / 256, 256>>>(Wk, wh + 1 * WSTRIDE, wl + 1 * WSTRIDE, n4w);
    split_kernel<<<n4w / 256, 256>>>(Wv, wh + 2 * WSTRIDE, wl + 2 * WSTRIDE, n4w);
    split_kernel<<<n4w / 256, 256>>>(Wo, wh + 3 * WSTRIDE, wl + 3 * WSTRIDE, n4w);

    dim3 ggrid(DM / 128, MTOT / 128);  // (8, 64)
    gemm_bf16<<<ggrid, 256, GSMEM>>>(xh, xl, wh + 0 * WSTRIDE, wl + 0 * WSTRIDE, pos, q, 1);
    gemm_bf16<<<ggrid, 256, GSMEM>>>(xh, xl, wh + 1 * WSTRIDE, wl + 1 * WSTRIDE, pos, k, 1);
    gemm_bf16<<<ggrid, 256, GSMEM>>>(xh, xl, wh + 2 * WSTRIDE, wl + 2 * WSTRIDE, pos, v, 2);

    dim3 agrid(SEQ / 64, NH, BATCHN);
    attn_kernel<<<agrid, 256, ATTN_SMEM>>>(q, k, v, o);

    split_kernel<<<n4x / 256, 256>>>(o, xh, xl, n4x);
    gemm_bf16<<<ggrid, 256, GSMEM>>>(xh, xl, wh + 3 * WSTRIDE, wl + 3 * WSTRIDE, pos, out, 0);
}

// round 6
// speedup vs baseline: 2.3807x; 1.6983x over previous
#include <cuda_runtime.h>
#include <cuda_bf16.h>
#include <math.h>
#include <stdint.h>

#define SEQ 4096
#define DM 1024
#define NH 16
#define DK 64
#define BATCHN 2
#define MTOT (BATCHN*SEQ)

// ---------------- scratch (allocation-free) ----------------
__device__ __nv_bfloat16 g_xh[(size_t)MTOT * DM];
__device__ __nv_bfloat16 g_xl[(size_t)MTOT * DM];
__device__ __nv_bfloat16 g_wh[(size_t)4 * DM * DM];
__device__ __nv_bfloat16 g_wl[(size_t)4 * DM * DM];
__device__ __nv_bfloat16 g_qh[(size_t)MTOT * DM];
__device__ __nv_bfloat16 g_ql[(size_t)MTOT * DM];
__device__ __nv_bfloat16 g_kh[(size_t)MTOT * DM];
__device__ __nv_bfloat16 g_kl[(size_t)MTOT * DM];
__device__ __nv_bfloat16 g_vh[(size_t)MTOT * DM];
__device__ __nv_bfloat16 g_vl[(size_t)MTOT * DM];
__device__ float g_o[(size_t)MTOT * DM];

// ---------------- helpers ----------------
__device__ __forceinline__ uint32_t s2u(const void* p) {
    uint32_t a;
    asm("{ .reg .u64 t; cvta.to.shared.u64 t, %1; cvt.u32.u64 %0, t; }" : "=r"(a) : "l"(p));
    return a;
}

// RoPE rotation; Cody-Waite 2*pi reduction (robust under fast-math).
__device__ __forceinline__ void rope_rot(float p, float d_e, float& e, float& o) {
    const float LOG2_THETA_DIV = 13.287712379549449f / 64.0f;
    float freq = exp2f(-d_e * LOG2_THETA_DIV);
    float ang = p * freq;
    float n = rintf(ang * 0.15915494309189535f);
    float r = fmaf(-n, 6.28125f, ang);
    r = fmaf(-n, 1.9353071795864774e-3f, r);
    float s, c;
    sincosf(r, &s, &c);
    float ne = e * c - o * s;
    float no = e * s + o * c;
    e = ne; o = no;
}

// Fast exp for x <= 0 on the FMA/ALU pipes (no MUFU). ~1e-6 rel err.
__device__ __forceinline__ float fexp(float x) {
    float t = fmaxf(x * 1.4426950408889634f, -126.0f);
    float z = t + 12582912.0f;              // round-to-nearest int in mantissa
    int ii = __float_as_int(z);
    float f = t - (z - 12582912.0f);        // f in [-0.5, 0.5]
    float p = 1.3333558e-3f;
    p = fmaf(p, f, 9.6181291e-3f);
    p = fmaf(p, f, 5.5504109e-2f);
    p = fmaf(p, f, 2.4022651e-1f);
    p = fmaf(p, f, 6.9314718e-1f);
    p = fmaf(p, f, 1.0f);
    return __int_as_float((ii << 23) + 0x3F800000) * p;  // * 2^i
}

// split fp32 pair -> packed bf16 hi + bf16 lo (lo half = first arg)
__device__ __forceinline__ void pack_split(float a, float b, uint32_t& hp, uint32_t& lp) {
    __nv_bfloat162 H = __floats2bfloat162_rn(a, b);
    hp = *(uint32_t*)&H;
    float ra = a - __bfloat162float(H.x);
    float rb = b - __bfloat162float(H.y);
    __nv_bfloat162 L = __floats2bfloat162_rn(ra, rb);
    lp = *(uint32_t*)&L;
}

#define LDSM4(r0, r1, r2, r3, addr) \
    asm volatile("ldmatrix.sync.aligned.m8n8.x4.shared.b16 {%0,%1,%2,%3}, [%4];" \
        : "=r"(r0), "=r"(r1), "=r"(r2), "=r"(r3) : "r"(addr))

#define LDSM4T(r0, r1, r2, r3, addr) \
    asm volatile("ldmatrix.sync.aligned.m8n8.x4.trans.shared.b16 {%0,%1,%2,%3}, [%4];" \
        : "=r"(r0), "=r"(r1), "=r"(r2), "=r"(r3) : "r"(addr))

#define MMA16816(c, a, b) \
    asm volatile("mma.sync.aligned.m16n8k16.row.col.f32.bf16.bf16.f32 " \
        "{%0,%1,%2,%3}, {%4,%5,%6,%7}, {%8,%9}, {%0,%1,%2,%3};" \
        : "+f"((c)[0]), "+f"((c)[1]), "+f"((c)[2]), "+f"((c)[3]) \
        : "r"((a)[0]), "r"((a)[1]), "r"((a)[2]), "r"((a)[3]), "r"((b)[0]), "r"((b)[1]))

// ---------------- split kernel: fp32 -> (bf16 hi, bf16 lo) ----------------
__global__ __launch_bounds__(256) void split_kernel(
    const float* __restrict__ in, __nv_bfloat16* __restrict__ hi,
    __nv_bfloat16* __restrict__ lo, int n4)
{
    int i = blockIdx.x * 256 + threadIdx.x;
    if (i >= n4) return;
    float4 x = ((const float4*)in)[i];
    uint32_t h01, l01, h23, l23;
    pack_split(x.x, x.y, h01, l01);
    pack_split(x.z, x.w, h23, l23);
    ((uint2*)hi)[i] = make_uint2(h01, h23);
    ((uint2*)lo)[i] = make_uint2(l01, l23);
}

// ---------------- bf16 split-3 GEMM via mma.sync (HMMA) ----------------
// C[m,n] = sum_k A[m,k]*B[n,k].
// mode 0: fp32 out[m][n]; mode 1: Q (rope, scale, bf16 split [b,h,s,d]);
// mode 2: K (rope, bf16 split); mode 3: V (bf16 split)
#define SROWB 80
#define ARR_B (128 * SROWB)
#define STAGE_B (4 * ARR_B)
#define GSMEM (2 * STAGE_B)

__global__ __launch_bounds__(256) void gemm_bf16(
    const __nv_bfloat16* __restrict__ Ah, const __nv_bfloat16* __restrict__ Al,
    const __nv_bfloat16* __restrict__ Bh, const __nv_bfloat16* __restrict__ Bl,
    const int* __restrict__ pos, float* __restrict__ outf,
    __nv_bfloat16* __restrict__ outh, __nv_bfloat16* __restrict__ outl,
    int mode, float scale)
{
    extern __shared__ char smem[];
    const uint32_t sb32 = s2u(smem);
    int tid = threadIdx.x, lane = tid & 31, wid = tid >> 5;
    int m0 = blockIdx.y << 7, n0 = blockIdx.x << 7;
    int wm = (wid >> 2) << 6;
    int wn = (wid & 3) << 5;

    int frow = tid >> 1;
    int fh = tid & 1;
    const uint4* gAh = (const uint4*)(Ah + (size_t)(m0 + frow) * DM);
    const uint4* gAl = (const uint4*)(Al + (size_t)(m0 + frow) * DM);
    const uint4* gBh = (const uint4*)(Bh + (size_t)(n0 + frow) * DM);
    const uint4* gBl = (const uint4*)(Bl + (size_t)(n0 + frow) * DM);
    char* sfill = smem + frow * SROWB + fh * 32;

    float c[4][4][4] = {};
    uint4 st[8];

    #define LOADG(s) { \
        int bi = (s) * 4 + (fh << 1); \
        st[0] = gAh[bi]; st[1] = gAh[bi + 1]; \
        st[2] = gAl[bi]; st[3] = gAl[bi + 1]; \
        st[4] = gBh[bi]; st[5] = gBh[bi + 1]; \
        st[6] = gBl[bi]; st[7] = gBl[bi + 1]; }

    LOADG(0);

    for (int s = 0; s < 32; s++) {
        int buf = s & 1;
        __syncthreads();
        char* sp = sfill + buf * STAGE_B;
        *(uint4*)(sp + 0 * ARR_B)      = st[0];
        *(uint4*)(sp + 0 * ARR_B + 16) = st[1];
        *(uint4*)(sp + 1 * ARR_B)      = st[2];
        *(uint4*)(sp + 1 * ARR_B + 16) = st[3];
        *(uint4*)(sp + 2 * ARR_B)      = st[4];
        *(uint4*)(sp + 2 * ARR_B + 16) = st[5];
        *(uint4*)(sp + 3 * ARR_B)      = st[6];
        *(uint4*)(sp + 3 * ARR_B + 16) = st[7];
        __syncthreads();
        if (s < 31) LOADG(s + 1);

        uint32_t base = sb32 + buf * STAGE_B;
        uint32_t aRow = base + (uint32_t)(wm + (lane & 15)) * SROWB + ((lane >> 4) << 4);
        int q = lane >> 3;
        uint32_t bRow = base + 2 * ARR_B +
                        (uint32_t)(wn + ((q >> 1) << 3) + (lane & 7)) * SROWB +
                        ((q & 1) << 4);

        #pragma unroll
        for (int step = 0; step < 2; step++) {
            uint32_t ko = step * 32;
            uint32_t ah[4][4], al[4][4], bh[4][2], bl[4][2];
            #pragma unroll
            for (int mt = 0; mt < 4; mt++) {
                uint32_t aAddr = aRow + (uint32_t)(mt * 16) * SROWB + ko;
                LDSM4(ah[mt][0], ah[mt][1], ah[mt][2], ah[mt][3], aAddr);
                LDSM4(al[mt][0], al[mt][1], al[mt][2], al[mt][3], aAddr + ARR_B);
            }
            #pragma unroll
            for (int pn = 0; pn < 2; pn++) {
                uint32_t bAddr = bRow + (uint32_t)(pn * 16) * SROWB + ko;
                LDSM4(bh[2*pn][0], bh[2*pn][1], bh[2*pn+1][0], bh[2*pn+1][1], bAddr);
                LDSM4(bl[2*pn][0], bl[2*pn][1], bl[2*pn+1][0], bl[2*pn+1][1], bAddr + ARR_B);
            }
            #pragma unroll
            for (int mt = 0; mt < 4; mt++)
                #pragma unroll
                for (int nt = 0; nt < 4; nt++) {
                    MMA16816(c[mt][nt], ah[mt], bh[nt]);
                    MMA16816(c[mt][nt], ah[mt], bl[nt]);
                    MMA16816(c[mt][nt], al[mt], bh[nt]);
                }
        }
    }

    // ---------------- epilogue ----------------
    int gid = lane >> 2, tig = lane & 3;
    #pragma unroll
    for (int mt = 0; mt < 4; mt++) {
        int m_a = m0 + wm + mt * 16 + gid;
        int m_b = m_a + 8;
        float p_a = 0.f, p_b = 0.f;
        if (mode == 1 || mode == 2) { p_a = (float)pos[m_a]; p_b = (float)pos[m_b]; }
        #pragma unroll
        for (int nt = 0; nt < 4; nt++) {
            int n = n0 + wn + nt * 8 + tig * 2;
            float v0 = c[mt][nt][0], v1 = c[mt][nt][1];
            float v2 = c[mt][nt][2], v3 = c[mt][nt][3];
            if (mode == 0) {
                *(float2*)(outf + (size_t)m_a * DM + n) = make_float2(v0, v1);
                *(float2*)(outf + (size_t)m_b * DM + n) = make_float2(v2, v3);
            } else {
                int h = n >> 6, d = n & 63;
                if (mode != 3) {
                    rope_rot(p_a, (float)d, v0, v1);
                    rope_rot(p_b, (float)d, v2, v3);
                }
                v0 *= scale; v1 *= scale; v2 *= scale; v3 *= scale;
                int ba = m_a >> 12, sa = m_a & (SEQ - 1);
                int bb = m_b >> 12, sbq = m_b & (SEQ - 1);
                size_t ia = ((size_t)(ba * NH + h) * SEQ + sa) * DK + d;
                size_t ib = ((size_t)(bb * NH + h) * SEQ + sbq) * DK + d;
                uint32_t hp, lp;
                pack_split(v0, v1, hp, lp);
                *(uint32_t*)(outh + ia) = hp; *(uint32_t*)(outl + ia) = lp;
                pack_split(v2, v3, hp, lp);
                *(uint32_t*)(outh + ib) = hp; *(uint32_t*)(outl + ib) = lp;
            }
        }
    }
}

// ---------------- split-bf16 HMMA flash attention ----------------
// Q pre-scaled by 1/8 (folded in projection). CTA: 128q x 64k, 8 warps (16q each).
// smem: sKh 0, sKl 9216, sVh 18432, sVl 27648  (64 rows x 144B each) = 36864 B
// Q phase uses same buffer: sQh 0 (128x144), sQl 18432.
#define AROW 144
#define ASMEM 36864

__global__ __launch_bounds__(256) void attn_mma(
    const __nv_bfloat16* __restrict__ Qh, const __nv_bfloat16* __restrict__ Ql,
    const __nv_bfloat16* __restrict__ Kh, const __nv_bfloat16* __restrict__ Kl,
    const __nv_bfloat16* __restrict__ Vh, const __nv_bfloat16* __restrict__ Vl,
    float* __restrict__ O)
{
    extern __shared__ char sm[];
    uint32_t sb = s2u(sm);
    int tid = threadIdx.x, lane = tid & 31, w = tid >> 5;
    int qt = blockIdx.x, hh = blockIdx.y, bb = blockIdx.z;
    int q0 = qt << 7;
    size_t base = (size_t)(bb * NH + hh) * SEQ * DK;
    int gid = lane >> 2, tig = lane & 3;

    // ---- Q tile -> smem -> register fragments (held for whole CTA) ----
    {
        int row = tid >> 1, hf = tid & 1;
        const uint4* gqh = (const uint4*)(Qh + base + (size_t)(q0 + row) * DK);
        const uint4* gql = (const uint4*)(Ql + base + (size_t)(q0 + row) * DK);
        char* s0 = sm + row * AROW + hf * 64;
        #pragma unroll
        for (int j = 0; j < 4; j++) {
            *(uint4*)(s0 + j * 16)         = gqh[hf * 4 + j];
            *(uint4*)(s0 + 18432 + j * 16) = gql[hf * 4 + j];
        }
    }
    __syncthreads();
    uint32_t qfh[4][4], qfl[4][4];
    {
        uint32_t aAddr = sb + (uint32_t)((16 * w + (lane & 15)) * AROW + ((lane >> 4) << 4));
        #pragma unroll
        for (int ds = 0; ds < 4; ds++) {
            LDSM4(qfh[ds][0], qfh[ds][1], qfh[ds][2], qfh[ds][3], aAddr + ds * 32);
            LDSM4(qfl[ds][0], qfl[ds][1], qfl[ds][2], qfl[ds][3], aAddr + 18432 + ds * 32);
        }
    }

    float o_[8][4] = {};
    float m0 = -1e30f, m1 = -1e30f, l0 = 0.f, l1 = 0.f;
    int q0w = q0 + 16 * w;
    int qg = lane >> 3;
    // K b-frag (validated non-trans [n][k] pattern, n = k-col, contraction = d)
    uint32_t kOff = (uint32_t)(((((qg >> 1) << 3) | (lane & 7)) * AROW) + ((qg & 1) << 4));
    // V b-frag via ldmatrix.trans from [k][d]: rows k, byte = n(d)
    uint32_t vOff = (uint32_t)(((((qg & 1) << 3) | (lane & 7)) * AROW) + ((qg >> 1) << 4));

    int niter = 2 * qt + 2;
    for (int kt = 0; kt < niter; kt++) {
        int k0 = kt << 6;
        __syncthreads();
        for (int cc = tid; cc < 512; cc += 256) {
            int row = cc >> 3, col = cc & 7;
            size_t g = base + (size_t)(k0 + row) * DK + col * 8;
            *(uint4*)(sm +         row * AROW + col * 16) = *(const uint4*)(Kh + g);
            *(uint4*)(sm +  9216 + row * AROW + col * 16) = *(const uint4*)(Kl + g);
            *(uint4*)(sm + 18432 + row * AROW + col * 16) = *(const uint4*)(Vh + g);
            *(uint4*)(sm + 27648 + row * AROW + col * 16) = *(const uint4*)(Vl + g);
        }
        __syncthreads();

        // S = Q K^T (3-pass split)
        float s_[8][4] = {};
        #pragma unroll
        for (int ds = 0; ds < 4; ds++) {
            uint32_t bh[8][2], bl[8][2];
            #pragma unroll
            for (int p = 0; p < 4; p++) {
                uint32_t ba_ = sb + kOff + (uint32_t)(p * 16 * AROW) + ds * 32;
                LDSM4(bh[2*p][0], bh[2*p][1], bh[2*p+1][0], bh[2*p+1][1], ba_);
                LDSM4(bl[2*p][0], bl[2*p][1], bl[2*p+1][0], bl[2*p+1][1], ba_ + 9216);
            }
            #pragma unroll
            for (int j = 0; j < 8; j++) {
                MMA16816(s_[j], qfh[ds], bh[j]);
                MMA16816(s_[j], qfh[ds], bl[j]);
                MMA16816(s_[j], qfl[ds], bh[j]);
            }
        }

        // causal mask (only tiles crossing this warp's rows)
        if (k0 + 63 > q0w) {
            int r0 = q0w + gid, r1 = r0 + 8;
            #pragma unroll
            for (int j = 0; j < 8; j++) {
                int cb = k0 + 8 * j + 2 * tig;
                if (cb     > r0) s_[j][0] = -1e30f;
                if (cb + 1 > r0) s_[j][1] = -1e30f;
                if (cb     > r1) s_[j][2] = -1e30f;
                if (cb + 1 > r1) s_[j][3] = -1e30f;
            }
        }

        // online softmax (poly exp, no MUFU)
        float mx0 = s_[0][0], mx1 = s_[0][2];
        #pragma unroll
        for (int j = 0; j < 8; j++) {
            mx0 = fmaxf(mx0, fmaxf(s_[j][0], s_[j][1]));
            mx1 = fmaxf(mx1, fmaxf(s_[j][2], s_[j][3]));
        }
        mx0 = fmaxf(mx0, __shfl_xor_sync(0xffffffffu, mx0, 1));
        mx0 = fmaxf(mx0, __shfl_xor_sync(0xffffffffu, mx0, 2));
        mx1 = fmaxf(mx1, __shfl_xor_sync(0xffffffffu, mx1, 1));
        mx1 = fmaxf(mx1, __shfl_xor_sync(0xffffffffu, mx1, 2));
        float mn0 = fmaxf(m0, mx0), mn1 = fmaxf(m1, mx1);
        float c0 = fexp(m0 - mn0), c1 = fexp(m1 - mn1);
        m0 = mn0; m1 = mn1;
        float rs0 = 0.f, rs1 = 0.f;
        #pragma unroll
        for (int j = 0; j < 8; j++) {
            s_[j][0] = fexp(s_[j][0] - mn0);
            s_[j][1] = fexp(s_[j][1] - mn0);
            s_[j][2] = fexp(s_[j][2] - mn1);
            s_[j][3] = fexp(s_[j][3] - mn1);
            rs0 += s_[j][0] + s_[j][1];
            rs1 += s_[j][2] + s_[j][3];
        }
        rs0 += __shfl_xor_sync(0xffffffffu, rs0, 1);
        rs0 += __shfl_xor_sync(0xffffffffu, rs0, 2);
        rs1 += __shfl_xor_sync(0xffffffffu, rs1, 1);
        rs1 += __shfl_xor_sync(0xffffffffu, rs1, 2);
        l0 = l0 * c0 + rs0; l1 = l1 * c1 + rs1;
        #pragma unroll
        for (int j = 0; j < 8; j++) {
            o_[j][0] *= c0; o_[j][1] *= c0; o_[j][2] *= c1; o_[j][3] *= c1;
        }

        // P: C-frag pairs -> A-frags in registers (no shuffle), split hi/lo
        uint32_t pfh[4][4], pfl[4][4];
        #pragma unroll
        for (int ks = 0; ks < 4; ks++) {
            int j0 = 2 * ks, j1 = 2 * ks + 1;
            pack_split(s_[j0][0], s_[j0][1], pfh[ks][0], pfl[ks][0]);
            pack_split(s_[j0][2], s_[j0][3], pfh[ks][1], pfl[ks][1]);
            pack_split(s_[j1][0], s_[j1][1], pfh[ks][2], pfl[ks][2]);
            pack_split(s_[j1][2], s_[j1][3], pfh[ks][3], pfl[ks][3]);
        }

        // O += P V (3-pass split), V frags via ldmatrix.trans
        #pragma unroll
        for (int ks = 0; ks < 4; ks++) {
            uint32_t vh[8][2], vl[8][2];
            #pragma unroll
            for (int p = 0; p < 4; p++) {
                uint32_t ba_ = sb + 18432 + vOff + (uint32_t)(ks * 16 * AROW) + p * 32;
                LDSM4T(vh[2*p][0], vh[2*p][1], vh[2*p+1][0], vh[2*p+1][1], ba_);
                LDSM4T(vl[2*p][0], vl[2*p][1], vl[2*p+1][0], vl[2*p+1][1], ba_ + 9216);
            }
            #pragma unroll
            for (int j = 0; j < 8; j++) {
                MMA16816(o_[j], pfh[ks], vh[j]);
                MMA16816(o_[j], pfh[ks], vl[j]);
                MMA16816(o_[j], pfl[ks], vh[j]);
            }
        }
    }

    // finalize
    float inv0 = 1.0f / l0, inv1 = 1.0f / l1;
    int r0 = q0 + 16 * w + gid, r1 = r0 + 8;
    float* O0 = O + ((size_t)bb * SEQ + r0) * DM + hh * DK + 2 * tig;
    float* O1 = O + ((size_t)bb * SEQ + r1) * DM + hh * DK + 2 * tig;
    #pragma unroll
    for (int j = 0; j < 8; j++) {
        *(float2*)(O0 + 8 * j) = make_float2(o_[j][0] * inv0, o_[j][1] * inv0);
        *(float2*)(O1 + 8 * j) = make_float2(o_[j][2] * inv1, o_[j][3] * inv1);
    }
}

// ---------------- launch ----------------
extern "C" void kernel_launch(void* const* d_in, const int* in_sizes, int n_in,
                              void* d_out, int out_size) {
    (void)in_sizes; (void)n_in; (void)out_size;
    const float* x   = (const float*)d_in[0];
    const int*   pos = (const int*)d_in[1];
    const float* Wq  = (const float*)d_in[2];
    const float* Wk  = (const float*)d_in[3];
    const float* Wv  = (const float*)d_in[4];
    const float* Wo  = (const float*)d_in[5];
    float* out = (float*)d_out;

    __nv_bfloat16 *xh, *xl, *wh, *wl, *qh, *ql, *kh, *kl, *vh, *vl;
    float* o;
    cudaGetSymbolAddress((void**)&xh, g_xh);
    cudaGetSymbolAddress((void**)&xl, g_xl);
    cudaGetSymbolAddress((void**)&wh, g_wh);
    cudaGetSymbolAddress((void**)&wl, g_wl);
    cudaGetSymbolAddress((void**)&qh, g_qh);
    cudaGetSymbolAddress((void**)&ql, g_ql);
    cudaGetSymbolAddress((void**)&kh, g_kh);
    cudaGetSymbolAddress((void**)&kl, g_kl);
    cudaGetSymbolAddress((void**)&vh, g_vh);
    cudaGetSymbolAddress((void**)&vl, g_vl);
    cudaGetSymbolAddress((void**)&o, g_o);

    cudaFuncSetAttribute(gemm_bf16, cudaFuncAttributeMaxDynamicSharedMemorySize, GSMEM);
    cudaFuncSetAttribute(attn_mma, cudaFuncAttributeMaxDynamicSharedMemorySize, ASMEM);

    const int n4x = MTOT * DM / 4;
    const int n4w = DM * DM / 4;
    const size_t WS = (size_t)DM * DM;

    split_kernel<<<n4x / 256, 256>>>(x, xh, xl, n4x);
    split_kernel<<<n4w / 256, 256>>>(Wq, wh + 0 * WS, wl + 0 * WS, n4w);
    split_kernel<<<n4w / 256, 256>>>(Wk, wh + 1 * WS, wl + 1 * WS, n4w);
    split_kernel<<<n4w / 256, 256>>>(Wv, wh + 2 * WS, wl + 2 * WS, n4w);
    split_kernel<<<n4w / 256, 256>>>(Wo, wh + 3 * WS, wl + 3 * WS, n4w);

    dim3 ggrid(DM / 128, MTOT / 128);
    gemm_bf16<<<ggrid, 256, GSMEM>>>(xh, xl, wh + 0 * WS, wl + 0 * WS, pos,
                                     nullptr, qh, ql, 1, 0.125f);
    gemm_bf16<<<ggrid, 256, GSMEM>>>(xh, xl, wh + 1 * WS, wl + 1 * WS, pos,
                                     nullptr, kh, kl, 2, 1.0f);
    gemm_bf16<<<ggrid, 256, GSMEM>>>(xh, xl, wh + 2 * WS, wl + 2 * WS, pos,
                                     nullptr, vh, vl, 3, 1.0f);

    dim3 agrid(SEQ / 128, NH, BATCHN);
    attn_mma<<<agrid, 256, ASMEM>>>(qh, ql, kh, kl, vh, vl, o);

    split_kernel<<<n4x / 256, 256>>>(o, xh, xl, n4x);
    gemm_bf16<<<ggrid, 256, GSMEM>>>(xh, xl, wh + 3 * WS, wl + 3 * WS, pos,
                                     out, nullptr, nullptr, 0, 1.0f);
}

// round 7
// speedup vs baseline: 2.4721x; 1.0384x over previous
#include <cuda_runtime.h>
#include <cuda_bf16.h>
#include <math.h>
#include <stdint.h>

#define SEQ 4096
#define DM 1024
#define NH 16
#define DK 64
#define BATCHN 2
#define MTOT (BATCHN*SEQ)

// ---------------- scratch (allocation-free) ----------------
__device__ __nv_bfloat16 g_xh[(size_t)MTOT * DM];
__device__ __nv_bfloat16 g_xl[(size_t)MTOT * DM];
__device__ __nv_bfloat16 g_wh[(size_t)4 * DM * DM];
__device__ __nv_bfloat16 g_wl[(size_t)4 * DM * DM];
__device__ __nv_bfloat16 g_qh[(size_t)MTOT * DM];
__device__ __nv_bfloat16 g_ql[(size_t)MTOT * DM];
__device__ __nv_bfloat16 g_kh[(size_t)MTOT * DM];
__device__ __nv_bfloat16 g_kl[(size_t)MTOT * DM];
__device__ __nv_bfloat16 g_vh[(size_t)MTOT * DM];
__device__ __nv_bfloat16 g_vl[(size_t)MTOT * DM];
__device__ float g_o[(size_t)MTOT * DM];

// ---------------- helpers ----------------
__device__ __forceinline__ uint32_t s2u(const void* p) {
    uint32_t a;
    asm("{ .reg .u64 t; cvta.to.shared.u64 t, %1; cvt.u32.u64 %0, t; }" : "=r"(a) : "l"(p));
    return a;
}

// RoPE rotation; Cody-Waite 2*pi reduction (robust under fast-math).
__device__ __forceinline__ void rope_rot(float p, float d_e, float& e, float& o) {
    const float LOG2_THETA_DIV = 13.287712379549449f / 64.0f;
    float freq = exp2f(-d_e * LOG2_THETA_DIV);
    float ang = p * freq;
    float n = rintf(ang * 0.15915494309189535f);
    float r = fmaf(-n, 6.28125f, ang);
    r = fmaf(-n, 1.9353071795864774e-3f, r);
    float s, c;
    sincosf(r, &s, &c);
    float ne = e * c - o * s;
    float no = e * s + o * c;
    e = ne; o = no;
}

// Fast exp for x <= 0 on the FMA/ALU pipes (no MUFU). ~1e-6 rel err.
__device__ __forceinline__ float fexp(float x) {
    float t = fmaxf(x * 1.4426950408889634f, -126.0f);
    float z = t + 12582912.0f;
    int ii = __float_as_int(z);
    float f = t - (z - 12582912.0f);
    float p = 1.3333558e-3f;
    p = fmaf(p, f, 9.6181291e-3f);
    p = fmaf(p, f, 5.5504109e-2f);
    p = fmaf(p, f, 2.4022651e-1f);
    p = fmaf(p, f, 6.9314718e-1f);
    p = fmaf(p, f, 1.0f);
    return __int_as_float((ii << 23) + 0x3F800000) * p;
}

__device__ __forceinline__ void pack_split(float a, float b, uint32_t& hp, uint32_t& lp) {
    __nv_bfloat162 H = __floats2bfloat162_rn(a, b);
    hp = *(uint32_t*)&H;
    float ra = a - __bfloat162float(H.x);
    float rb = b - __bfloat162float(H.y);
    __nv_bfloat162 L = __floats2bfloat162_rn(ra, rb);
    lp = *(uint32_t*)&L;
}

#define LDSM4(r0, r1, r2, r3, addr) \
    asm volatile("ldmatrix.sync.aligned.m8n8.x4.shared.b16 {%0,%1,%2,%3}, [%4];" \
        : "=r"(r0), "=r"(r1), "=r"(r2), "=r"(r3) : "r"(addr))

#define LDSM4T(r0, r1, r2, r3, addr) \
    asm volatile("ldmatrix.sync.aligned.m8n8.x4.trans.shared.b16 {%0,%1,%2,%3}, [%4];" \
        : "=r"(r0), "=r"(r1), "=r"(r2), "=r"(r3) : "r"(addr))

#define MMA16816(c, a, b) \
    asm volatile("mma.sync.aligned.m16n8k16.row.col.f32.bf16.bf16.f32 " \
        "{%0,%1,%2,%3}, {%4,%5,%6,%7}, {%8,%9}, {%0,%1,%2,%3};" \
        : "+f"((c)[0]), "+f"((c)[1]), "+f"((c)[2]), "+f"((c)[3]) \
        : "r"((a)[0]), "r"((a)[1]), "r"((a)[2]), "r"((a)[3]), "r"((b)[0]), "r"((b)[1]))

#define CPA16(dst, src) \
    asm volatile("cp.async.cg.shared.global [%0], [%1], 16;" :: "r"(dst), "l"(src))
#define CPCOMMIT() asm volatile("cp.async.commit_group;" ::: "memory")
#define CPWAIT(n)  asm volatile("cp.async.wait_group %0;" :: "n"(n) : "memory")

// ---------------- split kernel: fp32 -> (bf16 hi, bf16 lo) ----------------
__global__ __launch_bounds__(256) void split_kernel(
    const float* __restrict__ in, __nv_bfloat16* __restrict__ hi,
    __nv_bfloat16* __restrict__ lo, int n4)
{
    int i = blockIdx.x * 256 + threadIdx.x;
    if (i >= n4) return;
    float4 x = ((const float4*)in)[i];
    uint32_t h01, l01, h23, l23;
    pack_split(x.x, x.y, h01, l01);
    pack_split(x.z, x.w, h23, l23);
    ((uint2*)hi)[i] = make_uint2(h01, h23);
    ((uint2*)lo)[i] = make_uint2(l01, l23);
}

// ---------------- bf16 split-3 GEMM via mma.sync, cp.async 4-stage ----------------
#define SROWB 80
#define ARR_B (128 * SROWB)
#define STAGE_B (4 * ARR_B)     // 40960
#define NSTAGE 4
#define GSMEM (NSTAGE * STAGE_B) // 163840

__global__ __launch_bounds__(256) void gemm_bf16(
    const __nv_bfloat16* __restrict__ Ah, const __nv_bfloat16* __restrict__ Al,
    const __nv_bfloat16* __restrict__ Bh, const __nv_bfloat16* __restrict__ Bl,
    const int* __restrict__ pos, float* __restrict__ outf,
    __nv_bfloat16* __restrict__ outh, __nv_bfloat16* __restrict__ outl,
    int mode, float scale)
{
    extern __shared__ char smem[];
    const uint32_t sb32 = s2u(smem);
    int tid = threadIdx.x, lane = tid & 31, wid = tid >> 5;
    int m0 = blockIdx.y << 7, n0 = blockIdx.x << 7;
    int wm = (wid >> 2) << 6;
    int wn = (wid & 3) << 5;

    int frow = tid >> 1;
    int fh = tid & 1;
    const uint4* gAh = (const uint4*)(Ah + (size_t)(m0 + frow) * DM);
    const uint4* gAl = (const uint4*)(Al + (size_t)(m0 + frow) * DM);
    const uint4* gBh = (const uint4*)(Bh + (size_t)(n0 + frow) * DM);
    const uint4* gBl = (const uint4*)(Bl + (size_t)(n0 + frow) * DM);
    uint32_t sfill = sb32 + (uint32_t)(frow * SROWB + fh * 32);

    #define GISSUE(s_) { \
        int bi = (s_) * 4 + (fh << 1); \
        uint32_t d0 = sfill + ((s_) & (NSTAGE - 1)) * STAGE_B; \
        CPA16(d0 + 0 * ARR_B,      gAh + bi); \
        CPA16(d0 + 0 * ARR_B + 16, gAh + bi + 1); \
        CPA16(d0 + 1 * ARR_B,      gAl + bi); \
        CPA16(d0 + 1 * ARR_B + 16, gAl + bi + 1); \
        CPA16(d0 + 2 * ARR_B,      gBh + bi); \
        CPA16(d0 + 2 * ARR_B + 16, gBh + bi + 1); \
        CPA16(d0 + 3 * ARR_B,      gBl + bi); \
        CPA16(d0 + 3 * ARR_B + 16, gBl + bi + 1); }

    float c[4][4][4] = {};

    GISSUE(0); CPCOMMIT();
    GISSUE(1); CPCOMMIT();
    GISSUE(2); CPCOMMIT();

    for (int s = 0; s < 32; s++) {
        CPWAIT(2);              // stage s resident (2 newer groups may pend)
        __syncthreads();        // data visible; compute s-1 fully done
        if (s + 3 < 32) GISSUE(s + 3);
        CPCOMMIT();             // uniform group count (empty group ok)

        uint32_t base = sb32 + (uint32_t)(s & (NSTAGE - 1)) * STAGE_B;
        uint32_t aRow = base + (uint32_t)(wm + (lane & 15)) * SROWB + ((lane >> 4) << 4);
        int q = lane >> 3;
        uint32_t bRow = base + 2 * ARR_B +
                        (uint32_t)(wn + ((q >> 1) << 3) + (lane & 7)) * SROWB +
                        ((q & 1) << 4);

        #pragma unroll
        for (int step = 0; step < 2; step++) {
            uint32_t ko = step * 32;
            uint32_t ah[4][4], al[4][4], bh[4][2], bl[4][2];
            #pragma unroll
            for (int mt = 0; mt < 4; mt++) {
                uint32_t aAddr = aRow + (uint32_t)(mt * 16) * SROWB + ko;
                LDSM4(ah[mt][0], ah[mt][1], ah[mt][2], ah[mt][3], aAddr);
                LDSM4(al[mt][0], al[mt][1], al[mt][2], al[mt][3], aAddr + ARR_B);
            }
            #pragma unroll
            for (int pn = 0; pn < 2; pn++) {
                uint32_t bAddr = bRow + (uint32_t)(pn * 16) * SROWB + ko;
                LDSM4(bh[2*pn][0], bh[2*pn][1], bh[2*pn+1][0], bh[2*pn+1][1], bAddr);
                LDSM4(bl[2*pn][0], bl[2*pn][1], bl[2*pn+1][0], bl[2*pn+1][1], bAddr + ARR_B);
            }
            #pragma unroll
            for (int mt = 0; mt < 4; mt++)
                #pragma unroll
                for (int nt = 0; nt < 4; nt++) {
                    MMA16816(c[mt][nt], ah[mt], bh[nt]);
                    MMA16816(c[mt][nt], ah[mt], bl[nt]);
                    MMA16816(c[mt][nt], al[mt], bh[nt]);
                }
        }
    }

    // ---------------- epilogue ----------------
    int gid = lane >> 2, tig = lane & 3;
    #pragma unroll
    for (int mt = 0; mt < 4; mt++) {
        int m_a = m0 + wm + mt * 16 + gid;
        int m_b = m_a + 8;
        float p_a = 0.f, p_b = 0.f;
        if (mode == 1 || mode == 2) { p_a = (float)pos[m_a]; p_b = (float)pos[m_b]; }
        #pragma unroll
        for (int nt = 0; nt < 4; nt++) {
            int n = n0 + wn + nt * 8 + tig * 2;
            float v0 = c[mt][nt][0], v1 = c[mt][nt][1];
            float v2 = c[mt][nt][2], v3 = c[mt][nt][3];
            if (mode == 0) {
                *(float2*)(outf + (size_t)m_a * DM + n) = make_float2(v0, v1);
                *(float2*)(outf + (size_t)m_b * DM + n) = make_float2(v2, v3);
            } else {
                int h = n >> 6, d = n & 63;
                if (mode != 3) {
                    rope_rot(p_a, (float)d, v0, v1);
                    rope_rot(p_b, (float)d, v2, v3);
                }
                v0 *= scale; v1 *= scale; v2 *= scale; v3 *= scale;
                int ba = m_a >> 12, sa = m_a & (SEQ - 1);
                int bb = m_b >> 12, sbq = m_b & (SEQ - 1);
                size_t ia = ((size_t)(ba * NH + h) * SEQ + sa) * DK + d;
                size_t ib = ((size_t)(bb * NH + h) * SEQ + sbq) * DK + d;
                uint32_t hp, lp;
                pack_split(v0, v1, hp, lp);
                *(uint32_t*)(outh + ia) = hp; *(uint32_t*)(outl + ia) = lp;
                pack_split(v2, v3, hp, lp);
                *(uint32_t*)(outh + ib) = hp; *(uint32_t*)(outl + ib) = lp;
            }
        }
    }
}

// ---------------- split-bf16 HMMA flash attention, cp.async 2-stage ----------------
#define AROW 144
#define ASTG 36864
#define ASMEM (2 * ASTG)

__global__ __launch_bounds__(256) void attn_mma(
    const __nv_bfloat16* __restrict__ Qh, const __nv_bfloat16* __restrict__ Ql,
    const __nv_bfloat16* __restrict__ Kh, const __nv_bfloat16* __restrict__ Kl,
    const __nv_bfloat16* __restrict__ Vh, const __nv_bfloat16* __restrict__ Vl,
    float* __restrict__ O)
{
    extern __shared__ char sm[];
    uint32_t sb = s2u(sm);
    int tid = threadIdx.x, lane = tid & 31, w = tid >> 5;
    int qt = blockIdx.x, hh = blockIdx.y, bb = blockIdx.z;
    int q0 = qt << 7;
    size_t base = (size_t)(bb * NH + hh) * SEQ * DK;
    int gid = lane >> 2, tig = lane & 3;

    // ---- Q tile -> smem (buf0) -> register fragments ----
    {
        int row = tid >> 1, hf = tid & 1;
        const uint4* gqh = (const uint4*)(Qh + base + (size_t)(q0 + row) * DK);
        const uint4* gql = (const uint4*)(Ql + base + (size_t)(q0 + row) * DK);
        char* s0 = sm + row * AROW + hf * 64;
        #pragma unroll
        for (int j = 0; j < 4; j++) {
            *(uint4*)(s0 + j * 16)         = gqh[hf * 4 + j];
            *(uint4*)(s0 + 18432 + j * 16) = gql[hf * 4 + j];
        }
    }
    __syncthreads();
    uint32_t qfh[4][4], qfl[4][4];
    {
        uint32_t aAddr = sb + (uint32_t)((16 * w + (lane & 15)) * AROW + ((lane >> 4) << 4));
        #pragma unroll
        for (int ds = 0; ds < 4; ds++) {
            LDSM4(qfh[ds][0], qfh[ds][1], qfh[ds][2], qfh[ds][3], aAddr + ds * 32);
            LDSM4(qfl[ds][0], qfl[ds][1], qfl[ds][2], qfl[ds][3], aAddr + 18432 + ds * 32);
        }
    }
    __syncthreads();  // everyone's Q frags read before buf0 is overwritten

    // per-thread fill coords: 2 rows (tid>>3 stride 32? keep cc loop unrolled)
    int frow0 = tid >> 3, fcol = tid & 7;  // rows tid>>3 and +32
    uint32_t fdst = sb + (uint32_t)(frow0 * AROW + fcol * 16);

    #define AISSUE(kt_, buf_) { \
        size_t g0 = base + (size_t)(((kt_) << 6) + frow0) * DK + fcol * 8; \
        size_t g1 = g0 + 32 * DK; \
        uint32_t d0 = fdst + (buf_) * (uint32_t)ASTG; \
        uint32_t d1 = d0 + 32 * AROW; \
        CPA16(d0,         Kh + g0); CPA16(d1,         Kh + g1); \
        CPA16(d0 +  9216, Kl + g0); CPA16(d1 +  9216, Kl + g1); \
        CPA16(d0 + 18432, Vh + g0); CPA16(d1 + 18432, Vh + g1); \
        CPA16(d0 + 27648, Vl + g0); CPA16(d1 + 27648, Vl + g1); }

    float o_[8][4] = {};
    float m0 = -1e30f, m1 = -1e30f, l0 = 0.f, l1 = 0.f;
    int q0w = q0 + 16 * w;
    int qg = lane >> 3;
    uint32_t kOff = (uint32_t)(((((qg >> 1) << 3) | (lane & 7)) * AROW) + ((qg & 1) << 4));
    uint32_t vOff = (uint32_t)(((((qg & 1) << 3) | (lane & 7)) * AROW) + ((qg >> 1) << 4));

    int niter = 2 * qt + 2;
    AISSUE(0, 0); CPCOMMIT();

    for (int kt = 0; kt < niter; kt++) {
        int k0 = kt << 6;
        int buf = kt & 1;
        CPWAIT(0);              // stage kt resident
        __syncthreads();        // visible to all; compute kt-1 done
        if (kt + 1 < niter) { AISSUE(kt + 1, buf ^ 1); CPCOMMIT(); }

        uint32_t sK = sb + (uint32_t)buf * ASTG;

        // S = Q K^T (3-pass split)
        float s_[8][4] = {};
        #pragma unroll
        for (int ds = 0; ds < 4; ds++) {
            uint32_t bh[8][2], bl[8][2];
            #pragma unroll
            for (int p = 0; p < 4; p++) {
                uint32_t ba_ = sK + kOff + (uint32_t)(p * 16 * AROW) + ds * 32;
                LDSM4(bh[2*p][0], bh[2*p][1], bh[2*p+1][0], bh[2*p+1][1], ba_);
                LDSM4(bl[2*p][0], bl[2*p][1], bl[2*p+1][0], bl[2*p+1][1], ba_ + 9216);
            }
            #pragma unroll
            for (int j = 0; j < 8; j++) {
                MMA16816(s_[j], qfh[ds], bh[j]);
                MMA16816(s_[j], qfh[ds], bl[j]);
                MMA16816(s_[j], qfl[ds], bh[j]);
            }
        }

        // causal mask
        if (k0 + 63 > q0w) {
            int r0 = q0w + gid, r1 = r0 + 8;
            #pragma unroll
            for (int j = 0; j < 8; j++) {
                int cb = k0 + 8 * j + 2 * tig;
                if (cb     > r0) s_[j][0] = -1e30f;
                if (cb + 1 > r0) s_[j][1] = -1e30f;
                if (cb     > r1) s_[j][2] = -1e30f;
                if (cb + 1 > r1) s_[j][3] = -1e30f;
            }
        }

        // online softmax (poly exp)
        float mx0 = s_[0][0], mx1 = s_[0][2];
        #pragma unroll
        for (int j = 0; j < 8; j++) {
            mx0 = fmaxf(mx0, fmaxf(s_[j][0], s_[j][1]));
            mx1 = fmaxf(mx1, fmaxf(s_[j][2], s_[j][3]));
        }
        mx0 = fmaxf(mx0, __shfl_xor_sync(0xffffffffu, mx0, 1));
        mx0 = fmaxf(mx0, __shfl_xor_sync(0xffffffffu, mx0, 2));
        mx1 = fmaxf(mx1, __shfl_xor_sync(0xffffffffu, mx1, 1));
        mx1 = fmaxf(mx1, __shfl_xor_sync(0xffffffffu, mx1, 2));
        float mn0 = fmaxf(m0, mx0), mn1 = fmaxf(m1, mx1);
        float c0 = fexp(m0 - mn0), c1 = fexp(m1 - mn1);
        m0 = mn0; m1 = mn1;
        float rs0 = 0.f, rs1 = 0.f;
        #pragma unroll
        for (int j = 0; j < 8; j++) {
            s_[j][0] = fexp(s_[j][0] - mn0);
            s_[j][1] = fexp(s_[j][1] - mn0);
            s_[j][2] = fexp(s_[j][2] - mn1);
            s_[j][3] = fexp(s_[j][3] - mn1);
            rs0 += s_[j][0] + s_[j][1];
            rs1 += s_[j][2] + s_[j][3];
        }
        rs0 += __shfl_xor_sync(0xffffffffu, rs0, 1);
        rs0 += __shfl_xor_sync(0xffffffffu, rs0, 2);
        rs1 += __shfl_xor_sync(0xffffffffu, rs1, 1);
        rs1 += __shfl_xor_sync(0xffffffffu, rs1, 2);
        l0 = l0 * c0 + rs0; l1 = l1 * c1 + rs1;
        #pragma unroll
        for (int j = 0; j < 8; j++) {
            o_[j][0] *= c0; o_[j][1] *= c0; o_[j][2] *= c1; o_[j][3] *= c1;
        }

        // P -> A-frags in registers, split hi/lo
        uint32_t pfh[4][4], pfl[4][4];
        #pragma unroll
        for (int ks = 0; ks < 4; ks++) {
            int j0 = 2 * ks, j1 = 2 * ks + 1;
            pack_split(s_[j0][0], s_[j0][1], pfh[ks][0], pfl[ks][0]);
            pack_split(s_[j0][2], s_[j0][3], pfh[ks][1], pfl[ks][1]);
            pack_split(s_[j1][0], s_[j1][1], pfh[ks][2], pfl[ks][2]);
            pack_split(s_[j1][2], s_[j1][3], pfh[ks][3], pfl[ks][3]);
        }

        // O += P V (3-pass split)
        #pragma unroll
        for (int ks = 0; ks < 4; ks++) {
            uint32_t vh[8][2], vl[8][2];
            #pragma unroll
            for (int p = 0; p < 4; p++) {
                uint32_t ba_ = sK + 18432 + vOff + (uint32_t)(ks * 16 * AROW) + p * 32;
                LDSM4T(vh[2*p][0], vh[2*p][1], vh[2*p+1][0], vh[2*p+1][1], ba_);
                LDSM4T(vl[2*p][0], vl[2*p][1], vl[2*p+1][0], vl[2*p+1][1], ba_ + 9216);
            }
            #pragma unroll
            for (int j = 0; j < 8; j++) {
                MMA16816(o_[j], pfh[ks], vh[j]);
                MMA16816(o_[j], pfh[ks], vl[j]);
                MMA16816(o_[j], pfl[ks], vh[j]);
            }
        }
    }

    // finalize
    float inv0 = 1.0f / l0, inv1 = 1.0f / l1;
    int r0 = q0 + 16 * w + gid, r1 = r0 + 8;
    float* O0 = O + ((size_t)bb * SEQ + r0) * DM + hh * DK + 2 * tig;
    float* O1 = O + ((size_t)bb * SEQ + r1) * DM + hh * DK + 2 * tig;
    #pragma unroll
    for (int j = 0; j < 8; j++) {
        *(float2*)(O0 + 8 * j) = make_float2(o_[j][0] * inv0, o_[j][1] * inv0);
        *(float2*)(O1 + 8 * j) = make_float2(o_[j][2] * inv1, o_[j][3] * inv1);
    }
}

// ---------------- launch ----------------
extern "C" void kernel_launch(void* const* d_in, const int* in_sizes, int n_in,
                              void* d_out, int out_size) {
    (void)in_sizes; (void)n_in; (void)out_size;
    const float* x   = (const float*)d_in[0];
    const int*   pos = (const int*)d_in[1];
    const float* Wq  = (const float*)d_in[2];
    const float* Wk  = (const float*)d_in[3];
    const float* Wv  = (const float*)d_in[4];
    const float* Wo  = (const float*)d_in[5];
    float* out = (float*)d_out;

    __nv_bfloat16 *xh, *xl, *wh, *wl, *qh, *ql, *kh, *kl, *vh, *vl;
    float* o;
    cudaGetSymbolAddress((void**)&xh, g_xh);
    cudaGetSymbolAddress((void**)&xl, g_xl);
    cudaGetSymbolAddress((void**)&wh, g_wh);
    cudaGetSymbolAddress((void**)&wl, g_wl);
    cudaGetSymbolAddress((void**)&qh, g_qh);
    cudaGetSymbolAddress((void**)&ql, g_ql);
    cudaGetSymbolAddress((void**)&kh, g_kh);
    cudaGetSymbolAddress((void**)&kl, g_kl);
    cudaGetSymbolAddress((void**)&vh, g_vh);
    cudaGetSymbolAddress((void**)&vl, g_vl);
    cudaGetSymbolAddress((void**)&o, g_o);

    cudaFuncSetAttribute(gemm_bf16, cudaFuncAttributeMaxDynamicSharedMemorySize, GSMEM);
    cudaFuncSetAttribute(attn_mma, cudaFuncAttributeMaxDynamicSharedMemorySize, ASMEM);

    const int n4x = MTOT * DM / 4;
    const int n4w = DM * DM / 4;
    const size_t WS = (size_t)DM * DM;

    split_kernel<<<n4x / 256, 256>>>(x, xh, xl, n4x);
    split_kernel<<<n4w / 256, 256>>>(Wq, wh + 0 * WS, wl + 0 * WS, n4w);
    split_kernel<<<n4w / 256, 256>>>(Wk, wh + 1 * WS, wl + 1 * WS, n4w);
    split_kernel<<<n4w / 256, 256>>>(Wv, wh + 2 * WS, wl + 2 * WS, n4w);
    split_kernel<<<n4w / 256, 256>>>(Wo, wh + 3 * WS, wl + 3 * WS, n4w);

    dim3 ggrid(DM / 128, MTOT / 128);
    gemm_bf16<<<ggrid, 256, GSMEM>>>(xh, xl, wh + 0 * WS, wl + 0 * WS, pos,
                                     nullptr, qh, ql, 1, 0.125f);
    gemm_bf16<<<ggrid, 256, GSMEM>>>(xh, xl, wh + 1 * WS, wl + 1 * WS, pos,
                                     nullptr, kh, kl, 2, 1.0f);
    gemm_bf16<<<ggrid, 256, GSMEM>>>(xh, xl, wh + 2 * WS, wl + 2 * WS, pos,
                                     nullptr, vh, vl, 3, 1.0f);

    dim3 agrid(SEQ / 128, NH, BATCHN);
    attn_mma<<<agrid, 256, ASMEM>>>(qh, ql, kh, kl, vh, vl, o);

    split_kernel<<<n4x / 256, 256>>>(o, xh, xl, n4x);
    gemm_bf16<<<ggrid, 256, GSMEM>>>(xh, xl, wh + 3 * WS, wl + 3 * WS, pos,
                                     out, nullptr, nullptr, 0, 1.0f);
}

// round 8
// speedup vs baseline: 2.4989x; 1.0109x over previous
#include <cuda_runtime.h>
#include <cuda_fp16.h>
#include <math.h>
#include <stdint.h>

#define SEQ 4096
#define DM 1024
#define NH 16
#define DK 64
#define BATCHN 2
#define MTOT (BATCHN*SEQ)

// ---------------- scratch (allocation-free) ----------------
__device__ __half g_xh[(size_t)MTOT * DM];
__device__ __half g_xl[(size_t)MTOT * DM];
__device__ __half g_wh[(size_t)4 * DM * DM];
__device__ __half g_wl[(size_t)4 * DM * DM];
__device__ __half g_qh[(size_t)MTOT * DM];
__device__ __half g_ql[(size_t)MTOT * DM];
__device__ __half g_kh[(size_t)MTOT * DM];
__device__ __half g_kl[(size_t)MTOT * DM];
__device__ __half g_vh[(size_t)MTOT * DM];
__device__ __half g_vl[(size_t)MTOT * DM];
__device__ float g_o[(size_t)MTOT * DM];

// ---------------- helpers ----------------
__device__ __forceinline__ uint32_t s2u(const void* p) {
    uint32_t a;
    asm("{ .reg .u64 t; cvta.to.shared.u64 t, %1; cvt.u32.u64 %0, t; }" : "=r"(a) : "l"(p));
    return a;
}

// RoPE rotation; Cody-Waite 2*pi reduction (robust under fast-math).
__device__ __forceinline__ void rope_rot(float p, float d_e, float& e, float& o) {
    const float LOG2_THETA_DIV = 13.287712379549449f / 64.0f;
    float freq = exp2f(-d_e * LOG2_THETA_DIV);
    float ang = p * freq;
    float n = rintf(ang * 0.15915494309189535f);
    float r = fmaf(-n, 6.28125f, ang);
    r = fmaf(-n, 1.9353071795864774e-3f, r);
    float s, c;
    sincosf(r, &s, &c);
    float ne = e * c - o * s;
    float no = e * s + o * c;
    e = ne; o = no;
}

// Fast exp for x <= 0 on the FMA/ALU pipes (no MUFU). ~1e-6 rel err.
__device__ __forceinline__ float fexp(float x) {
    float t = fmaxf(x * 1.4426950408889634f, -126.0f);
    float z = t + 12582912.0f;
    int ii = __float_as_int(z);
    float f = t - (z - 12582912.0f);
    float p = 1.3333558e-3f;
    p = fmaf(p, f, 9.6181291e-3f);
    p = fmaf(p, f, 5.5504109e-2f);
    p = fmaf(p, f, 2.4022651e-1f);
    p = fmaf(p, f, 6.9314718e-1f);
    p = fmaf(p, f, 1.0f);
    return __int_as_float((ii << 23) + 0x3F800000) * p;
}

// split fp32 pair -> packed fp16 hi + fp16 lo
__device__ __forceinline__ void pack_split(float a, float b, uint32_t& hp, uint32_t& lp) {
    __half2 H = __floats2half2_rn(a, b);
    hp = *(uint32_t*)&H;
    float2 hf = __half22float2(H);
    __half2 L = __floats2half2_rn(a - hf.x, b - hf.y);
    lp = *(uint32_t*)&L;
}

__device__ __forceinline__ void unpack_add(uint32_t u, float& a, float& b) {
    float2 f = __half22float2(*(__half2*)&u);
    a += f.x; b += f.y;
}

#define LDSM4(r0, r1, r2, r3, addr) \
    asm volatile("ldmatrix.sync.aligned.m8n8.x4.shared.b16 {%0,%1,%2,%3}, [%4];" \
        : "=r"(r0), "=r"(r1), "=r"(r2), "=r"(r3) : "r"(addr))

#define LDSM4T(r0, r1, r2, r3, addr) \
    asm volatile("ldmatrix.sync.aligned.m8n8.x4.trans.shared.b16 {%0,%1,%2,%3}, [%4];" \
        : "=r"(r0), "=r"(r1), "=r"(r2), "=r"(r3) : "r"(addr))

// fp16 inputs, fp32 accumulators (main hi*hi pass)
#define MMA16816(c, a, b) \
    asm volatile("mma.sync.aligned.m16n8k16.row.col.f32.f16.f16.f32 " \
        "{%0,%1,%2,%3}, {%4,%5,%6,%7}, {%8,%9}, {%0,%1,%2,%3};" \
        : "+f"((c)[0]), "+f"((c)[1]), "+f"((c)[2]), "+f"((c)[3]) \
        : "r"((a)[0]), "r"((a)[1]), "r"((a)[2]), "r"((a)[3]), "r"((b)[0]), "r"((b)[1]))

// fp16 inputs, fp16 accumulators (2x rate; cross passes)
#define MMA16816H(c, a, b) \
    asm volatile("mma.sync.aligned.m16n8k16.row.col.f16.f16.f16.f16 " \
        "{%0,%1}, {%2,%3,%4,%5}, {%6,%7}, {%0,%1};" \
        : "+r"((c)[0]), "+r"((c)[1]) \
        : "r"((a)[0]), "r"((a)[1]), "r"((a)[2]), "r"((a)[3]), "r"((b)[0]), "r"((b)[1]))

#define CPA16(dst, src) \
    asm volatile("cp.async.cg.shared.global [%0], [%1], 16;" :: "r"(dst), "l"(src))
#define CPCOMMIT() asm volatile("cp.async.commit_group;" ::: "memory")
#define CPWAIT(n)  asm volatile("cp.async.wait_group %0;" :: "n"(n) : "memory")

// ---------------- split kernel: fp32 -> (fp16 hi, fp16 lo) ----------------
__global__ __launch_bounds__(256) void split_kernel(
    const float* __restrict__ in, __half* __restrict__ hi,
    __half* __restrict__ lo, int n4)
{
    int i = blockIdx.x * 256 + threadIdx.x;
    if (i >= n4) return;
    float4 x = ((const float4*)in)[i];
    uint32_t h01, l01, h23, l23;
    pack_split(x.x, x.y, h01, l01);
    pack_split(x.z, x.w, h23, l23);
    ((uint2*)hi)[i] = make_uint2(h01, h23);
    ((uint2*)lo)[i] = make_uint2(l01, l23);
}

// ---------------- fp16 split GEMM via mma.sync, cp.async 4-stage ----------------
#define SROWB 80
#define ARR_B (128 * SROWB)
#define STAGE_B (4 * ARR_B)
#define NSTAGE 4
#define GSMEM (NSTAGE * STAGE_B)

__global__ __launch_bounds__(256) void gemm_f16(
    const __half* __restrict__ Ah, const __half* __restrict__ Al,
    const __half* __restrict__ Bh, const __half* __restrict__ Bl,
    const int* __restrict__ pos, float* __restrict__ outf,
    __half* __restrict__ outh, __half* __restrict__ outl,
    int mode, float scale)
{
    extern __shared__ char smem[];
    const uint32_t sb32 = s2u(smem);
    int tid = threadIdx.x, lane = tid & 31, wid = tid >> 5;
    int m0 = blockIdx.y << 7, n0 = blockIdx.x << 7;
    int wm = (wid >> 2) << 6;
    int wn = (wid & 3) << 5;

    int frow = tid >> 1;
    int fh = tid & 1;
    const uint4* gAh = (const uint4*)(Ah + (size_t)(m0 + frow) * DM);
    const uint4* gAl = (const uint4*)(Al + (size_t)(m0 + frow) * DM);
    const uint4* gBh = (const uint4*)(Bh + (size_t)(n0 + frow) * DM);
    const uint4* gBl = (const uint4*)(Bl + (size_t)(n0 + frow) * DM);
    uint32_t sfill = sb32 + (uint32_t)(frow * SROWB + fh * 32);

    #define GISSUE(s_) { \
        int bi = (s_) * 4 + (fh << 1); \
        uint32_t d0 = sfill + ((s_) & (NSTAGE - 1)) * STAGE_B; \
        CPA16(d0 + 0 * ARR_B,      gAh + bi); \
        CPA16(d0 + 0 * ARR_B + 16, gAh + bi + 1); \
        CPA16(d0 + 1 * ARR_B,      gAl + bi); \
        CPA16(d0 + 1 * ARR_B + 16, gAl + bi + 1); \
        CPA16(d0 + 2 * ARR_B,      gBh + bi); \
        CPA16(d0 + 2 * ARR_B + 16, gBh + bi + 1); \
        CPA16(d0 + 3 * ARR_B,      gBl + bi); \
        CPA16(d0 + 3 * ARR_B + 16, gBl + bi + 1); }

    float c[4][4][4] = {};
    uint32_t cx[4][4][2] = {};   // f16 accum for both cross passes

    GISSUE(0); CPCOMMIT();
    GISSUE(1); CPCOMMIT();
    GISSUE(2); CPCOMMIT();

    for (int s = 0; s < 32; s++) {
        CPWAIT(2);
        __syncthreads();
        if (s + 3 < 32) GISSUE(s + 3);
        CPCOMMIT();

        uint32_t base = sb32 + (uint32_t)(s & (NSTAGE - 1)) * STAGE_B;
        uint32_t aRow = base + (uint32_t)(wm + (lane & 15)) * SROWB + ((lane >> 4) << 4);
        int q = lane >> 3;
        uint32_t bRow = base + 2 * ARR_B +
                        (uint32_t)(wn + ((q >> 1) << 3) + (lane & 7)) * SROWB +
                        ((q & 1) << 4);

        #pragma unroll
        for (int step = 0; step < 2; step++) {
            uint32_t ko = step * 32;
            uint32_t ah[4][4], al[4][4], bh[4][2], bl[4][2];
            #pragma unroll
            for (int mt = 0; mt < 4; mt++) {
                uint32_t aAddr = aRow + (uint32_t)(mt * 16) * SROWB + ko;
                LDSM4(ah[mt][0], ah[mt][1], ah[mt][2], ah[mt][3], aAddr);
                LDSM4(al[mt][0], al[mt][1], al[mt][2], al[mt][3], aAddr + ARR_B);
            }
            #pragma unroll
            for (int pn = 0; pn < 2; pn++) {
                uint32_t bAddr = bRow + (uint32_t)(pn * 16) * SROWB + ko;
                LDSM4(bh[2*pn][0], bh[2*pn][1], bh[2*pn+1][0], bh[2*pn+1][1], bAddr);
                LDSM4(bl[2*pn][0], bl[2*pn][1], bl[2*pn+1][0], bl[2*pn+1][1], bAddr + ARR_B);
            }
            #pragma unroll
            for (int mt = 0; mt < 4; mt++)
                #pragma unroll
                for (int nt = 0; nt < 4; nt++) {
                    MMA16816(c[mt][nt], ah[mt], bh[nt]);
                    MMA16816H(cx[mt][nt], ah[mt], bl[nt]);
                    MMA16816H(cx[mt][nt], al[mt], bh[nt]);
                }
        }
    }

    // ---------------- epilogue ----------------
    int gid = lane >> 2, tig = lane & 3;
    #pragma unroll
    for (int mt = 0; mt < 4; mt++) {
        int m_a = m0 + wm + mt * 16 + gid;
        int m_b = m_a + 8;
        float p_a = 0.f, p_b = 0.f;
        if (mode == 1 || mode == 2) { p_a = (float)pos[m_a]; p_b = (float)pos[m_b]; }
        #pragma unroll
        for (int nt = 0; nt < 4; nt++) {
            int n = n0 + wn + nt * 8 + tig * 2;
            float v0 = c[mt][nt][0], v1 = c[mt][nt][1];
            float v2 = c[mt][nt][2], v3 = c[mt][nt][3];
            unpack_add(cx[mt][nt][0], v0, v1);
            unpack_add(cx[mt][nt][1], v2, v3);
            if (mode == 0) {
                *(float2*)(outf + (size_t)m_a * DM + n) = make_float2(v0, v1);
                *(float2*)(outf + (size_t)m_b * DM + n) = make_float2(v2, v3);
            } else {
                int h = n >> 6, d = n & 63;
                if (mode != 3) {
                    rope_rot(p_a, (float)d, v0, v1);
                    rope_rot(p_b, (float)d, v2, v3);
                }
                v0 *= scale; v1 *= scale; v2 *= scale; v3 *= scale;
                int ba = m_a >> 12, sa = m_a & (SEQ - 1);
                int bb = m_b >> 12, sbq = m_b & (SEQ - 1);
                size_t ia = ((size_t)(ba * NH + h) * SEQ + sa) * DK + d;
                size_t ib = ((size_t)(bb * NH + h) * SEQ + sbq) * DK + d;
                uint32_t hp, lp;
                pack_split(v0, v1, hp, lp);
                *(uint32_t*)(outh + ia) = hp; *(uint32_t*)(outl + ia) = lp;
                pack_split(v2, v3, hp, lp);
                *(uint32_t*)(outh + ib) = hp; *(uint32_t*)(outl + ib) = lp;
            }
        }
    }
}

// ---------------- fp16 split HMMA flash attention, cp.async 2-stage ----------------
#define AROW 144
#define ASTG 36864
#define ASMEM (2 * ASTG)

__global__ __launch_bounds__(256) void attn_mma(
    const __half* __restrict__ Qh, const __half* __restrict__ Ql,
    const __half* __restrict__ Kh, const __half* __restrict__ Kl,
    const __half* __restrict__ Vh, const __half* __restrict__ Vl,
    float* __restrict__ O)
{
    extern __shared__ char sm[];
    uint32_t sb = s2u(sm);
    int tid = threadIdx.x, lane = tid & 31, w = tid >> 5;
    int qt = blockIdx.x, hh = blockIdx.y, bb = blockIdx.z;
    int q0 = qt << 7;
    size_t base = (size_t)(bb * NH + hh) * SEQ * DK;
    int gid = lane >> 2, tig = lane & 3;

    // ---- Q tile -> smem (buf0) -> register fragments ----
    {
        int row = tid >> 1, hf = tid & 1;
        const uint4* gqh = (const uint4*)(Qh + base + (size_t)(q0 + row) * DK);
        const uint4* gql = (const uint4*)(Ql + base + (size_t)(q0 + row) * DK);
        char* s0 = sm + row * AROW + hf * 64;
        #pragma unroll
        for (int j = 0; j < 4; j++) {
            *(uint4*)(s0 + j * 16)         = gqh[hf * 4 + j];
            *(uint4*)(s0 + 18432 + j * 16) = gql[hf * 4 + j];
        }
    }
    __syncthreads();
    uint32_t qfh[4][4], qfl[4][4];
    {
        uint32_t aAddr = sb + (uint32_t)((16 * w + (lane & 15)) * AROW + ((lane >> 4) << 4));
        #pragma unroll
        for (int ds = 0; ds < 4; ds++) {
            LDSM4(qfh[ds][0], qfh[ds][1], qfh[ds][2], qfh[ds][3], aAddr + ds * 32);
            LDSM4(qfl[ds][0], qfl[ds][1], qfl[ds][2], qfl[ds][3], aAddr + 18432 + ds * 32);
        }
    }
    __syncthreads();

    int frow0 = tid >> 3, fcol = tid & 7;
    uint32_t fdst = sb + (uint32_t)(frow0 * AROW + fcol * 16);

    #define AISSUE(kt_, buf_) { \
        size_t g0 = base + (size_t)(((kt_) << 6) + frow0) * DK + fcol * 8; \
        size_t g1 = g0 + 32 * DK; \
        uint32_t d0 = fdst + (buf_) * (uint32_t)ASTG; \
        uint32_t d1 = d0 + 32 * AROW; \
        CPA16(d0,         Kh + g0); CPA16(d1,         Kh + g1); \
        CPA16(d0 +  9216, Kl + g0); CPA16(d1 +  9216, Kl + g1); \
        CPA16(d0 + 18432, Vh + g0); CPA16(d1 + 18432, Vh + g1); \
        CPA16(d0 + 27648, Vl + g0); CPA16(d1 + 27648, Vl + g1); }

    float o_[8][4] = {};
    float m0 = -1e30f, m1 = -1e30f, l0 = 0.f, l1 = 0.f;
    int q0w = q0 + 16 * w;
    int qg = lane >> 3;
    uint32_t kOff = (uint32_t)(((((qg >> 1) << 3) | (lane & 7)) * AROW) + ((qg & 1) << 4));
    uint32_t vOff = (uint32_t)(((((qg & 1) << 3) | (lane & 7)) * AROW) + ((qg >> 1) << 4));

    int niter = 2 * qt + 2;
    AISSUE(0, 0); CPCOMMIT();

    for (int kt = 0; kt < niter; kt++) {
        int k0 = kt << 6;
        int buf = kt & 1;
        CPWAIT(0);
        __syncthreads();
        if (kt + 1 < niter) { AISSUE(kt + 1, buf ^ 1); CPCOMMIT(); }

        uint32_t sK = sb + (uint32_t)buf * ASTG;

        // S = Q K^T  (hh in f32, cross pair in f16 accum)
        float s_[8][4] = {};
        uint32_t sx[8][2] = {};
        #pragma unroll
        for (int ds = 0; ds < 4; ds++) {
            uint32_t bh[8][2], bl[8][2];
            #pragma unroll
            for (int p = 0; p < 4; p++) {
                uint32_t ba_ = sK + kOff + (uint32_t)(p * 16 * AROW) + ds * 32;
                LDSM4(bh[2*p][0], bh[2*p][1], bh[2*p+1][0], bh[2*p+1][1], ba_);
                LDSM4(bl[2*p][0], bl[2*p][1], bl[2*p+1][0], bl[2*p+1][1], ba_ + 9216);
            }
            #pragma unroll
            for (int j = 0; j < 8; j++) {
                MMA16816(s_[j], qfh[ds], bh[j]);
                MMA16816H(sx[j], qfh[ds], bl[j]);
                MMA16816H(sx[j], qfl[ds], bh[j]);
            }
        }
        #pragma unroll
        for (int j = 0; j < 8; j++) {
            unpack_add(sx[j][0], s_[j][0], s_[j][1]);
            unpack_add(sx[j][1], s_[j][2], s_[j][3]);
        }

        // causal mask
        if (k0 + 63 > q0w) {
            int r0 = q0w + gid, r1 = r0 + 8;
            #pragma unroll
            for (int j = 0; j < 8; j++) {
                int cb = k0 + 8 * j + 2 * tig;
                if (cb     > r0) s_[j][0] = -1e30f;
                if (cb + 1 > r0) s_[j][1] = -1e30f;
                if (cb     > r1) s_[j][2] = -1e30f;
                if (cb + 1 > r1) s_[j][3] = -1e30f;
            }
        }

        // online softmax (poly exp)
        float mx0 = s_[0][0], mx1 = s_[0][2];
        #pragma unroll
        for (int j = 0; j < 8; j++) {
            mx0 = fmaxf(mx0, fmaxf(s_[j][0], s_[j][1]));
            mx1 = fmaxf(mx1, fmaxf(s_[j][2], s_[j][3]));
        }
        mx0 = fmaxf(mx0, __shfl_xor_sync(0xffffffffu, mx0, 1));
        mx0 = fmaxf(mx0, __shfl_xor_sync(0xffffffffu, mx0, 2));
        mx1 = fmaxf(mx1, __shfl_xor_sync(0xffffffffu, mx1, 1));
        mx1 = fmaxf(mx1, __shfl_xor_sync(0xffffffffu, mx1, 2));
        float mn0 = fmaxf(m0, mx0), mn1 = fmaxf(m1, mx1);
        float c0 = fexp(m0 - mn0), c1 = fexp(m1 - mn1);
        m0 = mn0; m1 = mn1;
        float rs0 = 0.f, rs1 = 0.f;
        #pragma unroll
        for (int j = 0; j < 8; j++) {
            s_[j][0] = fexp(s_[j][0] - mn0);
            s_[j][1] = fexp(s_[j][1] - mn0);
            s_[j][2] = fexp(s_[j][2] - mn1);
            s_[j][3] = fexp(s_[j][3] - mn1);
            rs0 += s_[j][0] + s_[j][1];
            rs1 += s_[j][2] + s_[j][3];
        }
        rs0 += __shfl_xor_sync(0xffffffffu, rs0, 1);
        rs0 += __shfl_xor_sync(0xffffffffu, rs0, 2);
        rs1 += __shfl_xor_sync(0xffffffffu, rs1, 1);
        rs1 += __shfl_xor_sync(0xffffffffu, rs1, 2);
        l0 = l0 * c0 + rs0; l1 = l1 * c1 + rs1;
        #pragma unroll
        for (int j = 0; j < 8; j++) {
            o_[j][0] *= c0; o_[j][1] *= c0; o_[j][2] *= c1; o_[j][3] *= c1;
        }

        // P -> A-frags in registers, fp16 split
        uint32_t pfh[4][4], pfl[4][4];
        #pragma unroll
        for (int ks = 0; ks < 4; ks++) {
            int j0 = 2 * ks, j1 = 2 * ks + 1;
            pack_split(s_[j0][0], s_[j0][1], pfh[ks][0], pfl[ks][0]);
            pack_split(s_[j0][2], s_[j0][3], pfh[ks][1], pfl[ks][1]);
            pack_split(s_[j1][0], s_[j1][1], pfh[ks][2], pfl[ks][2]);
            pack_split(s_[j1][2], s_[j1][3], pfh[ks][3], pfl[ks][3]);
        }

        // O += P V  (hh in f32, cross pair in f16; folded per-iter)
        uint32_t ox[8][2] = {};
        #pragma unroll
        for (int ks = 0; ks < 4; ks++) {
            uint32_t vh[8][2], vl[8][2];
            #pragma unroll
            for (int p = 0; p < 4; p++) {
                uint32_t ba_ = sK + 18432 + vOff + (uint32_t)(ks * 16 * AROW) + p * 32;
                LDSM4T(vh[2*p][0], vh[2*p][1], vh[2*p+1][0], vh[2*p+1][1], ba_);
                LDSM4T(vl[2*p][0], vl[2*p][1], vl[2*p+1][0], vl[2*p+1][1], ba_ + 9216);
            }
            #pragma unroll
            for (int j = 0; j < 8; j++) {
                MMA16816(o_[j], pfh[ks], vh[j]);
                MMA16816H(ox[j], pfh[ks], vl[j]);
                MMA16816H(ox[j], pfl[ks], vh[j]);
            }
        }
        #pragma unroll
        for (int j = 0; j < 8; j++) {
            unpack_add(ox[j][0], o_[j][0], o_[j][1]);
            unpack_add(ox[j][1], o_[j][2], o_[j][3]);
        }
    }

    // finalize
    float inv0 = 1.0f / l0, inv1 = 1.0f / l1;
    int r0 = q0 + 16 * w + gid, r1 = r0 + 8;
    float* O0 = O + ((size_t)bb * SEQ + r0) * DM + hh * DK + 2 * tig;
    float* O1 = O + ((size_t)bb * SEQ + r1) * DM + hh * DK + 2 * tig;
    #pragma unroll
    for (int j = 0; j < 8; j++) {
        *(float2*)(O0 + 8 * j) = make_float2(o_[j][0] * inv0, o_[j][1] * inv0);
        *(float2*)(O1 + 8 * j) = make_float2(o_[j][2] * inv1, o_[j][3] * inv1);
    }
}

// ---------------- launch ----------------
extern "C" void kernel_launch(void* const* d_in, const int* in_sizes, int n_in,
                              void* d_out, int out_size) {
    (void)in_sizes; (void)n_in; (void)out_size;
    const float* x   = (const float*)d_in[0];
    const int*   pos = (const int*)d_in[1];
    const float* Wq  = (const float*)d_in[2];
    const float* Wk  = (const float*)d_in[3];
    const float* Wv  = (const float*)d_in[4];
    const float* Wo  = (const float*)d_in[5];
    float* out = (float*)d_out;

    __half *xh, *xl, *wh, *wl, *qh, *ql, *kh, *kl, *vh, *vl;
    float* o;
    cudaGetSymbolAddress((void**)&xh, g_xh);
    cudaGetSymbolAddress((void**)&xl, g_xl);
    cudaGetSymbolAddress((void**)&wh, g_wh);
    cudaGetSymbolAddress((void**)&wl, g_wl);
    cudaGetSymbolAddress((void**)&qh, g_qh);
    cudaGetSymbolAddress((void**)&ql, g_ql);
    cudaGetSymbolAddress((void**)&kh, g_kh);
    cudaGetSymbolAddress((void**)&kl, g_kl);
    cudaGetSymbolAddress((void**)&vh, g_vh);
    cudaGetSymbolAddress((void**)&vl, g_vl);
    cudaGetSymbolAddress((void**)&o, g_o);

    cudaFuncSetAttribute(gemm_f16, cudaFuncAttributeMaxDynamicSharedMemorySize, GSMEM);
    cudaFuncSetAttribute(attn_mma, cudaFuncAttributeMaxDynamicSharedMemorySize, ASMEM);

    const int n4x = MTOT * DM / 4;
    const int n4w = DM * DM / 4;
    const size_t WS = (size_t)DM * DM;

    split_kernel<<<n4x / 256, 256>>>(x, xh, xl, n4x);
    split_kernel<<<n4w / 256, 256>>>(Wq, wh + 0 * WS, wl + 0 * WS, n4w);
    split_kernel<<<n4w / 256, 256>>>(Wk, wh + 1 * WS, wl + 1 * WS, n4w);
    split_kernel<<<n4w / 256, 256>>>(Wv, wh + 2 * WS, wl + 2 * WS, n4w);
    split_kernel<<<n4w / 256, 256>>>(Wo, wh + 3 * WS, wl + 3 * WS, n4w);

    dim3 ggrid(DM / 128, MTOT / 128);
    gemm_f16<<<ggrid, 256, GSMEM>>>(xh, xl, wh + 0 * WS, wl + 0 * WS, pos,
                                    nullptr, qh, ql, 1, 0.125f);
    gemm_f16<<<ggrid, 256, GSMEM>>>(xh, xl, wh + 1 * WS, wl + 1 * WS, pos,
                                    nullptr, kh, kl, 2, 1.0f);
    gemm_f16<<<ggrid, 256, GSMEM>>>(xh, xl, wh + 2 * WS, wl + 2 * WS, pos,
                                    nullptr, vh, vl, 3, 1.0f);

    dim3 agrid(SEQ / 128, NH, BATCHN);
    attn_mma<<<agrid, 256, ASMEM>>>(qh, ql, kh, kl, vh, vl, o);

    split_kernel<<<n4x / 256, 256>>>(o, xh, xl, n4x);
    gemm_f16<<<ggrid, 256, GSMEM>>>(xh, xl, wh + 3 * WS, wl + 3 * WS, pos,
                                    out, nullptr, nullptr, 0, 1.0f);
}

// round 10
// speedup vs baseline: 3.4957x; 1.3989x over previous
#include <cuda_runtime.h>
#include <cuda_fp16.h>
#include <math.h>
#include <stdint.h>

#define SEQ 4096
#define DM 1024
#define NH 16
#define DK 64
#define BATCHN 2
#define MTOT (BATCHN*SEQ)

// ---------------- scratch (allocation-free) ----------------
__device__ __half g_xh[(size_t)MTOT * DM];
__device__ __half g_xl[(size_t)MTOT * DM];
__device__ __half g_w[(size_t)4 * DM * DM];
__device__ __half g_qh[(size_t)MTOT * DM];
__device__ __half g_ql[(size_t)MTOT * DM];
__device__ __half g_kh[(size_t)MTOT * DM];
__device__ __half g_vh[(size_t)MTOT * DM];
__device__ float g_o[(size_t)MTOT * DM];

// ---------------- helpers ----------------
__device__ __forceinline__ uint32_t s2u(const void* p) {
    uint32_t a;
    asm("{ .reg .u64 t; cvta.to.shared.u64 t, %1; cvt.u32.u64 %0, t; }" : "=r"(a) : "l"(p));
    return a;
}

// RoPE rotation; Cody-Waite 2*pi reduction (robust under fast-math).
__device__ __forceinline__ void rope_rot(float p, float d_e, float& e, float& o) {
    const float LOG2_THETA_DIV = 13.287712379549449f / 64.0f;
    float freq = exp2f(-d_e * LOG2_THETA_DIV);
    float ang = p * freq;
    float n = rintf(ang * 0.15915494309189535f);
    float r = fmaf(-n, 6.28125f, ang);
    r = fmaf(-n, 1.9353071795864774e-3f, r);
    float s, c;
    sincosf(r, &s, &c);
    float ne = e * c - o * s;
    float no = e * s + o * c;
    e = ne; o = no;
}

// Fast exp for x <= 0 on the FMA/ALU pipes (no MUFU). ~1e-6 rel err.
__device__ __forceinline__ float fexp(float x) {
    float t = fmaxf(x * 1.4426950408889634f, -126.0f);
    float z = t + 12582912.0f;
    int ii = __float_as_int(z);
    float f = t - (z - 12582912.0f);
    float p = 1.3333558e-3f;
    p = fmaf(p, f, 9.6181291e-3f);
    p = fmaf(p, f, 5.5504109e-2f);
    p = fmaf(p, f, 2.4022651e-1f);
    p = fmaf(p, f, 6.9314718e-1f);
    p = fmaf(p, f, 1.0f);
    return __int_as_float((ii << 23) + 0x3F800000) * p;
}

// split fp32 pair -> packed fp16 hi + fp16 lo
__device__ __forceinline__ void pack_split(float a, float b, uint32_t& hp, uint32_t& lp) {
    __half2 H = __floats2half2_rn(a, b);
    hp = *(uint32_t*)&H;
    float2 hf = __half22float2(H);
    __half2 L = __floats2half2_rn(a - hf.x, b - hf.y);
    lp = *(uint32_t*)&L;
}

__device__ __forceinline__ uint32_t pack_h(float a, float b) {
    __half2 H = __floats2half2_rn(a, b);
    return *(uint32_t*)&H;
}

#define LDSM4(r0, r1, r2, r3, addr) \
    asm volatile("ldmatrix.sync.aligned.m8n8.x4.shared.b16 {%0,%1,%2,%3}, [%4];" \
        : "=r"(r0), "=r"(r1), "=r"(r2), "=r"(r3) : "r"(addr))

#define LDSM4T(r0, r1, r2, r3, addr) \
    asm volatile("ldmatrix.sync.aligned.m8n8.x4.trans.shared.b16 {%0,%1,%2,%3}, [%4];" \
        : "=r"(r0), "=r"(r1), "=r"(r2), "=r"(r3) : "r"(addr))

#define MMA16816(c, a, b) \
    asm volatile("mma.sync.aligned.m16n8k16.row.col.f32.f16.f16.f32 " \
        "{%0,%1,%2,%3}, {%4,%5,%6,%7}, {%8,%9}, {%0,%1,%2,%3};" \
        : "+f"((c)[0]), "+f"((c)[1]), "+f"((c)[2]), "+f"((c)[3]) \
        : "r"((a)[0]), "r"((a)[1]), "r"((a)[2]), "r"((a)[3]), "r"((b)[0]), "r"((b)[1]))

#define CPA16(dst, src) \
    asm volatile("cp.async.cg.shared.global [%0], [%1], 16;" :: "r"(dst), "l"(src))
#define CPCOMMIT() asm volatile("cp.async.commit_group;" ::: "memory")
#define CPWAIT(n)  asm volatile("cp.async.wait_group %0;" :: "n"(n) : "memory")

// ---------------- split kernel: fp32 -> (fp16 hi, fp16 lo) ----------------
__global__ __launch_bounds__(256) void split_kernel(
    const float* __restrict__ in, __half* __restrict__ hi,
    __half* __restrict__ lo, int n4)
{
    int i = blockIdx.x * 256 + threadIdx.x;
    if (i >= n4) return;
    float4 x = ((const float4*)in)[i];
    uint32_t h01, l01, h23, l23;
    pack_split(x.x, x.y, h01, l01);
    pack_split(x.z, x.w, h23, l23);
    ((uint2*)hi)[i] = make_uint2(h01, h23);
    ((uint2*)lo)[i] = make_uint2(l01, l23);
}

// ---------------- convert kernel: fp32 -> fp16 (hi only, for B operands) ----------------
__global__ __launch_bounds__(256) void conv_kernel(
    const float* __restrict__ in, __half* __restrict__ hi, int n4)
{
    int i = blockIdx.x * 256 + threadIdx.x;
    if (i >= n4) return;
    float4 x = ((const float4*)in)[i];
    ((uint2*)hi)[i] = make_uint2(pack_h(x.x, x.y), pack_h(x.z, x.w));
}

// ---------------- fp16 2-pass GEMM via mma.sync, cp.async 4-stage ----------------
// C = (Ah + Al) * Bh.  A split fp16 hi/lo, B plain fp16.
#define SROWB 80
#define ARR_B (128 * SROWB)
#define STAGE_B (3 * ARR_B)      // 30720
#define NSTAGE 4
#define GSMEM (NSTAGE * STAGE_B) // 122880

__global__ __launch_bounds__(256) void gemm_f16(
    const __half* __restrict__ Ah, const __half* __restrict__ Al,
    const __half* __restrict__ Bh,
    const int* __restrict__ pos, float* __restrict__ outf,
    __half* __restrict__ outh, __half* __restrict__ outl,
    int mode, float scale)
{
    extern __shared__ char smem[];
    const uint32_t sb32 = s2u(smem);
    int tid = threadIdx.x, lane = tid & 31, wid = tid >> 5;
    int m0 = blockIdx.y << 7, n0 = blockIdx.x << 7;
    int wm = (wid >> 2) << 6;
    int wn = (wid & 3) << 5;

    int frow = tid >> 1;
    int fh = tid & 1;
    const uint4* gAh = (const uint4*)(Ah + (size_t)(m0 + frow) * DM);
    const uint4* gAl = (const uint4*)(Al + (size_t)(m0 + frow) * DM);
    const uint4* gBh = (const uint4*)(Bh + (size_t)(n0 + frow) * DM);
    uint32_t sfill = sb32 + (uint32_t)(frow * SROWB + fh * 32);

    #define GISSUE(s_) { \
        int bi = (s_) * 4 + (fh << 1); \
        uint32_t d0 = sfill + ((s_) & (NSTAGE - 1)) * STAGE_B; \
        CPA16(d0 + 0 * ARR_B,      gAh + bi); \
        CPA16(d0 + 0 * ARR_B + 16, gAh + bi + 1); \
        CPA16(d0 + 1 * ARR_B,      gAl + bi); \
        CPA16(d0 + 1 * ARR_B + 16, gAl + bi + 1); \
        CPA16(d0 + 2 * ARR_B,      gBh + bi); \
        CPA16(d0 + 2 * ARR_B + 16, gBh + bi + 1); }

    float c[4][4][4] = {};

    GISSUE(0); CPCOMMIT();
    GISSUE(1); CPCOMMIT();
    GISSUE(2); CPCOMMIT();

    for (int s = 0; s < 32; s++) {
        CPWAIT(2);
        __syncthreads();
        if (s + 3 < 32) GISSUE(s + 3);
        CPCOMMIT();

        uint32_t base = sb32 + (uint32_t)(s & (NSTAGE - 1)) * STAGE_B;
        uint32_t aRow = base + (uint32_t)(wm + (lane & 15)) * SROWB + ((lane >> 4) << 4);
        int q = lane >> 3;
        uint32_t bRow = base + 2 * ARR_B +
                        (uint32_t)(wn + ((q >> 1) << 3) + (lane & 7)) * SROWB +
                        ((q & 1) << 4);

        #pragma unroll
        for (int step = 0; step < 2; step++) {
            uint32_t ko = step * 32;
            uint32_t ah[4][4], al[4][4], bh[4][2];
            #pragma unroll
            for (int mt = 0; mt < 4; mt++) {
                uint32_t aAddr = aRow + (uint32_t)(mt * 16) * SROWB + ko;
                LDSM4(ah[mt][0], ah[mt][1], ah[mt][2], ah[mt][3], aAddr);
                LDSM4(al[mt][0], al[mt][1], al[mt][2], al[mt][3], aAddr + ARR_B);
            }
            #pragma unroll
            for (int pn = 0; pn < 2; pn++) {
                uint32_t bAddr = bRow + (uint32_t)(pn * 16) * SROWB + ko;
                LDSM4(bh[2*pn][0], bh[2*pn][1], bh[2*pn+1][0], bh[2*pn+1][1], bAddr);
            }
            #pragma unroll
            for (int mt = 0; mt < 4; mt++)
                #pragma unroll
                for (int nt = 0; nt < 4; nt++) {
                    MMA16816(c[mt][nt], ah[mt], bh[nt]);
                    MMA16816(c[mt][nt], al[mt], bh[nt]);
                }
        }
    }

    // ---------------- epilogue ----------------
    int gid = lane >> 2, tig = lane & 3;
    #pragma unroll
    for (int mt = 0; mt < 4; mt++) {
        int m_a = m0 + wm + mt * 16 + gid;
        int m_b = m_a + 8;
        float p_a = 0.f, p_b = 0.f;
        if (mode == 1 || mode == 2) { p_a = (float)pos[m_a]; p_b = (float)pos[m_b]; }
        #pragma unroll
        for (int nt = 0; nt < 4; nt++) {
            int n = n0 + wn + nt * 8 + tig * 2;
            float v0 = c[mt][nt][0], v1 = c[mt][nt][1];
            float v2 = c[mt][nt][2], v3 = c[mt][nt][3];
            if (mode == 0) {
                *(float2*)(outf + (size_t)m_a * DM + n) = make_float2(v0, v1);
                *(float2*)(outf + (size_t)m_b * DM + n) = make_float2(v2, v3);
            } else {
                int h = n >> 6, d = n & 63;
                if (mode != 3) {
                    rope_rot(p_a, (float)d, v0, v1);
                    rope_rot(p_b, (float)d, v2, v3);
                }
                v0 *= scale; v1 *= scale; v2 *= scale; v3 *= scale;
                int ba = m_a >> 12, sa = m_a & (SEQ - 1);
                int bb = m_b >> 12, sbq = m_b & (SEQ - 1);
                size_t ia = ((size_t)(ba * NH + h) * SEQ + sa) * DK + d;
                size_t ib = ((size_t)(bb * NH + h) * SEQ + sbq) * DK + d;
                if (mode == 1) {  // Q: split hi/lo
                    uint32_t hp, lp;
                    pack_split(v0, v1, hp, lp);
                    *(uint32_t*)(outh + ia) = hp; *(uint32_t*)(outl + ia) = lp;
                    pack_split(v2, v3, hp, lp);
                    *(uint32_t*)(outh + ib) = hp; *(uint32_t*)(outl + ib) = lp;
                } else {          // K/V: hi only
                    *(uint32_t*)(outh + ia) = pack_h(v0, v1);
                    *(uint32_t*)(outh + ib) = pack_h(v2, v3);
                }
            }
        }
    }
}

// ---------------- 2-pass HMMA flash attention, cp.async 2-stage ----------------
// smem stage: Kh @ 0 (64x144), Vh @ 9216 (64x144) = 18432 per stage, 2 stages.
#define AROW 144
#define ASTG 18432
#define ASMEM (2 * ASTG)

__global__ __launch_bounds__(256) void attn_mma(
    const __half* __restrict__ Qh, const __half* __restrict__ Ql,
    const __half* __restrict__ Kh, const __half* __restrict__ Vh,
    float* __restrict__ O)
{
    extern __shared__ char sm[];
    uint32_t sb = s2u(sm);
    int tid = threadIdx.x, lane = tid & 31, w = tid >> 5;
    int qt = blockIdx.x, hh = blockIdx.y, bb = blockIdx.z;
    int q0 = qt << 7;
    size_t base = (size_t)(bb * NH + hh) * SEQ * DK;
    int gid = lane >> 2, tig = lane & 3;

    // ---- Q tile -> smem (hi @0, lo @18432) -> register fragments ----
    {
        int row = tid >> 1, hf = tid & 1;
        const uint4* gqh = (const uint4*)(Qh + base + (size_t)(q0 + row) * DK);
        const uint4* gql = (const uint4*)(Ql + base + (size_t)(q0 + row) * DK);
        char* s0 = sm + row * AROW + hf * 64;
        #pragma unroll
        for (int j = 0; j < 4; j++) {
            *(uint4*)(s0 + j * 16)         = gqh[hf * 4 + j];
            *(uint4*)(s0 + 18432 + j * 16) = gql[hf * 4 + j];
        }
    }
    __syncthreads();
    uint32_t qfh[4][4], qfl[4][4];
    {
        uint32_t aAddr = sb + (uint32_t)((16 * w + (lane & 15)) * AROW + ((lane >> 4) << 4));
        #pragma unroll
        for (int ds = 0; ds < 4; ds++) {
            LDSM4(qfh[ds][0], qfh[ds][1], qfh[ds][2], qfh[ds][3], aAddr + ds * 32);
            LDSM4(qfl[ds][0], qfl[ds][1], qfl[ds][2], qfl[ds][3], aAddr + 18432 + ds * 32);
        }
    }
    __syncthreads();

    int frow0 = tid >> 3, fcol = tid & 7;
    uint32_t fdst = sb + (uint32_t)(frow0 * AROW + fcol * 16);

    #define AISSUE(kt_, buf_) { \
        size_t g0 = base + (size_t)(((kt_) << 6) + frow0) * DK + fcol * 8; \
        size_t g1 = g0 + 32 * DK; \
        uint32_t d0 = fdst + (buf_) * (uint32_t)ASTG; \
        uint32_t d1 = d0 + 32 * AROW; \
        CPA16(d0,        Kh + g0); CPA16(d1,        Kh + g1); \
        CPA16(d0 + 9216, Vh + g0); CPA16(d1 + 9216, Vh + g1); }

    float o_[8][4] = {};
    float m0 = -1e30f, m1 = -1e30f, l0 = 0.f, l1 = 0.f;
    int q0w = q0 + 16 * w;
    int qg = lane >> 3;
    uint32_t kOff = (uint32_t)(((((qg >> 1) << 3) | (lane & 7)) * AROW) + ((qg & 1) << 4));
    uint32_t vOff = (uint32_t)(((((qg & 1) << 3) | (lane & 7)) * AROW) + ((qg >> 1) << 4));

    int niter = 2 * qt + 2;
    AISSUE(0, 0); CPCOMMIT();

    for (int kt = 0; kt < niter; kt++) {
        int k0 = kt << 6;
        int buf = kt & 1;
        CPWAIT(0);
        __syncthreads();
        if (kt + 1 < niter) { AISSUE(kt + 1, buf ^ 1); CPCOMMIT(); }

        uint32_t sK = sb + (uint32_t)buf * ASTG;

        // S = (Qh + Ql) K^T
        float s_[8][4] = {};
        #pragma unroll
        for (int ds = 0; ds < 4; ds++) {
            uint32_t bh[8][2];
            #pragma unroll
            for (int p = 0; p < 4; p++) {
                uint32_t ba_ = sK + kOff + (uint32_t)(p * 16 * AROW) + ds * 32;
                LDSM4(bh[2*p][0], bh[2*p][1], bh[2*p+1][0], bh[2*p+1][1], ba_);
            }
            #pragma unroll
            for (int j = 0; j < 8; j++) {
                MMA16816(s_[j], qfh[ds], bh[j]);
                MMA16816(s_[j], qfl[ds], bh[j]);
            }
        }

        // causal mask
        if (k0 + 63 > q0w) {
            int r0 = q0w + gid, r1 = r0 + 8;
            #pragma unroll
            for (int j = 0; j < 8; j++) {
                int cb = k0 + 8 * j + 2 * tig;
                if (cb     > r0) s_[j][0] = -1e30f;
                if (cb + 1 > r0) s_[j][1] = -1e30f;
                if (cb     > r1) s_[j][2] = -1e30f;
                if (cb + 1 > r1) s_[j][3] = -1e30f;
            }
        }

        // online softmax (poly exp)
        float mx0 = s_[0][0], mx1 = s_[0][2];
        #pragma unroll
        for (int j = 0; j < 8; j++) {
            mx0 = fmaxf(mx0, fmaxf(s_[j][0], s_[j][1]));
            mx1 = fmaxf(mx1, fmaxf(s_[j][2], s_[j][3]));
        }
        mx0 = fmaxf(mx0, __shfl_xor_sync(0xffffffffu, mx0, 1));
        mx0 = fmaxf(mx0, __shfl_xor_sync(0xffffffffu, mx0, 2));
        mx1 = fmaxf(mx1, __shfl_xor_sync(0xffffffffu, mx1, 1));
        mx1 = fmaxf(mx1, __shfl_xor_sync(0xffffffffu, mx1, 2));
        float mn0 = fmaxf(m0, mx0), mn1 = fmaxf(m1, mx1);
        float c0 = fexp(m0 - mn0), c1 = fexp(m1 - mn1);
        m0 = mn0; m1 = mn1;
        float rs0 = 0.f, rs1 = 0.f;
        #pragma unroll
        for (int j = 0; j < 8; j++) {
            s_[j][0] = fexp(s_[j][0] - mn0);
            s_[j][1] = fexp(s_[j][1] - mn0);
            s_[j][2] = fexp(s_[j][2] - mn1);
            s_[j][3] = fexp(s_[j][3] - mn1);
            rs0 += s_[j][0] + s_[j][1];
            rs1 += s_[j][2] + s_[j][3];
        }
        rs0 += __shfl_xor_sync(0xffffffffu, rs0, 1);
        rs0 += __shfl_xor_sync(0xffffffffu, rs0, 2);
        rs1 += __shfl_xor_sync(0xffffffffu, rs1, 1);
        rs1 += __shfl_xor_sync(0xffffffffu, rs1, 2);
        l0 = l0 * c0 + rs0; l1 = l1 * c1 + rs1;
        #pragma unroll
        for (int j = 0; j < 8; j++) {
            o_[j][0] *= c0; o_[j][1] *= c0; o_[j][2] *= c1; o_[j][3] *= c1;
        }

        // P -> A-frags in registers, fp16 split
        uint32_t pfh[4][4], pfl[4][4];
        #pragma unroll
        for (int ks = 0; ks < 4; ks++) {
            int j0 = 2 * ks, j1 = 2 * ks + 1;
            pack_split(s_[j0][0], s_[j0][1], pfh[ks][0], pfl[ks][0]);
            pack_split(s_[j0][2], s_[j0][3], pfh[ks][1], pfl[ks][1]);
            pack_split(s_[j1][0], s_[j1][1], pfh[ks][2], pfl[ks][2]);
            pack_split(s_[j1][2], s_[j1][3], pfh[ks][3], pfl[ks][3]);
        }

        // O += (Ph + Pl) V
        #pragma unroll
        for (int ks = 0; ks < 4; ks++) {
            uint32_t vh[8][2];
            #pragma unroll
            for (int p = 0; p < 4; p++) {
                uint32_t ba_ = sK + 9216 + vOff + (uint32_t)(ks * 16 * AROW) + p * 32;
                LDSM4T(vh[2*p][0], vh[2*p][1], vh[2*p+1][0], vh[2*p+1][1], ba_);
            }
            #pragma unroll
            for (int j = 0; j < 8; j++) {
                MMA16816(o_[j], pfh[ks], vh[j]);
                MMA16816(o_[j], pfl[ks], vh[j]);
            }
        }
    }

    // finalize
    float inv0 = 1.0f / l0, inv1 = 1.0f / l1;
    int r0 = q0 + 16 * w + gid, r1 = r0 + 8;
    float* O0 = O + ((size_t)bb * SEQ + r0) * DM + hh * DK + 2 * tig;
    float* O1 = O + ((size_t)bb * SEQ + r1) * DM + hh * DK + 2 * tig;
    #pragma unroll
    for (int j = 0; j < 8; j++) {
        *(float2*)(O0 + 8 * j) = make_float2(o_[j][0] * inv0, o_[j][1] * inv0);
        *(float2*)(O1 + 8 * j) = make_float2(o_[j][2] * inv1, o_[j][3] * inv1);
    }
}

// ---------------- launch ----------------
extern "C" void kernel_launch(void* const* d_in, const int* in_sizes, int n_in,
                              void* d_out, int out_size) {
    (void)in_sizes; (void)n_in; (void)out_size;
    const float* x   = (const float*)d_in[0];
    const int*   pos = (const int*)d_in[1];
    const float* Wq  = (const float*)d_in[2];
    const float* Wk  = (const float*)d_in[3];
    const float* Wv  = (const float*)d_in[4];
    const float* Wo  = (const float*)d_in[5];
    float* out = (float*)d_out;

    __half *xh, *xl, *wp, *qh, *ql, *kh, *vh;
    float* o;
    cudaGetSymbolAddress((void**)&xh, g_xh);
    cudaGetSymbolAddress((void**)&xl, g_xl);
    cudaGetSymbolAddress((void**)&wp, g_w);
    cudaGetSymbolAddress((void**)&qh, g_qh);
    cudaGetSymbolAddress((void**)&ql, g_ql);
    cudaGetSymbolAddress((void**)&kh, g_kh);
    cudaGetSymbolAddress((void**)&vh, g_vh);
    cudaGetSymbolAddress((void**)&o, g_o);

    cudaFuncSetAttribute(gemm_f16, cudaFuncAttributeMaxDynamicSharedMemorySize, GSMEM);
    cudaFuncSetAttribute(attn_mma, cudaFuncAttributeMaxDynamicSharedMemorySize, ASMEM);

    const int n4x = MTOT * DM / 4;
    const int n4w = DM * DM / 4;
    const size_t WS = (size_t)DM * DM;

    split_kernel<<<n4x / 256, 256>>>(x, xh, xl, n4x);
    conv_kernel<<<n4w / 256, 256>>>(Wq, wp + 0 * WS, n4w);
    conv_kernel<<<n4w / 256, 256>>>(Wk, wp + 1 * WS, n4w);
    conv_kernel<<<n4w / 256, 256>>>(Wv, wp + 2 * WS, n4w);
    conv_kernel<<<n4w / 256, 256>>>(Wo, wp + 3 * WS, n4w);

    dim3 ggrid(DM / 128, MTOT / 128);
    gemm_f16<<<ggrid, 256, GSMEM>>>(xh, xl, wp + 0 * WS, pos,
                                    nullptr, qh, ql, 1, 0.125f);
    gemm_f16<<<ggrid, 256, GSMEM>>>(xh, xl, wp + 1 * WS, pos,
                                    nullptr, kh, nullptr, 2, 1.0f);
    gemm_f16<<<ggrid, 256, GSMEM>>>(xh, xl, wp + 2 * WS, pos,
                                    nullptr, vh, nullptr, 3, 1.0f);

    dim3 agrid(SEQ / 128, NH, BATCHN);
    attn_mma<<<agrid, 256, ASMEM>>>(qh, ql, kh, vh, o);

    split_kernel<<<n4x / 256, 256>>>(o, xh, xl, n4x);
    gemm_f16<<<ggrid, 256, GSMEM>>>(xh, xl, wp + 3 * WS, pos,
                                    out, nullptr, nullptr, 0, 1.0f);
}

// round 13
// speedup vs baseline: 3.9324x; 1.1249x over previous
#include <cuda_runtime.h>
#include <cuda_fp16.h>
#include <math.h>
#include <stdint.h>

#define SEQ 4096
#define DM 1024
#define NH 16
#define DK 64
#define BATCHN 2
#define MTOT (BATCHN*SEQ)

// ---------------- scratch (allocation-free) ----------------
__device__ __half g_xh[(size_t)MTOT * DM];
__device__ __half g_xl[(size_t)MTOT * DM];
__device__ __half g_w[(size_t)4 * DM * DM];
__device__ __half g_qh[(size_t)MTOT * DM];
__device__ __half g_ql[(size_t)MTOT * DM];
__device__ __half g_kh[(size_t)MTOT * DM];
__device__ __half g_vh[(size_t)MTOT * DM];
__device__ float g_o[(size_t)MTOT * DM];

// ---------------- helpers ----------------
__device__ __forceinline__ uint32_t s2u(const void* p) {
    uint32_t a;
    asm("{ .reg .u64 t; cvta.to.shared.u64 t, %1; cvt.u32.u64 %0, t; }" : "=r"(a) : "l"(p));
    return a;
}

// RoPE rotation; Cody-Waite 2*pi reduction (robust under fast-math).
__device__ __forceinline__ void rope_rot(float p, float d_e, float& e, float& o) {
    const float LOG2_THETA_DIV = 13.287712379549449f / 64.0f;
    float freq = exp2f(-d_e * LOG2_THETA_DIV);
    float ang = p * freq;
    float n = rintf(ang * 0.15915494309189535f);
    float r = fmaf(-n, 6.28125f, ang);
    r = fmaf(-n, 1.9353071795864774e-3f, r);
    float s, c;
    sincosf(r, &s, &c);
    float ne = e * c - o * s;
    float no = e * s + o * c;
    e = ne; o = no;
}

// Fast exp for x <= 0 on the FMA/ALU pipes (no MUFU). ~1e-6 rel err.
__device__ __forceinline__ float fexp(float x) {
    float t = fmaxf(x * 1.4426950408889634f, -126.0f);
    float z = t + 12582912.0f;
    int ii = __float_as_int(z);
    float f = t - (z - 12582912.0f);
    float p = 1.3333558e-3f;
    p = fmaf(p, f, 9.6181291e-3f);
    p = fmaf(p, f, 5.5504109e-2f);
    p = fmaf(p, f, 2.4022651e-1f);
    p = fmaf(p, f, 6.9314718e-1f);
    p = fmaf(p, f, 1.0f);
    return __int_as_float((ii << 23) + 0x3F800000) * p;
}

// split fp32 pair -> packed fp16 hi + fp16 lo
__device__ __forceinline__ void pack_split(float a, float b, uint32_t& hp, uint32_t& lp) {
    __half2 H = __floats2half2_rn(a, b);
    hp = *(uint32_t*)&H;
    float2 hf = __half22float2(H);
    __half2 L = __floats2half2_rn(a - hf.x, b - hf.y);
    lp = *(uint32_t*)&L;
}

__device__ __forceinline__ uint32_t pack_h(float a, float b) {
    __half2 H = __floats2half2_rn(a, b);
    return *(uint32_t*)&H;
}

#define LDSM4(r0, r1, r2, r3, addr) \
    asm volatile("ldmatrix.sync.aligned.m8n8.x4.shared.b16 {%0,%1,%2,%3}, [%4];" \
        : "=r"(r0), "=r"(r1), "=r"(r2), "=r"(r3) : "r"(addr))

#define LDSM4T(r0, r1, r2, r3, addr) \
    asm volatile("ldmatrix.sync.aligned.m8n8.x4.trans.shared.b16 {%0,%1,%2,%3}, [%4];" \
        : "=r"(r0), "=r"(r1), "=r"(r2), "=r"(r3) : "r"(addr))

#define MMA16816(c, a, b) \
    asm volatile("mma.sync.aligned.m16n8k16.row.col.f32.f16.f16.f32 " \
        "{%0,%1,%2,%3}, {%4,%5,%6,%7}, {%8,%9}, {%0,%1,%2,%3};" \
        : "+f"((c)[0]), "+f"((c)[1]), "+f"((c)[2]), "+f"((c)[3]) \
        : "r"((a)[0]), "r"((a)[1]), "r"((a)[2]), "r"((a)[3]), "r"((b)[0]), "r"((b)[1]))

#define CPA16(dst, src) \
    asm volatile("cp.async.cg.shared.global [%0], [%1], 16;" :: "r"(dst), "l"(src))
#define CPCOMMIT() asm volatile("cp.async.commit_group;" ::: "memory")
#define CPWAIT(n)  asm volatile("cp.async.wait_group %0;" :: "n"(n) : "memory")

// ---------------- split kernel: fp32 -> (fp16 hi, fp16 lo) ----------------
__global__ __launch_bounds__(256) void split_kernel(
    const float* __restrict__ in, __half* __restrict__ hi,
    __half* __restrict__ lo, int n4)
{
    int i = blockIdx.x * 256 + threadIdx.x;
    if (i >= n4) return;
    float4 x = ((const float4*)in)[i];
    uint32_t h01, l01, h23, l23;
    pack_split(x.x, x.y, h01, l01);
    pack_split(x.z, x.w, h23, l23);
    ((uint2*)hi)[i] = make_uint2(h01, h23);
    ((uint2*)lo)[i] = make_uint2(l01, l23);
}

// ---------------- convert kernel: fp32 -> fp16 (hi only) ----------------
__global__ __launch_bounds__(256) void conv_kernel(
    const float* __restrict__ in, __half* __restrict__ hi, int n4)
{
    int i = blockIdx.x * 256 + threadIdx.x;
    if (i >= n4) return;
    float4 x = ((const float4*)in)[i];
    ((uint2*)hi)[i] = make_uint2(pack_h(x.x, x.y), pack_h(x.z, x.w));
}

// ---------------- fp16 2-pass GEMM via mma.sync, cp.async 3-stage, 2 CTA/SM ----------------
// C = (Ah + Al) * Bh.  A split fp16 hi/lo, B plain fp16.
#define SROWB 80
#define ARR_B (128 * SROWB)
#define STAGE_B (3 * ARR_B)      // 30720
#define NSTAGE 3
#define GSMEM (NSTAGE * STAGE_B) // 92160

__global__ __launch_bounds__(256, 2) void gemm_f16(
    const __half* __restrict__ Ah, const __half* __restrict__ Al,
    const __half* __restrict__ Bh,
    const int* __restrict__ pos, float* __restrict__ outf,
    __half* __restrict__ outh, __half* __restrict__ outl,
    int mode, float scale)
{
    extern __shared__ char smem[];
    const uint32_t sb32 = s2u(smem);
    int tid = threadIdx.x, lane = tid & 31, wid = tid >> 5;
    int m0 = blockIdx.y << 7, n0 = blockIdx.x << 7;
    int wm = (wid >> 2) << 6;
    int wn = (wid & 3) << 5;

    int frow = tid >> 1;
    int fh = tid & 1;
    const uint4* gAh = (const uint4*)(Ah + (size_t)(m0 + frow) * DM);
    const uint4* gAl = (const uint4*)(Al + (size_t)(m0 + frow) * DM);
    const uint4* gBh = (const uint4*)(Bh + (size_t)(n0 + frow) * DM);
    uint32_t sfill = sb32 + (uint32_t)(frow * SROWB + fh * 32);

    #define GISSUE(s_) { \
        int bi = (s_) * 4 + (fh << 1); \
        uint32_t d0 = sfill + ((s_) % NSTAGE) * STAGE_B; \
        CPA16(d0 + 0 * ARR_B,      gAh + bi); \
        CPA16(d0 + 0 * ARR_B + 16, gAh + bi + 1); \
        CPA16(d0 + 1 * ARR_B,      gAl + bi); \
        CPA16(d0 + 1 * ARR_B + 16, gAl + bi + 1); \
        CPA16(d0 + 2 * ARR_B,      gBh + bi); \
        CPA16(d0 + 2 * ARR_B + 16, gBh + bi + 1); }

    float c[4][4][4] = {};

    GISSUE(0); CPCOMMIT();
    GISSUE(1); CPCOMMIT();

    for (int s = 0; s < 32; s++) {
        CPWAIT(1);              // stage s resident (1 newer group may pend)
        __syncthreads();        // data visible; compute s-1 fully done
        if (s + 2 < 32) GISSUE(s + 2);
        CPCOMMIT();             // uniform group count

        uint32_t base = sb32 + (uint32_t)((s % NSTAGE) * STAGE_B);
        uint32_t aRow = base + (uint32_t)(wm + (lane & 15)) * SROWB + ((lane >> 4) << 4);
        int q = lane >> 3;
        uint32_t bRow = base + 2 * ARR_B +
                        (uint32_t)(wn + ((q >> 1) << 3) + (lane & 7)) * SROWB +
                        ((q & 1) << 4);

        #pragma unroll
        for (int step = 0; step < 2; step++) {
            uint32_t ko = step * 32;
            uint32_t ah[4][4], al[4][4], bh[4][2];
            #pragma unroll
            for (int mt = 0; mt < 4; mt++) {
                uint32_t aAddr = aRow + (uint32_t)(mt * 16) * SROWB + ko;
                LDSM4(ah[mt][0], ah[mt][1], ah[mt][2], ah[mt][3], aAddr);
                LDSM4(al[mt][0], al[mt][1], al[mt][2], al[mt][3], aAddr + ARR_B);
            }
            #pragma unroll
            for (int pn = 0; pn < 2; pn++) {
                uint32_t bAddr = bRow + (uint32_t)(pn * 16) * SROWB + ko;
                LDSM4(bh[2*pn][0], bh[2*pn][1], bh[2*pn+1][0], bh[2*pn+1][1], bAddr);
            }
            #pragma unroll
            for (int mt = 0; mt < 4; mt++)
                #pragma unroll
                for (int nt = 0; nt < 4; nt++) {
                    MMA16816(c[mt][nt], ah[mt], bh[nt]);
                    MMA16816(c[mt][nt], al[mt], bh[nt]);
                }
        }
    }

    // ---------------- epilogue ----------------
    int gid = lane >> 2, tig = lane & 3;
    #pragma unroll
    for (int mt = 0; mt < 4; mt++) {
        int m_a = m0 + wm + mt * 16 + gid;
        int m_b = m_a + 8;
        float p_a = 0.f, p_b = 0.f;
        if (mode == 1 || mode == 2) { p_a = (float)pos[m_a]; p_b = (float)pos[m_b]; }
        #pragma unroll
        for (int nt = 0; nt < 4; nt++) {
            int n = n0 + wn + nt * 8 + tig * 2;
            float v0 = c[mt][nt][0], v1 = c[mt][nt][1];
            float v2 = c[mt][nt][2], v3 = c[mt][nt][3];
            if (mode == 0) {
                *(float2*)(outf + (size_t)m_a * DM + n) = make_float2(v0, v1);
                *(float2*)(outf + (size_t)m_b * DM + n) = make_float2(v2, v3);
            } else {
                int h = n >> 6, d = n & 63;
                if (mode != 3) {
                    rope_rot(p_a, (float)d, v0, v1);
                    rope_rot(p_b, (float)d, v2, v3);
                }
                v0 *= scale; v1 *= scale; v2 *= scale; v3 *= scale;
                int ba = m_a >> 12, sa = m_a & (SEQ - 1);
                int bb = m_b >> 12, sbq = m_b & (SEQ - 1);
                size_t ia = ((size_t)(ba * NH + h) * SEQ + sa) * DK + d;
                size_t ib = ((size_t)(bb * NH + h) * SEQ + sbq) * DK + d;
                if (mode == 1) {  // Q: split hi/lo
                    uint32_t hp, lp;
                    pack_split(v0, v1, hp, lp);
                    *(uint32_t*)(outh + ia) = hp; *(uint32_t*)(outl + ia) = lp;
                    pack_split(v2, v3, hp, lp);
                    *(uint32_t*)(outh + ib) = hp; *(uint32_t*)(outl + ib) = lp;
                } else {          // K/V: hi only
                    *(uint32_t*)(outh + ia) = pack_h(v0, v1);
                    *(uint32_t*)(outh + ib) = pack_h(v2, v3);
                }
            }
        }
    }
}

// ---------------- HMMA flash attention: S 2-pass, PV 1-pass ----------------
#define AROW 144
#define ASTG 18432
#define ASMEM (2 * ASTG)

__global__ __launch_bounds__(256) void attn_mma(
    const __half* __restrict__ Qh, const __half* __restrict__ Ql,
    const __half* __restrict__ Kh, const __half* __restrict__ Vh,
    float* __restrict__ O)
{
    extern __shared__ char sm[];
    uint32_t sb = s2u(sm);
    int tid = threadIdx.x, lane = tid & 31, w = tid >> 5;
    int qt = blockIdx.x, hh = blockIdx.y, bb = blockIdx.z;
    int q0 = qt << 7;
    size_t base = (size_t)(bb * NH + hh) * SEQ * DK;
    int gid = lane >> 2, tig = lane & 3;

    // ---- Q tile -> smem (hi @0, lo @18432) -> register fragments ----
    {
        int row = tid >> 1, hf = tid & 1;
        const uint4* gqh = (const uint4*)(Qh + base + (size_t)(q0 + row) * DK);
        const uint4* gql = (const uint4*)(Ql + base + (size_t)(q0 + row) * DK);
        char* s0 = sm + row * AROW + hf * 64;
        #pragma unroll
        for (int j = 0; j < 4; j++) {
            *(uint4*)(s0 + j * 16)         = gqh[hf * 4 + j];
            *(uint4*)(s0 + 18432 + j * 16) = gql[hf * 4 + j];
        }
    }
    __syncthreads();
    uint32_t qfh[4][4], qfl[4][4];
    {
        uint32_t aAddr = sb + (uint32_t)((16 * w + (lane & 15)) * AROW + ((lane >> 4) << 4));
        #pragma unroll
        for (int ds = 0; ds < 4; ds++) {
            LDSM4(qfh[ds][0], qfh[ds][1], qfh[ds][2], qfh[ds][3], aAddr + ds * 32);
            LDSM4(qfl[ds][0], qfl[ds][1], qfl[ds][2], qfl[ds][3], aAddr + 18432 + ds * 32);
        }
    }
    __syncthreads();

    int frow0 = tid >> 3, fcol = tid & 7;
    uint32_t fdst = sb + (uint32_t)(frow0 * AROW + fcol * 16);

    #define AISSUE(kt_, buf_) { \
        size_t g0 = base + (size_t)(((kt_) << 6) + frow0) * DK + fcol * 8; \
        size_t g1 = g0 + 32 * DK; \
        uint32_t d0 = fdst + (buf_) * (uint32_t)ASTG; \
        uint32_t d1 = d0 + 32 * AROW; \
        CPA16(d0,        Kh + g0); CPA16(d1,        Kh + g1); \
        CPA16(d0 + 9216, Vh + g0); CPA16(d1 + 9216, Vh + g1); }

    float o_[8][4] = {};
    float m0 = -1e30f, m1 = -1e30f, l0 = 0.f, l1 = 0.f;
    int q0w = q0 + 16 * w;
    int qg = lane >> 3;
    uint32_t kOff = (uint32_t)(((((qg >> 1) << 3) | (lane & 7)) * AROW) + ((qg & 1) << 4));
    uint32_t vOff = (uint32_t)(((((qg & 1) << 3) | (lane & 7)) * AROW) + ((qg >> 1) << 4));

    int niter = 2 * qt + 2;
    AISSUE(0, 0); CPCOMMIT();

    for (int kt = 0; kt < niter; kt++) {
        int k0 = kt << 6;
        int buf = kt & 1;
        CPWAIT(0);
        __syncthreads();
        if (kt + 1 < niter) { AISSUE(kt + 1, buf ^ 1); CPCOMMIT(); }

        uint32_t sK = sb + (uint32_t)buf * ASTG;

        // S = (Qh + Ql) K^T
        float s_[8][4] = {};
        #pragma unroll
        for (int ds = 0; ds < 4; ds++) {
            uint32_t bh[8][2];
            #pragma unroll
            for (int p = 0; p < 4; p++) {
                uint32_t ba_ = sK + kOff + (uint32_t)(p * 16 * AROW) + ds * 32;
                LDSM4(bh[2*p][0], bh[2*p][1], bh[2*p+1][0], bh[2*p+1][1], ba_);
            }
            #pragma unroll
            for (int j = 0; j < 8; j++) {
                MMA16816(s_[j], qfh[ds], bh[j]);
                MMA16816(s_[j], qfl[ds], bh[j]);
            }
        }

        // causal mask
        if (k0 + 63 > q0w) {
            int r0 = q0w + gid, r1 = r0 + 8;
            #pragma unroll
            for (int j = 0; j < 8; j++) {
                int cb = k0 + 8 * j + 2 * tig;
                if (cb     > r0) s_[j][0] = -1e30f;
                if (cb + 1 > r0) s_[j][1] = -1e30f;
                if (cb     > r1) s_[j][2] = -1e30f;
                if (cb + 1 > r1) s_[j][3] = -1e30f;
            }
        }

        // online softmax (poly exp)
        float mx0 = s_[0][0], mx1 = s_[0][2];
        #pragma unroll
        for (int j = 0; j < 8; j++) {
            mx0 = fmaxf(mx0, fmaxf(s_[j][0], s_[j][1]));
            mx1 = fmaxf(mx1, fmaxf(s_[j][2], s_[j][3]));
        }
        mx0 = fmaxf(mx0, __shfl_xor_sync(0xffffffffu, mx0, 1));
        mx0 = fmaxf(mx0, __shfl_xor_sync(0xffffffffu, mx0, 2));
        mx1 = fmaxf(mx1, __shfl_xor_sync(0xffffffffu, mx1, 1));
        mx1 = fmaxf(mx1, __shfl_xor_sync(0xffffffffu, mx1, 2));
        float mn0 = fmaxf(m0, mx0), mn1 = fmaxf(m1, mx1);
        float c0 = fexp(m0 - mn0), c1 = fexp(m1 - mn1);
        m0 = mn0; m1 = mn1;
        float rs0 = 0.f, rs1 = 0.f;
        #pragma unroll
        for (int j = 0; j < 8; j++) {
            s_[j][0] = fexp(s_[j][0] - mn0);
            s_[j][1] = fexp(s_[j][1] - mn0);
            s_[j][2] = fexp(s_[j][2] - mn1);
            s_[j][3] = fexp(s_[j][3] - mn1);
            rs0 += s_[j][0] + s_[j][1];
            rs1 += s_[j][2] + s_[j][3];
        }
        rs0 += __shfl_xor_sync(0xffffffffu, rs0, 1);
        rs0 += __shfl_xor_sync(0xffffffffu, rs0, 2);
        rs1 += __shfl_xor_sync(0xffffffffu, rs1, 1);
        rs1 += __shfl_xor_sync(0xffffffffu, rs1, 2);
        l0 = l0 * c0 + rs0; l1 = l1 * c1 + rs1;
        #pragma unroll
        for (int j = 0; j < 8; j++) {
            o_[j][0] *= c0; o_[j][1] *= c0; o_[j][2] *= c1; o_[j][3] *= c1;
        }

        // P -> A-frags (fp16 hi only; V already fp16-quantized, same error class)
        uint32_t pf[4][4];
        #pragma unroll
        for (int ks = 0; ks < 4; ks++) {
            int j0 = 2 * ks, j1 = 2 * ks + 1;
            pf[ks][0] = pack_h(s_[j0][0], s_[j0][1]);
            pf[ks][1] = pack_h(s_[j0][2], s_[j0][3]);
            pf[ks][2] = pack_h(s_[j1][0], s_[j1][1]);
            pf[ks][3] = pack_h(s_[j1][2], s_[j1][3]);
        }

        // O += P V  (single pass)
        #pragma unroll
        for (int ks = 0; ks < 4; ks++) {
            uint32_t vh[8][2];
            #pragma unroll
            for (int p = 0; p < 4; p++) {
                uint32_t ba_ = sK + 9216 + vOff + (uint32_t)(ks * 16 * AROW) + p * 32;
                LDSM4T(vh[2*p][0], vh[2*p][1], vh[2*p+1][0], vh[2*p+1][1], ba_);
            }
            #pragma unroll
            for (int j = 0; j < 8; j++)
                MMA16816(o_[j], pf[ks], vh[j]);
        }
    }

    // finalize
    float inv0 = 1.0f / l0, inv1 = 1.0f / l1;
    int r0 = q0 + 16 * w + gid, r1 = r0 + 8;
    float* O0 = O + ((size_t)bb * SEQ + r0) * DM + hh * DK + 2 * tig;
    float* O1 = O + ((size_t)bb * SEQ + r1) * DM + hh * DK + 2 * tig;
    #pragma unroll
    for (int j = 0; j < 8; j++) {
        *(float2*)(O0 + 8 * j) = make_float2(o_[j][0] * inv0, o_[j][1] * inv0);
        *(float2*)(O1 + 8 * j) = make_float2(o_[j][2] * inv1, o_[j][3] * inv1);
    }
}

// ---------------- launch ----------------
extern "C" void kernel_launch(void* const* d_in, const int* in_sizes, int n_in,
                              void* d_out, int out_size) {
    (void)in_sizes; (void)n_in; (void)out_size;
    const float* x   = (const float*)d_in[0];
    const int*   pos = (const int*)d_in[1];
    const float* Wq  = (const float*)d_in[2];
    const float* Wk  = (const float*)d_in[3];
    const float* Wv  = (const float*)d_in[4];
    const float* Wo  = (const float*)d_in[5];
    float* out = (float*)d_out;

    __half *xh, *xl, *wp, *qh, *ql, *kh, *vh;
    float* o;
    cudaGetSymbolAddress((void**)&xh, g_xh);
    cudaGetSymbolAddress((void**)&xl, g_xl);
    cudaGetSymbolAddress((void**)&wp, g_w);
    cudaGetSymbolAddress((void**)&qh, g_qh);
    cudaGetSymbolAddress((void**)&ql, g_ql);
    cudaGetSymbolAddress((void**)&kh, g_kh);
    cudaGetSymbolAddress((void**)&vh, g_vh);
    cudaGetSymbolAddress((void**)&o, g_o);

    cudaFuncSetAttribute(gemm_f16, cudaFuncAttributeMaxDynamicSharedMemorySize, GSMEM);
    cudaFuncSetAttribute(attn_mma, cudaFuncAttributeMaxDynamicSharedMemorySize, ASMEM);

    const int n4x = MTOT * DM / 4;
    const int n4w = DM * DM / 4;
    const size_t WS = (size_t)DM * DM;

    split_kernel<<<n4x / 256, 256>>>(x, xh, xl, n4x);
    conv_kernel<<<n4w / 256, 256>>>(Wq, wp + 0 * WS, n4w);
    conv_kernel<<<n4w / 256, 256>>>(Wk, wp + 1 * WS, n4w);
    conv_kernel<<<n4w / 256, 256>>>(Wv, wp + 2 * WS, n4w);
    conv_kernel<<<n4w / 256, 256>>>(Wo, wp + 3 * WS, n4w);

    dim3 ggrid(DM / 128, MTOT / 128);
    gemm_f16<<<ggrid, 256, GSMEM>>>(xh, xl, wp + 0 * WS, pos,
                                    nullptr, qh, ql, 1, 0.125f);
    gemm_f16<<<ggrid, 256, GSMEM>>>(xh, xl, wp + 1 * WS, pos,
                                    nullptr, kh, nullptr, 2, 1.0f);
    gemm_f16<<<ggrid, 256, GSMEM>>>(xh, xl, wp + 2 * WS, pos,
                                    nullptr, vh, nullptr, 3, 1.0f);

    dim3 agrid(SEQ / 128, NH, BATCHN);
    attn_mma<<<agrid, 256, ASMEM>>>(qh, ql, kh, vh, o);

    split_kernel<<<n4x / 256, 256>>>(o, xh, xl, n4x);
    gemm_f16<<<ggrid, 256, GSMEM>>>(xh, xl, wp + 3 * WS, pos,
                                    out, nullptr, nullptr, 0, 1.0f);
}

// round 14
// speedup vs baseline: 4.1503x; 1.0554x over previous
#include <cuda_runtime.h>
#include <cuda_fp16.h>
#include <math.h>
#include <stdint.h>

#define SEQ 4096
#define DM 1024
#define NH 16
#define DK 64
#define BATCHN 2
#define MTOT (BATCHN*SEQ)

// ---------------- scratch (allocation-free) ----------------
__device__ __half g_xh[(size_t)MTOT * DM];
__device__ __half g_xl[(size_t)MTOT * DM];
__device__ __half g_w[(size_t)4 * DM * DM];
__device__ __half g_qh[(size_t)MTOT * DM];
__device__ __half g_ql[(size_t)MTOT * DM];
__device__ __half g_kh[(size_t)MTOT * DM];
__device__ __half g_vh[(size_t)MTOT * DM];
__device__ float g_o[(size_t)MTOT * DM];

// ---------------- helpers ----------------
__device__ __forceinline__ uint32_t s2u(const void* p) {
    uint32_t a;
    asm("{ .reg .u64 t; cvta.to.shared.u64 t, %1; cvt.u32.u64 %0, t; }" : "=r"(a) : "l"(p));
    return a;
}

// RoPE rotation; Cody-Waite 2*pi reduction (robust under fast-math).
__device__ __forceinline__ void rope_rot(float p, float d_e, float& e, float& o) {
    const float LOG2_THETA_DIV = 13.287712379549449f / 64.0f;
    float freq = exp2f(-d_e * LOG2_THETA_DIV);
    float ang = p * freq;
    float n = rintf(ang * 0.15915494309189535f);
    float r = fmaf(-n, 6.28125f, ang);
    r = fmaf(-n, 1.9353071795864774e-3f, r);
    float s, c;
    sincosf(r, &s, &c);
    float ne = e * c - o * s;
    float no = e * s + o * c;
    e = ne; o = no;
}

// Fast exp for x <= 0 on the FMA/ALU pipes (no MUFU). ~1e-6 rel err.
__device__ __forceinline__ float fexp(float x) {
    float t = fmaxf(x * 1.4426950408889634f, -126.0f);
    float z = t + 12582912.0f;
    int ii = __float_as_int(z);
    float f = t - (z - 12582912.0f);
    float p = 1.3333558e-3f;
    p = fmaf(p, f, 9.6181291e-3f);
    p = fmaf(p, f, 5.5504109e-2f);
    p = fmaf(p, f, 2.4022651e-1f);
    p = fmaf(p, f, 6.9314718e-1f);
    p = fmaf(p, f, 1.0f);
    return __int_as_float((ii << 23) + 0x3F800000) * p;
}

// split fp32 pair -> packed fp16 hi + fp16 lo
__device__ __forceinline__ void pack_split(float a, float b, uint32_t& hp, uint32_t& lp) {
    __half2 H = __floats2half2_rn(a, b);
    hp = *(uint32_t*)&H;
    float2 hf = __half22float2(H);
    __half2 L = __floats2half2_rn(a - hf.x, b - hf.y);
    lp = *(uint32_t*)&L;
}

__device__ __forceinline__ uint32_t pack_h(float a, float b) {
    __half2 H = __floats2half2_rn(a, b);
    return *(uint32_t*)&H;
}

#define LDSM4(r0, r1, r2, r3, addr) \
    asm volatile("ldmatrix.sync.aligned.m8n8.x4.shared.b16 {%0,%1,%2,%3}, [%4];" \
        : "=r"(r0), "=r"(r1), "=r"(r2), "=r"(r3) : "r"(addr))

#define LDSM4T(r0, r1, r2, r3, addr) \
    asm volatile("ldmatrix.sync.aligned.m8n8.x4.trans.shared.b16 {%0,%1,%2,%3}, [%4];" \
        : "=r"(r0), "=r"(r1), "=r"(r2), "=r"(r3) : "r"(addr))

#define MMA16816(c, a, b) \
    asm volatile("mma.sync.aligned.m16n8k16.row.col.f32.f16.f16.f32 " \
        "{%0,%1,%2,%3}, {%4,%5,%6,%7}, {%8,%9}, {%0,%1,%2,%3};" \
        : "+f"((c)[0]), "+f"((c)[1]), "+f"((c)[2]), "+f"((c)[3]) \
        : "r"((a)[0]), "r"((a)[1]), "r"((a)[2]), "r"((a)[3]), "r"((b)[0]), "r"((b)[1]))

#define CPA16(dst, src) \
    asm volatile("cp.async.cg.shared.global [%0], [%1], 16;" :: "r"(dst), "l"(src))
#define CPCOMMIT() asm volatile("cp.async.commit_group;" ::: "memory")
#define CPWAIT(n)  asm volatile("cp.async.wait_group %0;" :: "n"(n) : "memory")

// ---------------- split kernel: fp32 -> (fp16 hi, fp16 lo) ----------------
__global__ __launch_bounds__(256) void split_kernel(
    const float* __restrict__ in, __half* __restrict__ hi,
    __half* __restrict__ lo, int n4)
{
    int i = blockIdx.x * 256 + threadIdx.x;
    if (i >= n4) return;
    float4 x = ((const float4*)in)[i];
    uint32_t h01, l01, h23, l23;
    pack_split(x.x, x.y, h01, l01);
    pack_split(x.z, x.w, h23, l23);
    ((uint2*)hi)[i] = make_uint2(h01, h23);
    ((uint2*)lo)[i] = make_uint2(l01, l23);
}

// ---------------- fused convert: 4 fp32 weights -> fp16 (blockIdx.y selects) ----------------
__global__ __launch_bounds__(256) void conv4_kernel(
    const float* __restrict__ w0, const float* __restrict__ w1,
    const float* __restrict__ w2, const float* __restrict__ w3,
    __half* __restrict__ hi, int n4)
{
    int i = blockIdx.x * 256 + threadIdx.x;
    if (i >= n4) return;
    int sel = blockIdx.y;
    const float* in = sel == 0 ? w0 : (sel == 1 ? w1 : (sel == 2 ? w2 : w3));
    float4 x = ((const float4*)in)[i];
    ((uint2*)(hi + (size_t)sel * DM * DM))[i] =
        make_uint2(pack_h(x.x, x.y), pack_h(x.z, x.w));
}

// ---------------- GEMM common config ----------------
#define SROWB 80
#define ARR_B (128 * SROWB)
#define STAGE_B (3 * ARR_B)      // 30720
#define NSTAGE 3
#define GSMEM (NSTAGE * STAGE_B) // 92160

#define GISSUE(s_) { \
    int bi = (s_) * 4 + (fh << 1); \
    uint32_t d0 = sfill + ((s_) % NSTAGE) * STAGE_B; \
    CPA16(d0 + 0 * ARR_B,      gAh + bi); \
    CPA16(d0 + 0 * ARR_B + 16, gAh + bi + 1); \
    CPA16(d0 + 1 * ARR_B,      gAl + bi); \
    CPA16(d0 + 1 * ARR_B + 16, gAl + bi + 1); \
    CPA16(d0 + 2 * ARR_B,      gBh + bi); \
    CPA16(d0 + 2 * ARR_B + 16, gBh + bi + 1); }

#define GEMM_MAINLOOP() \
    GISSUE(0); CPCOMMIT(); \
    GISSUE(1); CPCOMMIT(); \
    for (int s = 0; s < 32; s++) { \
        CPWAIT(1); \
        __syncthreads(); \
        if (s + 2 < 32) GISSUE(s + 2); \
        CPCOMMIT(); \
        uint32_t base = sb32 + (uint32_t)((s % NSTAGE) * STAGE_B); \
        uint32_t aRow = base + (uint32_t)(wm + (lane & 15)) * SROWB + ((lane >> 4) << 4); \
        int q = lane >> 3; \
        uint32_t bRow = base + 2 * ARR_B + \
                        (uint32_t)(wn + ((q >> 1) << 3) + (lane & 7)) * SROWB + \
                        ((q & 1) << 4); \
        _Pragma("unroll") \
        for (int step = 0; step < 2; step++) { \
            uint32_t ko = step * 32; \
            uint32_t ah[4][4], al[4][4], bh[4][2]; \
            _Pragma("unroll") \
            for (int mt = 0; mt < 4; mt++) { \
                uint32_t aAddr = aRow + (uint32_t)(mt * 16) * SROWB + ko; \
                LDSM4(ah[mt][0], ah[mt][1], ah[mt][2], ah[mt][3], aAddr); \
                LDSM4(al[mt][0], al[mt][1], al[mt][2], al[mt][3], aAddr + ARR_B); \
            } \
            _Pragma("unroll") \
            for (int pn = 0; pn < 2; pn++) { \
                uint32_t bAddr = bRow + (uint32_t)(pn * 16) * SROWB + ko; \
                LDSM4(bh[2*pn][0], bh[2*pn][1], bh[2*pn+1][0], bh[2*pn+1][1], bAddr); \
            } \
            _Pragma("unroll") \
            for (int mt = 0; mt < 4; mt++) \
                _Pragma("unroll") \
                for (int nt = 0; nt < 4; nt++) { \
                    MMA16816(c[mt][nt], ah[mt], bh[nt]); \
                    MMA16816(c[mt][nt], al[mt], bh[nt]); \
                } \
        } \
    }

// ---------------- fused QKV projection GEMM (one launch, 1536 CTAs) ----------------
// n-space is [0, 3*DM): pi = n0>>10 selects Q/K/V weight + epilogue.
__global__ __launch_bounds__(256, 2) void gemm_qkv(
    const __half* __restrict__ Ah, const __half* __restrict__ Al,
    const __half* __restrict__ W,
    const int* __restrict__ pos,
    __half* __restrict__ qh, __half* __restrict__ ql,
    __half* __restrict__ kh, __half* __restrict__ vh)
{
    extern __shared__ char smem[];
    const uint32_t sb32 = s2u(smem);
    int tid = threadIdx.x, lane = tid & 31, wid = tid >> 5;
    int m0 = blockIdx.y << 7, n0 = blockIdx.x << 7;
    int pi = n0 >> 10;           // 0=Q, 1=K, 2=V
    int nn0 = n0 & 1023;
    int wm = (wid >> 2) << 6;
    int wn = (wid & 3) << 5;

    int frow = tid >> 1;
    int fh = tid & 1;
    const uint4* gAh = (const uint4*)(Ah + (size_t)(m0 + frow) * DM);
    const uint4* gAl = (const uint4*)(Al + (size_t)(m0 + frow) * DM);
    const uint4* gBh = (const uint4*)(W + (size_t)pi * DM * DM + (size_t)(nn0 + frow) * DM);
    uint32_t sfill = sb32 + (uint32_t)(frow * SROWB + fh * 32);

    float c[4][4][4] = {};
    GEMM_MAINLOOP();

    // epilogue
    int gid = lane >> 2, tig = lane & 3;
    float scale = (pi == 0) ? 0.125f : 1.0f;
    #pragma unroll
    for (int mt = 0; mt < 4; mt++) {
        int m_a = m0 + wm + mt * 16 + gid;
        int m_b = m_a + 8;
        float p_a = 0.f, p_b = 0.f;
        if (pi != 2) { p_a = (float)pos[m_a]; p_b = (float)pos[m_b]; }
        #pragma unroll
        for (int nt = 0; nt < 4; nt++) {
            int n = nn0 + wn + nt * 8 + tig * 2;
            float v0 = c[mt][nt][0], v1 = c[mt][nt][1];
            float v2 = c[mt][nt][2], v3 = c[mt][nt][3];
            int h = n >> 6, d = n & 63;
            if (pi != 2) {
                rope_rot(p_a, (float)d, v0, v1);
                rope_rot(p_b, (float)d, v2, v3);
            }
            v0 *= scale; v1 *= scale; v2 *= scale; v3 *= scale;
            int ba = m_a >> 12, sa = m_a & (SEQ - 1);
            int bb = m_b >> 12, sbq = m_b & (SEQ - 1);
            size_t ia = ((size_t)(ba * NH + h) * SEQ + sa) * DK + d;
            size_t ib = ((size_t)(bb * NH + h) * SEQ + sbq) * DK + d;
            if (pi == 0) {
                uint32_t hp, lp;
                pack_split(v0, v1, hp, lp);
                *(uint32_t*)(qh + ia) = hp; *(uint32_t*)(ql + ia) = lp;
                pack_split(v2, v3, hp, lp);
                *(uint32_t*)(qh + ib) = hp; *(uint32_t*)(ql + ib) = lp;
            } else {
                __half* dst = (pi == 1) ? kh : vh;
                *(uint32_t*)(dst + ia) = pack_h(v0, v1);
                *(uint32_t*)(dst + ib) = pack_h(v2, v3);
            }
        }
    }
}

// ---------------- output projection GEMM (fp32 out) ----------------
__global__ __launch_bounds__(256, 2) void gemm_out(
    const __half* __restrict__ Ah, const __half* __restrict__ Al,
    const __half* __restrict__ Bh, float* __restrict__ outf)
{
    extern __shared__ char smem[];
    const uint32_t sb32 = s2u(smem);
    int tid = threadIdx.x, lane = tid & 31, wid = tid >> 5;
    int m0 = blockIdx.y << 7, n0 = blockIdx.x << 7;
    int wm = (wid >> 2) << 6;
    int wn = (wid & 3) << 5;

    int frow = tid >> 1;
    int fh = tid & 1;
    const uint4* gAh = (const uint4*)(Ah + (size_t)(m0 + frow) * DM);
    const uint4* gAl = (const uint4*)(Al + (size_t)(m0 + frow) * DM);
    const uint4* gBh = (const uint4*)(Bh + (size_t)(n0 + frow) * DM);
    uint32_t sfill = sb32 + (uint32_t)(frow * SROWB + fh * 32);

    float c[4][4][4] = {};
    GEMM_MAINLOOP();

    int gid = lane >> 2, tig = lane & 3;
    #pragma unroll
    for (int mt = 0; mt < 4; mt++) {
        int m_a = m0 + wm + mt * 16 + gid;
        int m_b = m_a + 8;
        #pragma unroll
        for (int nt = 0; nt < 4; nt++) {
            int n = n0 + wn + nt * 8 + tig * 2;
            *(float2*)(outf + (size_t)m_a * DM + n) = make_float2(c[mt][nt][0], c[mt][nt][1]);
            *(float2*)(outf + (size_t)m_b * DM + n) = make_float2(c[mt][nt][2], c[mt][nt][3]);
        }
    }
}

// ---------------- HMMA flash attention: S 2-pass, PV 1-pass, longest-first ----------------
#define AROW 144
#define ASTG 18432
#define ASMEM (2 * ASTG)

__global__ __launch_bounds__(256) void attn_mma(
    const __half* __restrict__ Qh, const __half* __restrict__ Ql,
    const __half* __restrict__ Kh, const __half* __restrict__ Vh,
    float* __restrict__ O)
{
    extern __shared__ char sm[];
    uint32_t sb = s2u(sm);
    int tid = threadIdx.x, lane = tid & 31, w = tid >> 5;
    int qt = (int)gridDim.x - 1 - (int)blockIdx.x;  // longest job first
    int hh = blockIdx.y, bb = blockIdx.z;
    int q0 = qt << 7;
    size_t base = (size_t)(bb * NH + hh) * SEQ * DK;
    int gid = lane >> 2, tig = lane & 3;

    // ---- Q tile -> smem (hi @0, lo @18432) -> register fragments ----
    {
        int row = tid >> 1, hf = tid & 1;
        const uint4* gqh = (const uint4*)(Qh + base + (size_t)(q0 + row) * DK);
        const uint4* gql = (const uint4*)(Ql + base + (size_t)(q0 + row) * DK);
        char* s0 = sm + row * AROW + hf * 64;
        #pragma unroll
        for (int j = 0; j < 4; j++) {
            *(uint4*)(s0 + j * 16)         = gqh[hf * 4 + j];
            *(uint4*)(s0 + 18432 + j * 16) = gql[hf * 4 + j];
        }
    }
    __syncthreads();
    uint32_t qfh[4][4], qfl[4][4];
    {
        uint32_t aAddr = sb + (uint32_t)((16 * w + (lane & 15)) * AROW + ((lane >> 4) << 4));
        #pragma unroll
        for (int ds = 0; ds < 4; ds++) {
            LDSM4(qfh[ds][0], qfh[ds][1], qfh[ds][2], qfh[ds][3], aAddr + ds * 32);
            LDSM4(qfl[ds][0], qfl[ds][1], qfl[ds][2], qfl[ds][3], aAddr + 18432 + ds * 32);
        }
    }
    __syncthreads();

    int frow0 = tid >> 3, fcol = tid & 7;
    uint32_t fdst = sb + (uint32_t)(frow0 * AROW + fcol * 16);

    #define AISSUE(kt_, buf_) { \
        size_t g0 = base + (size_t)(((kt_) << 6) + frow0) * DK + fcol * 8; \
        size_t g1 = g0 + 32 * DK; \
        uint32_t d0 = fdst + (buf_) * (uint32_t)ASTG; \
        uint32_t d1 = d0 + 32 * AROW; \
        CPA16(d0,        Kh + g0); CPA16(d1,        Kh + g1); \
        CPA16(d0 + 9216, Vh + g0); CPA16(d1 + 9216, Vh + g1); }

    float o_[8][4] = {};
    float m0 = -1e30f, m1 = -1e30f, l0 = 0.f, l1 = 0.f;
    int q0w = q0 + 16 * w;
    int qg = lane >> 3;
    uint32_t kOff = (uint32_t)(((((qg >> 1) << 3) | (lane & 7)) * AROW) + ((qg & 1) << 4));
    uint32_t vOff = (uint32_t)(((((qg & 1) << 3) | (lane & 7)) * AROW) + ((qg >> 1) << 4));

    int niter = 2 * qt + 2;
    AISSUE(0, 0); CPCOMMIT();

    for (int kt = 0; kt < niter; kt++) {
        int k0 = kt << 6;
        int buf = kt & 1;
        CPWAIT(0);
        __syncthreads();
        if (kt + 1 < niter) { AISSUE(kt + 1, buf ^ 1); CPCOMMIT(); }

        uint32_t sK = sb + (uint32_t)buf * ASTG;

        // S = (Qh + Ql) K^T
        float s_[8][4] = {};
        #pragma unroll
        for (int ds = 0; ds < 4; ds++) {
            uint32_t bh[8][2];
            #pragma unroll
            for (int p = 0; p < 4; p++) {
                uint32_t ba_ = sK + kOff + (uint32_t)(p * 16 * AROW) + ds * 32;
                LDSM4(bh[2*p][0], bh[2*p][1], bh[2*p+1][0], bh[2*p+1][1], ba_);
            }
            #pragma unroll
            for (int j = 0; j < 8; j++) {
                MMA16816(s_[j], qfh[ds], bh[j]);
                MMA16816(s_[j], qfl[ds], bh[j]);
            }
        }

        // causal mask
        if (k0 + 63 > q0w) {
            int r0 = q0w + gid, r1 = r0 + 8;
            #pragma unroll
            for (int j = 0; j < 8; j++) {
                int cb = k0 + 8 * j + 2 * tig;
                if (cb     > r0) s_[j][0] = -1e30f;
                if (cb + 1 > r0) s_[j][1] = -1e30f;
                if (cb     > r1) s_[j][2] = -1e30f;
                if (cb + 1 > r1) s_[j][3] = -1e30f;
            }
        }

        // online softmax (poly exp)
        float mx0 = s_[0][0], mx1 = s_[0][2];
        #pragma unroll
        for (int j = 0; j < 8; j++) {
            mx0 = fmaxf(mx0, fmaxf(s_[j][0], s_[j][1]));
            mx1 = fmaxf(mx1, fmaxf(s_[j][2], s_[j][3]));
        }
        mx0 = fmaxf(mx0, __shfl_xor_sync(0xffffffffu, mx0, 1));
        mx0 = fmaxf(mx0, __shfl_xor_sync(0xffffffffu, mx0, 2));
        mx1 = fmaxf(mx1, __shfl_xor_sync(0xffffffffu, mx1, 1));
        mx1 = fmaxf(mx1, __shfl_xor_sync(0xffffffffu, mx1, 2));
        float mn0 = fmaxf(m0, mx0), mn1 = fmaxf(m1, mx1);
        float c0 = fexp(m0 - mn0), c1 = fexp(m1 - mn1);
        m0 = mn0; m1 = mn1;
        float rs0 = 0.f, rs1 = 0.f;
        #pragma unroll
        for (int j = 0; j < 8; j++) {
            s_[j][0] = fexp(s_[j][0] - mn0);
            s_[j][1] = fexp(s_[j][1] - mn0);
            s_[j][2] = fexp(s_[j][2] - mn1);
            s_[j][3] = fexp(s_[j][3] - mn1);
            rs0 += s_[j][0] + s_[j][1];
            rs1 += s_[j][2] + s_[j][3];
        }
        rs0 += __shfl_xor_sync(0xffffffffu, rs0, 1);
        rs0 += __shfl_xor_sync(0xffffffffu, rs0, 2);
        rs1 += __shfl_xor_sync(0xffffffffu, rs1, 1);
        rs1 += __shfl_xor_sync(0xffffffffu, rs1, 2);
        l0 = l0 * c0 + rs0; l1 = l1 * c1 + rs1;
        #pragma unroll
        for (int j = 0; j < 8; j++) {
            o_[j][0] *= c0; o_[j][1] *= c0; o_[j][2] *= c1; o_[j][3] *= c1;
        }

        // P -> A-frags (fp16 hi only)
        uint32_t pf[4][4];
        #pragma unroll
        for (int ks = 0; ks < 4; ks++) {
            int j0 = 2 * ks, j1 = 2 * ks + 1;
            pf[ks][0] = pack_h(s_[j0][0], s_[j0][1]);
            pf[ks][1] = pack_h(s_[j0][2], s_[j0][3]);
            pf[ks][2] = pack_h(s_[j1][0], s_[j1][1]);
            pf[ks][3] = pack_h(s_[j1][2], s_[j1][3]);
        }

        // O += P V  (single pass)
        #pragma unroll
        for (int ks = 0; ks < 4; ks++) {
            uint32_t vh[8][2];
            #pragma unroll
            for (int p = 0; p < 4; p++) {
                uint32_t ba_ = sK + 9216 + vOff + (uint32_t)(ks * 16 * AROW) + p * 32;
                LDSM4T(vh[2*p][0], vh[2*p][1], vh[2*p+1][0], vh[2*p+1][1], ba_);
            }
            #pragma unroll
            for (int j = 0; j < 8; j++)
                MMA16816(o_[j], pf[ks], vh[j]);
        }
    }

    // finalize
    float inv0 = 1.0f / l0, inv1 = 1.0f / l1;
    int r0 = q0 + 16 * w + gid, r1 = r0 + 8;
    float* O0 = O + ((size_t)bb * SEQ + r0) * DM + hh * DK + 2 * tig;
    float* O1 = O + ((size_t)bb * SEQ + r1) * DM + hh * DK + 2 * tig;
    #pragma unroll
    for (int j = 0; j < 8; j++) {
        *(float2*)(O0 + 8 * j) = make_float2(o_[j][0] * inv0, o_[j][1] * inv0);
        *(float2*)(O1 + 8 * j) = make_float2(o_[j][2] * inv1, o_[j][3] * inv1);
    }
}

// ---------------- launch ----------------
extern "C" void kernel_launch(void* const* d_in, const int* in_sizes, int n_in,
                              void* d_out, int out_size) {
    (void)in_sizes; (void)n_in; (void)out_size;
    const float* x   = (const float*)d_in[0];
    const int*   pos = (const int*)d_in[1];
    const float* Wq  = (const float*)d_in[2];
    const float* Wk  = (const float*)d_in[3];
    const float* Wv  = (const float*)d_in[4];
    const float* Wo  = (const float*)d_in[5];
    float* out = (float*)d_out;

    __half *xh, *xl, *wp, *qh, *ql, *kh, *vh;
    float* o;
    cudaGetSymbolAddress((void**)&xh, g_xh);
    cudaGetSymbolAddress((void**)&xl, g_xl);
    cudaGetSymbolAddress((void**)&wp, g_w);
    cudaGetSymbolAddress((void**)&qh, g_qh);
    cudaGetSymbolAddress((void**)&ql, g_ql);
    cudaGetSymbolAddress((void**)&kh, g_kh);
    cudaGetSymbolAddress((void**)&vh, g_vh);
    cudaGetSymbolAddress((void**)&o, g_o);

    cudaFuncSetAttribute(gemm_qkv, cudaFuncAttributeMaxDynamicSharedMemorySize, GSMEM);
    cudaFuncSetAttribute(gemm_out, cudaFuncAttributeMaxDynamicSharedMemorySize, GSMEM);
    cudaFuncSetAttribute(attn_mma, cudaFuncAttributeMaxDynamicSharedMemorySize, ASMEM);

    const int n4x = MTOT * DM / 4;
    const int n4w = DM * DM / 4;

    split_kernel<<<n4x / 256, 256>>>(x, xh, xl, n4x);
    conv4_kernel<<<dim3(n4w / 256, 4), 256>>>(Wq, Wk, Wv, Wo, wp, n4w);

    dim3 qkvgrid(3 * DM / 128, MTOT / 128);   // (24, 64) = 1536 CTAs
    gemm_qkv<<<qkvgrid, 256, GSMEM>>>(xh, xl, wp, pos, qh, ql, kh, vh);

    dim3 agrid(SEQ / 128, NH, BATCHN);
    attn_mma<<<agrid, 256, ASMEM>>>(qh, ql, kh, vh, o);

    split_kernel<<<n4x / 256, 256>>>(o, xh, xl, n4x);
    dim3 ogrid(DM / 128, MTOT / 128);
    gemm_out<<<ogrid, 256, GSMEM>>>(xh, xl, wp + (size_t)3 * DM * DM, out);
}

// round 15
// speedup vs baseline: 4.3216x; 1.0413x over previous
#include <cuda_runtime.h>
#include <cuda_fp16.h>
#include <math.h>
#include <stdint.h>

#define SEQ 4096
#define DM 1024
#define NH 16
#define DK 64
#define BATCHN 2
#define MTOT (BATCHN*SEQ)

// ---------------- scratch (allocation-free) ----------------
__device__ __half g_xh[(size_t)MTOT * DM];
__device__ __half g_xl[(size_t)MTOT * DM];
__device__ __half g_w[(size_t)4 * DM * DM];
__device__ __half g_qh[(size_t)MTOT * DM];
__device__ __half g_ql[(size_t)MTOT * DM];
__device__ __half g_kh[(size_t)MTOT * DM];
__device__ __half g_vh[(size_t)MTOT * DM];
__device__ float g_o[(size_t)MTOT * DM];

// ---------------- helpers ----------------
__device__ __forceinline__ uint32_t s2u(const void* p) {
    uint32_t a;
    asm("{ .reg .u64 t; cvta.to.shared.u64 t, %1; cvt.u32.u64 %0, t; }" : "=r"(a) : "l"(p));
    return a;
}

// RoPE rotation; Cody-Waite 2*pi reduction (robust under fast-math).
__device__ __forceinline__ void rope_rot(float p, float d_e, float& e, float& o) {
    const float LOG2_THETA_DIV = 13.287712379549449f / 64.0f;
    float freq = exp2f(-d_e * LOG2_THETA_DIV);
    float ang = p * freq;
    float n = rintf(ang * 0.15915494309189535f);
    float r = fmaf(-n, 6.28125f, ang);
    r = fmaf(-n, 1.9353071795864774e-3f, r);
    float s, c;
    sincosf(r, &s, &c);
    float ne = e * c - o * s;
    float no = e * s + o * c;
    e = ne; o = no;
}

// Fast exp for x <= 0 on the FMA/ALU pipes (no MUFU). ~1e-6 rel err.
__device__ __forceinline__ float fexp(float x) {
    float t = fmaxf(x * 1.4426950408889634f, -126.0f);
    float z = t + 12582912.0f;
    int ii = __float_as_int(z);
    float f = t - (z - 12582912.0f);
    float p = 1.3333558e-3f;
    p = fmaf(p, f, 9.6181291e-3f);
    p = fmaf(p, f, 5.5504109e-2f);
    p = fmaf(p, f, 2.4022651e-1f);
    p = fmaf(p, f, 6.9314718e-1f);
    p = fmaf(p, f, 1.0f);
    return __int_as_float((ii << 23) + 0x3F800000) * p;
}

// split fp32 pair -> packed fp16 hi + fp16 lo
__device__ __forceinline__ void pack_split(float a, float b, uint32_t& hp, uint32_t& lp) {
    __half2 H = __floats2half2_rn(a, b);
    hp = *(uint32_t*)&H;
    float2 hf = __half22float2(H);
    __half2 L = __floats2half2_rn(a - hf.x, b - hf.y);
    lp = *(uint32_t*)&L;
}

__device__ __forceinline__ uint32_t pack_h(float a, float b) {
    __half2 H = __floats2half2_rn(a, b);
    return *(uint32_t*)&H;
}

#define LDSM4(r0, r1, r2, r3, addr) \
    asm volatile("ldmatrix.sync.aligned.m8n8.x4.shared.b16 {%0,%1,%2,%3}, [%4];" \
        : "=r"(r0), "=r"(r1), "=r"(r2), "=r"(r3) : "r"(addr))

#define LDSM4T(r0, r1, r2, r3, addr) \
    asm volatile("ldmatrix.sync.aligned.m8n8.x4.trans.shared.b16 {%0,%1,%2,%3}, [%4];" \
        : "=r"(r0), "=r"(r1), "=r"(r2), "=r"(r3) : "r"(addr))

#define MMA16816(c, a, b) \
    asm volatile("mma.sync.aligned.m16n8k16.row.col.f32.f16.f16.f32 " \
        "{%0,%1,%2,%3}, {%4,%5,%6,%7}, {%8,%9}, {%0,%1,%2,%3};" \
        : "+f"((c)[0]), "+f"((c)[1]), "+f"((c)[2]), "+f"((c)[3]) \
        : "r"((a)[0]), "r"((a)[1]), "r"((a)[2]), "r"((a)[3]), "r"((b)[0]), "r"((b)[1]))

#define CPA16(dst, src) \
    asm volatile("cp.async.cg.shared.global [%0], [%1], 16;" :: "r"(dst), "l"(src))
#define CPCOMMIT() asm volatile("cp.async.commit_group;" ::: "memory")
#define CPWAIT(n)  asm volatile("cp.async.wait_group %0;" :: "n"(n) : "memory")

// ---------------- split kernel: fp32 -> (fp16 hi, fp16 lo) ----------------
__global__ __launch_bounds__(256) void split_kernel(
    const float* __restrict__ in, __half* __restrict__ hi,
    __half* __restrict__ lo, int n4)
{
    int i = blockIdx.x * 256 + threadIdx.x;
    if (i >= n4) return;
    float4 x = ((const float4*)in)[i];
    uint32_t h01, l01, h23, l23;
    pack_split(x.x, x.y, h01, l01);
    pack_split(x.z, x.w, h23, l23);
    ((uint2*)hi)[i] = make_uint2(h01, h23);
    ((uint2*)lo)[i] = make_uint2(l01, l23);
}

// ---------------- fused convert: 4 fp32 weights -> fp16 (blockIdx.y selects) ----------------
__global__ __launch_bounds__(256) void conv4_kernel(
    const float* __restrict__ w0, const float* __restrict__ w1,
    const float* __restrict__ w2, const float* __restrict__ w3,
    __half* __restrict__ hi, int n4)
{
    int i = blockIdx.x * 256 + threadIdx.x;
    if (i >= n4) return;
    int sel = blockIdx.y;
    const float* in = sel == 0 ? w0 : (sel == 1 ? w1 : (sel == 2 ? w2 : w3));
    float4 x = ((const float4*)in)[i];
    ((uint2*)(hi + (size_t)sel * DM * DM))[i] =
        make_uint2(pack_h(x.x, x.y), pack_h(x.z, x.w));
}

// ---------------- GEMM common config ----------------
#define SROWB 80
#define ARR_B (128 * SROWB)
#define STAGE_B (3 * ARR_B)      // 30720
#define NSTAGE 3
#define GSMEM (NSTAGE * STAGE_B) // 92160

#define GISSUE(s_) { \
    int bi = (s_) * 4 + (fh << 1); \
    uint32_t d0 = sfill + ((s_) % NSTAGE) * STAGE_B; \
    CPA16(d0 + 0 * ARR_B,      gAh + bi); \
    CPA16(d0 + 0 * ARR_B + 16, gAh + bi + 1); \
    CPA16(d0 + 1 * ARR_B,      gAl + bi); \
    CPA16(d0 + 1 * ARR_B + 16, gAl + bi + 1); \
    CPA16(d0 + 2 * ARR_B,      gBh + bi); \
    CPA16(d0 + 2 * ARR_B + 16, gBh + bi + 1); }

#define GEMM_MAINLOOP() \
    GISSUE(0); CPCOMMIT(); \
    GISSUE(1); CPCOMMIT(); \
    for (int s = 0; s < 32; s++) { \
        CPWAIT(1); \
        __syncthreads(); \
        if (s + 2 < 32) GISSUE(s + 2); \
        CPCOMMIT(); \
        uint32_t base = sb32 + (uint32_t)((s % NSTAGE) * STAGE_B); \
        uint32_t aRow = base + (uint32_t)(wm + (lane & 15)) * SROWB + ((lane >> 4) << 4); \
        int q = lane >> 3; \
        uint32_t bRow = base + 2 * ARR_B + \
                        (uint32_t)(wn + ((q >> 1) << 3) + (lane & 7)) * SROWB + \
                        ((q & 1) << 4); \
        _Pragma("unroll") \
        for (int step = 0; step < 2; step++) { \
            uint32_t ko = step * 32; \
            uint32_t ah[4][4], al[4][4], bh[4][2]; \
            _Pragma("unroll") \
            for (int mt = 0; mt < 4; mt++) { \
                uint32_t aAddr = aRow + (uint32_t)(mt * 16) * SROWB + ko; \
                LDSM4(ah[mt][0], ah[mt][1], ah[mt][2], ah[mt][3], aAddr); \
                LDSM4(al[mt][0], al[mt][1], al[mt][2], al[mt][3], aAddr + ARR_B); \
            } \
            _Pragma("unroll") \
            for (int pn = 0; pn < 2; pn++) { \
                uint32_t bAddr = bRow + (uint32_t)(pn * 16) * SROWB + ko; \
                LDSM4(bh[2*pn][0], bh[2*pn][1], bh[2*pn+1][0], bh[2*pn+1][1], bAddr); \
            } \
            _Pragma("unroll") \
            for (int mt = 0; mt < 4; mt++) \
                _Pragma("unroll") \
                for (int nt = 0; nt < 4; nt++) { \
                    MMA16816(c[mt][nt], ah[mt], bh[nt]); \
                    MMA16816(c[mt][nt], al[mt], bh[nt]); \
                } \
        } \
    }

// ---------------- fused QKV projection GEMM (one launch, 1536 CTAs) ----------------
__global__ __launch_bounds__(256, 2) void gemm_qkv(
    const __half* __restrict__ Ah, const __half* __restrict__ Al,
    const __half* __restrict__ W,
    const int* __restrict__ pos,
    __half* __restrict__ qh, __half* __restrict__ ql,
    __half* __restrict__ kh, __half* __restrict__ vh)
{
    extern __shared__ char smem[];
    const uint32_t sb32 = s2u(smem);
    int tid = threadIdx.x, lane = tid & 31, wid = tid >> 5;
    int m0 = blockIdx.y << 7, n0 = blockIdx.x << 7;
    int pi = n0 >> 10;           // 0=Q, 1=K, 2=V
    int nn0 = n0 & 1023;
    int wm = (wid >> 2) << 6;
    int wn = (wid & 3) << 5;

    int frow = tid >> 1;
    int fh = tid & 1;
    const uint4* gAh = (const uint4*)(Ah + (size_t)(m0 + frow) * DM);
    const uint4* gAl = (const uint4*)(Al + (size_t)(m0 + frow) * DM);
    const uint4* gBh = (const uint4*)(W + (size_t)pi * DM * DM + (size_t)(nn0 + frow) * DM);
    uint32_t sfill = sb32 + (uint32_t)(frow * SROWB + fh * 32);

    float c[4][4][4] = {};
    GEMM_MAINLOOP();

    // epilogue
    int gid = lane >> 2, tig = lane & 3;
    float scale = (pi == 0) ? 0.125f : 1.0f;
    #pragma unroll
    for (int mt = 0; mt < 4; mt++) {
        int m_a = m0 + wm + mt * 16 + gid;
        int m_b = m_a + 8;
        float p_a = 0.f, p_b = 0.f;
        if (pi != 2) { p_a = (float)pos[m_a]; p_b = (float)pos[m_b]; }
        #pragma unroll
        for (int nt = 0; nt < 4; nt++) {
            int n = nn0 + wn + nt * 8 + tig * 2;
            float v0 = c[mt][nt][0], v1 = c[mt][nt][1];
            float v2 = c[mt][nt][2], v3 = c[mt][nt][3];
            int h = n >> 6, d = n & 63;
            if (pi != 2) {
                rope_rot(p_a, (float)d, v0, v1);
                rope_rot(p_b, (float)d, v2, v3);
            }
            v0 *= scale; v1 *= scale; v2 *= scale; v3 *= scale;
            int ba = m_a >> 12, sa = m_a & (SEQ - 1);
            int bb = m_b >> 12, sbq = m_b & (SEQ - 1);
            size_t ia = ((size_t)(ba * NH + h) * SEQ + sa) * DK + d;
            size_t ib = ((size_t)(bb * NH + h) * SEQ + sbq) * DK + d;
            if (pi == 0) {
                uint32_t hp, lp;
                pack_split(v0, v1, hp, lp);
                *(uint32_t*)(qh + ia) = hp; *(uint32_t*)(ql + ia) = lp;
                pack_split(v2, v3, hp, lp);
                *(uint32_t*)(qh + ib) = hp; *(uint32_t*)(ql + ib) = lp;
            } else {
                __half* dst = (pi == 1) ? kh : vh;
                *(uint32_t*)(dst + ia) = pack_h(v0, v1);
                *(uint32_t*)(dst + ib) = pack_h(v2, v3);
            }
        }
    }
}

// ---------------- output projection GEMM (fp32 out) ----------------
__global__ __launch_bounds__(256, 2) void gemm_out(
    const __half* __restrict__ Ah, const __half* __restrict__ Al,
    const __half* __restrict__ Bh, float* __restrict__ outf)
{
    extern __shared__ char smem[];
    const uint32_t sb32 = s2u(smem);
    int tid = threadIdx.x, lane = tid & 31, wid = tid >> 5;
    int m0 = blockIdx.y << 7, n0 = blockIdx.x << 7;
    int wm = (wid >> 2) << 6;
    int wn = (wid & 3) << 5;

    int frow = tid >> 1;
    int fh = tid & 1;
    const uint4* gAh = (const uint4*)(Ah + (size_t)(m0 + frow) * DM);
    const uint4* gAl = (const uint4*)(Al + (size_t)(m0 + frow) * DM);
    const uint4* gBh = (const uint4*)(Bh + (size_t)(n0 + frow) * DM);
    uint32_t sfill = sb32 + (uint32_t)(frow * SROWB + fh * 32);

    float c[4][4][4] = {};
    GEMM_MAINLOOP();

    int gid = lane >> 2, tig = lane & 3;
    #pragma unroll
    for (int mt = 0; mt < 4; mt++) {
        int m_a = m0 + wm + mt * 16 + gid;
        int m_b = m_a + 8;
        #pragma unroll
        for (int nt = 0; nt < 4; nt++) {
            int n = n0 + wn + nt * 8 + tig * 2;
            *(float2*)(outf + (size_t)m_a * DM + n) = make_float2(c[mt][nt][0], c[mt][nt][1]);
            *(float2*)(outf + (size_t)m_b * DM + n) = make_float2(c[mt][nt][2], c[mt][nt][3]);
        }
    }
}

// ---------------- HMMA flash attention: S 2-pass, PV 1-pass, 2 CTA/SM ----------------
// smem: K/V double buffer [0, 2*ASTG), Ql persistent @ 2*ASTG (128 x AROW).
// Q-lo fragments re-loaded from smem per iteration (frees 16 regs -> 2 CTAs/SM).
#define AROW 144
#define ASTG 18432
#define ASMEM (2 * ASTG + 18432)   // 73728; 2 CTAs = 147456 < 228K

__global__ __launch_bounds__(256, 2) void attn_mma(
    const __half* __restrict__ Qh, const __half* __restrict__ Ql,
    const __half* __restrict__ Kh, const __half* __restrict__ Vh,
    float* __restrict__ O)
{
    extern __shared__ char sm[];
    uint32_t sb = s2u(sm);
    int tid = threadIdx.x, lane = tid & 31, w = tid >> 5;
    int qt = (int)gridDim.x - 1 - (int)blockIdx.x;  // longest job first
    int hh = blockIdx.y, bb = blockIdx.z;
    int q0 = qt << 7;
    size_t base = (size_t)(bb * NH + hh) * SEQ * DK;
    int gid = lane >> 2, tig = lane & 3;

    // ---- Q tiles: Qh staged in buf0 (transient), Ql -> persistent @ 2*ASTG ----
    {
        int row = tid >> 1, hf = tid & 1;
        const uint4* gqh = (const uint4*)(Qh + base + (size_t)(q0 + row) * DK);
        const uint4* gql = (const uint4*)(Ql + base + (size_t)(q0 + row) * DK);
        char* s0 = sm + row * AROW + hf * 64;
        #pragma unroll
        for (int j = 0; j < 4; j++) {
            *(uint4*)(s0 + j * 16)            = gqh[hf * 4 + j];
            *(uint4*)(s0 + 2 * ASTG + j * 16) = gql[hf * 4 + j];
        }
    }
    __syncthreads();
    uint32_t qfh[4][4];
    uint32_t qRowOff = (uint32_t)((16 * w + (lane & 15)) * AROW + ((lane >> 4) << 4));
    {
        uint32_t aAddr = sb + qRowOff;
        #pragma unroll
        for (int ds = 0; ds < 4; ds++)
            LDSM4(qfh[ds][0], qfh[ds][1], qfh[ds][2], qfh[ds][3], aAddr + ds * 32);
    }
    __syncthreads();   // Qh frags read before buf0 reused by pipeline
    uint32_t qlAddr = sb + 2 * ASTG + qRowOff;   // persistent Q-lo

    int frow0 = tid >> 3, fcol = tid & 7;
    uint32_t fdst = sb + (uint32_t)(frow0 * AROW + fcol * 16);

    #define AISSUE(kt_, buf_) { \
        size_t g0 = base + (size_t)(((kt_) << 6) + frow0) * DK + fcol * 8; \
        size_t g1 = g0 + 32 * DK; \
        uint32_t d0 = fdst + (buf_) * (uint32_t)ASTG; \
        uint32_t d1 = d0 + 32 * AROW; \
        CPA16(d0,        Kh + g0); CPA16(d1,        Kh + g1); \
        CPA16(d0 + 9216, Vh + g0); CPA16(d1 + 9216, Vh + g1); }

    float o_[8][4] = {};
    float m0 = -1e30f, m1 = -1e30f, l0 = 0.f, l1 = 0.f;
    int q0w = q0 + 16 * w;
    int qg = lane >> 3;
    uint32_t kOff = (uint32_t)(((((qg >> 1) << 3) | (lane & 7)) * AROW) + ((qg & 1) << 4));
    uint32_t vOff = (uint32_t)(((((qg & 1) << 3) | (lane & 7)) * AROW) + ((qg >> 1) << 4));

    int niter = 2 * qt + 2;
    AISSUE(0, 0); CPCOMMIT();

    for (int kt = 0; kt < niter; kt++) {
        int k0 = kt << 6;
        int buf = kt & 1;
        CPWAIT(0);
        __syncthreads();
        if (kt + 1 < niter) { AISSUE(kt + 1, buf ^ 1); CPCOMMIT(); }

        uint32_t sK = sb + (uint32_t)buf * ASTG;

        // S = (Qh + Ql) K^T   (Ql frag re-loaded from persistent smem per ds)
        float s_[8][4] = {};
        #pragma unroll
        for (int ds = 0; ds < 4; ds++) {
            uint32_t bh[8][2], qfl[4];
            LDSM4(qfl[0], qfl[1], qfl[2], qfl[3], qlAddr + ds * 32);
            #pragma unroll
            for (int p = 0; p < 4; p++) {
                uint32_t ba_ = sK + kOff + (uint32_t)(p * 16 * AROW) + ds * 32;
                LDSM4(bh[2*p][0], bh[2*p][1], bh[2*p+1][0], bh[2*p+1][1], ba_);
            }
            #pragma unroll
            for (int j = 0; j < 8; j++) {
                MMA16816(s_[j], qfh[ds], bh[j]);
                MMA16816(s_[j], qfl, bh[j]);
            }
        }

        // causal mask
        if (k0 + 63 > q0w) {
            int r0 = q0w + gid, r1 = r0 + 8;
            #pragma unroll
            for (int j = 0; j < 8; j++) {
                int cb = k0 + 8 * j + 2 * tig;
                if (cb     > r0) s_[j][0] = -1e30f;
                if (cb + 1 > r0) s_[j][1] = -1e30f;
                if (cb     > r1) s_[j][2] = -1e30f;
                if (cb + 1 > r1) s_[j][3] = -1e30f;
            }
        }

        // online softmax (poly exp)
        float mx0 = s_[0][0], mx1 = s_[0][2];
        #pragma unroll
        for (int j = 0; j < 8; j++) {
            mx0 = fmaxf(mx0, fmaxf(s_[j][0], s_[j][1]));
            mx1 = fmaxf(mx1, fmaxf(s_[j][2], s_[j][3]));
        }
        mx0 = fmaxf(mx0, __shfl_xor_sync(0xffffffffu, mx0, 1));
        mx0 = fmaxf(mx0, __shfl_xor_sync(0xffffffffu, mx0, 2));
        mx1 = fmaxf(mx1, __shfl_xor_sync(0xffffffffu, mx1, 1));
        mx1 = fmaxf(mx1, __shfl_xor_sync(0xffffffffu, mx1, 2));
        float mn0 = fmaxf(m0, mx0), mn1 = fmaxf(m1, mx1);
        float c0 = fexp(m0 - mn0), c1 = fexp(m1 - mn1);
        m0 = mn0; m1 = mn1;
        float rs0 = 0.f, rs1 = 0.f;
        #pragma unroll
        for (int j = 0; j < 8; j++) {
            s_[j][0] = fexp(s_[j][0] - mn0);
            s_[j][1] = fexp(s_[j][1] - mn0);
            s_[j][2] = fexp(s_[j][2] - mn1);
            s_[j][3] = fexp(s_[j][3] - mn1);
            rs0 += s_[j][0] + s_[j][1];
            rs1 += s_[j][2] + s_[j][3];
        }
        rs0 += __shfl_xor_sync(0xffffffffu, rs0, 1);
        rs0 += __shfl_xor_sync(0xffffffffu, rs0, 2);
        rs1 += __shfl_xor_sync(0xffffffffu, rs1, 1);
        rs1 += __shfl_xor_sync(0xffffffffu, rs1, 2);
        l0 = l0 * c0 + rs0; l1 = l1 * c1 + rs1;
        #pragma unroll
        for (int j = 0; j < 8; j++) {
            o_[j][0] *= c0; o_[j][1] *= c0; o_[j][2] *= c1; o_[j][3] *= c1;
        }

        // P -> A-frags (fp16 hi only)
        uint32_t pf[4][4];
        #pragma unroll
        for (int ks = 0; ks < 4; ks++) {
            int j0 = 2 * ks, j1 = 2 * ks + 1;
            pf[ks][0] = pack_h(s_[j0][0], s_[j0][1]);
            pf[ks][1] = pack_h(s_[j0][2], s_[j0][3]);
            pf[ks][2] = pack_h(s_[j1][0], s_[j1][1]);
            pf[ks][3] = pack_h(s_[j1][2], s_[j1][3]);
        }

        // O += P V  (single pass)
        #pragma unroll
        for (int ks = 0; ks < 4; ks++) {
            uint32_t vh[8][2];
            #pragma unroll
            for (int p = 0; p < 4; p++) {
                uint32_t ba_ = sK + 9216 + vOff + (uint32_t)(ks * 16 * AROW) + p * 32;
                LDSM4T(vh[2*p][0], vh[2*p][1], vh[2*p+1][0], vh[2*p+1][1], ba_);
            }
            #pragma unroll
            for (int j = 0; j < 8; j++)
                MMA16816(o_[j], pf[ks], vh[j]);
        }
    }

    // finalize
    float inv0 = 1.0f / l0, inv1 = 1.0f / l1;
    int r0 = q0 + 16 * w + gid, r1 = r0 + 8;
    float* O0 = O + ((size_t)bb * SEQ + r0) * DM + hh * DK + 2 * tig;
    float* O1 = O + ((size_t)bb * SEQ + r1) * DM + hh * DK + 2 * tig;
    #pragma unroll
    for (int j = 0; j < 8; j++) {
        *(float2*)(O0 + 8 * j) = make_float2(o_[j][0] * inv0, o_[j][1] * inv0);
        *(float2*)(O1 + 8 * j) = make_float2(o_[j][2] * inv1, o_[j][3] * inv1);
    }
}

// ---------------- launch ----------------
extern "C" void kernel_launch(void* const* d_in, const int* in_sizes, int n_in,
                              void* d_out, int out_size) {
    (void)in_sizes; (void)n_in; (void)out_size;
    const float* x   = (const float*)d_in[0];
    const int*   pos = (const int*)d_in[1];
    const float* Wq  = (const float*)d_in[2];
    const float* Wk  = (const float*)d_in[3];
    const float* Wv  = (const float*)d_in[4];
    const float* Wo  = (const float*)d_in[5];
    float* out = (float*)d_out;

    __half *xh, *xl, *wp, *qh, *ql, *kh, *vh;
    float* o;
    cudaGetSymbolAddress((void**)&xh, g_xh);
    cudaGetSymbolAddress((void**)&xl, g_xl);
    cudaGetSymbolAddress((void**)&wp, g_w);
    cudaGetSymbolAddress((void**)&qh, g_qh);
    cudaGetSymbolAddress((void**)&ql, g_ql);
    cudaGetSymbolAddress((void**)&kh, g_kh);
    cudaGetSymbolAddress((void**)&vh, g_vh);
    cudaGetSymbolAddress((void**)&o, g_o);

    cudaFuncSetAttribute(gemm_qkv, cudaFuncAttributeMaxDynamicSharedMemorySize, GSMEM);
    cudaFuncSetAttribute(gemm_out, cudaFuncAttributeMaxDynamicSharedMemorySize, GSMEM);
    cudaFuncSetAttribute(attn_mma, cudaFuncAttributeMaxDynamicSharedMemorySize, ASMEM);

    const int n4x = MTOT * DM / 4;
    const int n4w = DM * DM / 4;

    split_kernel<<<n4x / 256, 256>>>(x, xh, xl, n4x);
    conv4_kernel<<<dim3(n4w / 256, 4), 256>>>(Wq, Wk, Wv, Wo, wp, n4w);

    dim3 qkvgrid(3 * DM / 128, MTOT / 128);   // (24, 64) = 1536 CTAs
    gemm_qkv<<<qkvgrid, 256, GSMEM>>>(xh, xl, wp, pos, qh, ql, kh, vh);

    dim3 agrid(SEQ / 128, NH, BATCHN);
    attn_mma<<<agrid, 256, ASMEM>>>(qh, ql, kh, vh, o);

    split_kernel<<<n4x / 256, 256>>>(o, xh, xl, n4x);
    dim3 ogrid(DM / 128, MTOT / 128);
    gemm_out<<<ogrid, 256, GSMEM>>>(xh, xl, wp + (size_t)3 * DM * DM, out);
}